// round 7
// baseline (speedup 1.0000x reference)
#include <cuda_runtime.h>
#include <math.h>
#include <float.h>

#define BATCH 8
#define HIDC  256
#define ZCH   64
#define KCODE 512

// ---------------- scratch (device globals; no allocation allowed) ----------------
__device__ float g_h1 [BATCH * HIDC * 64 * 64];  // after c1
__device__ float g_h2a[BATCH * HIDC * 32 * 32];  // ping
__device__ float g_h2b[BATCH * HIDC * 32 * 32];  // pong
__device__ float g_rr [BATCH * HIDC * 32 * 32];  // residual intermediate
__device__ float g_d1 [BATCH * HIDC * 32 * 32];  // decoder stage 1
__device__ float g_d2 [BATCH * HIDC * 64 * 64];  // decoder stage 2
__device__ float g_wt1[4 * HIDC * HIDC * 4];     // subpixel-decomposed t1 weights

// packed fp32x2 FMA (Blackwell): d = a * b + d, elementwise on 2 packed f32
__device__ __forceinline__ void fma2(unsigned long long& d,
                                     unsigned long long a,
                                     unsigned long long b)
{
    asm("fma.rn.f32x2 %0, %1, %2, %0;" : "+l"(d) : "l"(a), "l"(b));
}
__device__ __forceinline__ unsigned long long dup2(float v)
{
    unsigned long long r;
    asm("mov.b64 %0, {%1, %1};" : "=l"(r) : "f"(v));
    return r;
}

// =======================================================================
// Implicit-GEMM conv, double-buffered smem, f32x2 packed math.
//   C[M=Cout][N=B*Hout*Wout] = A[M][K] * B(gathered)[K][N]
// BM=64, BN=128, BK=16, 256 threads, TM=4 (2 M-pairs) x TN=8.
// Round-7 changes vs round-6 (which measured fma=43%, issue=42%):
//  * Bs stored PRE-DUPLICATED as f32x2 pairs -> inner loop has zero MOV-dup
//    and no alu->fma cross-pipe RAW; pure LDS.128 + FMA2.
//  * BK=16 halves the barrier count per launch.
//  * As rows padded (+4) to reduce STS bank conflicts.
// Grid >= 256 CTAs on 256-channel layers keeps 2 CTAs/SM (round-5 lesson).
// SUBPIX: 2x2 subpixel conv implementing convT(k4,s2,p1); blockIdx.z = parity.
// =======================================================================
template<int KH, int KW, bool SUBPIX, bool VST>
__global__ __launch_bounds__(256, 2) void conv_gemm(
    const float* __restrict__ A, const float* __restrict__ in,
    const float* __restrict__ bias, const float* __restrict__ res,
    float* __restrict__ out,
    int Cin, int Hin, int Win, int Cout, int Hout, int Wout,
    int stride, int pad, int K, int act, int inRelu,
    int Hfull, int Wfull)
{
    constexpr int BM = 64, BN = 128, BK = 16, TN = 8, TM = 4, TP = 2;
    constexpr int KHW = KH * KW;
    constexpr int AP = BM + 4;                  // padded A row (fewer STS conflicts)
    __shared__ float As[2][BK][AP];
    __shared__ unsigned long long Bs[2][BK][BN]; // pre-duplicated f32x2 pairs

    const int tid = threadIdx.x;
    const int m0 = blockIdx.y * BM;
    const int n0 = blockIdx.x * BN;
    const int HW = Hout * Wout;

    int par_y = 0, par_x = 0;
    const float* Ab = A;
    if (SUBPIX) {
        int pz = blockIdx.z;
        par_y = pz >> 1; par_x = pz & 1;
        Ab = A + (long)pz * Cout * K;
    }

    // ---- B gather mapping: fixed n per thread, 8 consecutive k ----
    const int bn  = tid & (BN - 1);
    const int bk8 = (tid >> 7) << 3;            // 0 or 8
    const int n   = n0 + bn;
    const int bimg = n / HW;
    const int hw   = n - bimg * HW;
    const int oy   = hw / Wout;
    const int ox   = hw - oy * Wout;
    const float* inb = in + (long)bimg * Cin * Hin * Win;
    int iy0, ix0;
    if (SUBPIX) { iy0 = oy - (1 - par_y); ix0 = ox - (1 - par_x); }
    else        { iy0 = oy * stride - pad; ix0 = ox * stride - pad; }

    // ---- A load mapping: one float4 per thread per tile (64*16/4 = 256) ----
    const int am = tid >> 2;
    const int ak = (tid & 3) << 2;
    const float* Arow = Ab + (long)(m0 + am) * K + ak;

    // ---- compute mapping ----
    const int rm = (tid & 15) * TM;
    const int rn = (tid >> 4) * TN;
    unsigned long long acc2[TP][TN];
    #pragma unroll
    for (int i = 0; i < TP; i++)
        #pragma unroll
        for (int j = 0; j < TN; j++) acc2[i][j] = 0ull;

    auto gatherB = [&](int k0, float* bv) {
        #pragma unroll
        for (int i = 0; i < 8; i++) {
            int k  = k0 + bk8 + i;
            int ic = k / KHW;
            int rr = k - ic * KHW;
            int ky = rr / KW;
            int kx = rr - ky * KW;
            int iy = iy0 + ky;
            int ix = ix0 + kx;
            float v = 0.f;
            if ((unsigned)iy < (unsigned)Hin && (unsigned)ix < (unsigned)Win)
                v = inb[(ic * Hin + iy) * Win + ix];
            if (inRelu) v = fmaxf(v, 0.f);
            bv[i] = v;
        }
    };

    const int nt = K / BK;
    float4 av;
    float  bv[8];

    // preload tile 0
    av = *reinterpret_cast<const float4*>(Arow);
    gatherB(0, bv);
    As[0][ak + 0][am] = av.x; As[0][ak + 1][am] = av.y;
    As[0][ak + 2][am] = av.z; As[0][ak + 3][am] = av.w;
    #pragma unroll
    for (int i = 0; i < 8; i++) Bs[0][bk8 + i][bn] = dup2(bv[i]);
    __syncthreads();

    int cur = 0;
    for (int t = 0; t < nt; t++) {
        if (t + 1 < nt) {
            int k0n = (t + 1) * BK;
            av = *reinterpret_cast<const float4*>(Arow + k0n);
            gatherB(k0n, bv);
        }
        #pragma unroll
        for (int kk = 0; kk < BK; kk++) {
            // A-side: 2 packed pairs along M from one LDS.128
            ulonglong2 ua = *reinterpret_cast<const ulonglong2*>(&As[cur][kk][rm]);
            // B-side: 8 pre-duplicated pairs from 4 LDS.128 (broadcast)
            ulonglong2 b01 = *reinterpret_cast<const ulonglong2*>(&Bs[cur][kk][rn + 0]);
            ulonglong2 b23 = *reinterpret_cast<const ulonglong2*>(&Bs[cur][kk][rn + 2]);
            ulonglong2 b45 = *reinterpret_cast<const ulonglong2*>(&Bs[cur][kk][rn + 4]);
            ulonglong2 b67 = *reinterpret_cast<const ulonglong2*>(&Bs[cur][kk][rn + 6]);
            fma2(acc2[0][0], ua.x, b01.x); fma2(acc2[1][0], ua.y, b01.x);
            fma2(acc2[0][1], ua.x, b01.y); fma2(acc2[1][1], ua.y, b01.y);
            fma2(acc2[0][2], ua.x, b23.x); fma2(acc2[1][2], ua.y, b23.x);
            fma2(acc2[0][3], ua.x, b23.y); fma2(acc2[1][3], ua.y, b23.y);
            fma2(acc2[0][4], ua.x, b45.x); fma2(acc2[1][4], ua.y, b45.x);
            fma2(acc2[0][5], ua.x, b45.y); fma2(acc2[1][5], ua.y, b45.y);
            fma2(acc2[0][6], ua.x, b67.x); fma2(acc2[1][6], ua.y, b67.x);
            fma2(acc2[0][7], ua.x, b67.y); fma2(acc2[1][7], ua.y, b67.y);
        }
        if (t + 1 < nt) {
            int nx = cur ^ 1;
            As[nx][ak + 0][am] = av.x; As[nx][ak + 1][am] = av.y;
            As[nx][ak + 2][am] = av.z; As[nx][ak + 3][am] = av.w;
            #pragma unroll
            for (int i = 0; i < 8; i++) Bs[nx][bk8 + i][bn] = dup2(bv[i]);
            __syncthreads();
            cur = nx;
        }
    }

    // ---- epilogue ----
    const int nb  = n0 + rn;
    const int b2  = nb / HW;                 // same image for all TN columns
    const int hwb = nb - b2 * HW;
    const int eoy = hwb / Wout;
    const int eox = hwb - eoy * Wout;        // row-constant: eox+TN-1 < Wout
    const long HWf = (long)Hfull * Wfull;
    const long base = (long)b2 * Cout * HWf;

    #pragma unroll
    for (int i = 0; i < TM; i++) {
        const int oc = m0 + rm + i;
        const float bvs = bias[oc];
        if (VST && !SUBPIX) {
            long idx = base + (long)oc * HWf + hwb;
            #pragma unroll
            for (int j = 0; j < TN; j += 4) {
                float2 p0 = *reinterpret_cast<const float2*>(&acc2[i >> 1][j + 0]);
                float2 p1 = *reinterpret_cast<const float2*>(&acc2[i >> 1][j + 1]);
                float2 p2 = *reinterpret_cast<const float2*>(&acc2[i >> 1][j + 2]);
                float2 p3 = *reinterpret_cast<const float2*>(&acc2[i >> 1][j + 3]);
                float4 v;
                v.x = ((i & 1) ? p0.y : p0.x) + bvs;
                v.y = ((i & 1) ? p1.y : p1.x) + bvs;
                v.z = ((i & 1) ? p2.y : p2.x) + bvs;
                v.w = ((i & 1) ? p3.y : p3.x) + bvs;
                if (res) {
                    float4 r = *reinterpret_cast<const float4*>(res + idx + j);
                    v.x += r.x; v.y += r.y; v.z += r.z; v.w += r.w;
                }
                if (act == 1) {
                    v.x = fmaxf(v.x, 0.f); v.y = fmaxf(v.y, 0.f);
                    v.z = fmaxf(v.z, 0.f); v.w = fmaxf(v.w, 0.f);
                }
                *reinterpret_cast<float4*>(out + idx + j) = v;
            }
        } else {
            #pragma unroll
            for (int j = 0; j < TN; j++) {
                float2 p = *reinterpret_cast<const float2*>(&acc2[i >> 1][j]);
                float v = ((i & 1) ? p.y : p.x) + bvs;
                if (act == 1) v = fmaxf(v, 0.f);
                int fy, fx;
                if (SUBPIX) { fy = 2 * eoy + par_y; fx = 2 * (eox + j) + par_x; }
                else        { fy = eoy;             fx = eox + j; }
                out[base + (long)oc * HWf + (long)fy * Wfull + fx] = v;
            }
        }
    }
}

// ---------------- VQ: one warp per z-vector ----------------
__global__ __launch_bounds__(128) void vq_kernel(
    const float* __restrict__ z, const float* __restrict__ cb,
    float* __restrict__ ek, float* __restrict__ ids_out)
{
    const int warp = threadIdx.x >> 5;
    const int lane = threadIdx.x & 31;
    const int n = blockIdx.x * 4 + warp;         // [0, 8192)
    const int b  = n >> 10;
    const int hw = n & 1023;

    __shared__ float zs[4][ZCH];
    const float* zb = z + (long)b * ZCH * 1024 + hw;
    zs[warp][lane]      = zb[(long)lane * 1024];
    zs[warp][lane + 32] = zb[(long)(lane + 32) * 1024];
    __syncwarp();

    float best = FLT_MAX;
    int bi = 0;
    for (int k = lane; k < KCODE; k += 32) {
        const float* c = cb + k * ZCH;
        float s = 0.f;
        #pragma unroll 16
        for (int ci = 0; ci < ZCH; ci++) {
            float cv = c[ci];
            s = fmaf(cv, cv - 2.f * zs[warp][ci], s);   // |c|^2 - 2 z.c
        }
        if (s < best) { best = s; bi = k; }
    }
    #pragma unroll
    for (int off = 16; off; off >>= 1) {
        float ov = __shfl_down_sync(0xffffffffu, best, off);
        int   oi = __shfl_down_sync(0xffffffffu, bi,   off);
        if (ov < best || (ov == best && oi < bi)) { best = ov; bi = oi; }
    }
    bi = __shfl_sync(0xffffffffu, bi, 0);

    if (lane == 0) ids_out[n] = (float)bi;
    const float* c = cb + bi * ZCH;
    float* ekb = ek + (long)b * ZCH * 1024 + hw;
    ekb[(long)lane * 1024]        = c[lane];
    ekb[(long)(lane + 32) * 1024] = c[lane + 32];
}

// ---------------- t1 subpixel weight prep ----------------
// wsub[pz=2p+q][oc][ic][ky'][kx'] = t1_w[ic][oc][3 - p - 2ky'][3 - q - 2kx']
__global__ void wt_kernel(const float* __restrict__ w, float* __restrict__ wf)
{
    int i = blockIdx.x * blockDim.x + threadIdx.x;
    const int total = 4 * HIDC * HIDC * 4;
    if (i >= total) return;
    int kx = i & 1, ky = (i >> 1) & 1;
    int r1 = i >> 2;
    int ic = r1 & (HIDC - 1);
    int r2 = r1 >> 8;
    int oc = r2 & (HIDC - 1);
    int pz = r2 >> 8;
    int p = pz >> 1, q = pz & 1;
    wf[i] = w[((long)(ic * HIDC + oc) << 4) + (3 - p - 2 * ky) * 4 + (3 - q - 2 * kx)];
}

// ---------------- t2: direct transposed conv 256->3, k4 s2 p1, fused sigmoid ----------------
__global__ __launch_bounds__(128) void t2_kernel(
    const float* __restrict__ in,   // (8,256,64,64)
    const float* __restrict__ w,    // t2_w (256,3,4,4)
    const float* __restrict__ bias, // (3,)
    float* __restrict__ out)        // (8,3,128,128)
{
    __shared__ float ws[HIDC][3][8];
    const int oy   = blockIdx.x;
    const int bimg = blockIdx.y;
    const int ox   = threadIdx.x;
    const int p = oy & 1;

    for (int idx = threadIdx.x; idx < HIDC * 3 * 8; idx += 128) {
        int ic = idx / 24;
        int r  = idx - ic * 24;
        int oc = r >> 3;
        int t  = r & 7;
        int kyi = t >> 2, kx = t & 3;
        int ky = p + 2 * kyi;
        ws[ic][oc][t] = w[((long)(ic * 3 + oc) << 4) + (3 - ky) * 4 + (3 - kx)];
    }
    __syncthreads();

    const int q = ox & 1;
    const int iy0 = (oy + p - 2) >> 1;
    const int iy1 = (oy + p) >> 1;
    const int ix0 = (ox + q - 2) >> 1;
    const int ix1 = (ox + q) >> 1;
    const bool vy0 = (iy0 >= 0), vy1 = (iy1 < 64);
    const bool vx0 = (ix0 >= 0), vx1 = (ix1 < 64);

    const float* inb = in + (long)bimg * HIDC * 4096;
    float acc0 = 0.f, acc1 = 0.f, acc2 = 0.f;
    for (int ic = 0; ic < HIDC; ic++) {
        const float* pl = inb + ic * 4096;
        float v00 = (vy0 && vx0) ? pl[iy0 * 64 + ix0] : 0.f;
        float v01 = (vy0 && vx1) ? pl[iy0 * 64 + ix1] : 0.f;
        float v10 = (vy1 && vx0) ? pl[iy1 * 64 + ix0] : 0.f;
        float v11 = (vy1 && vx1) ? pl[iy1 * 64 + ix1] : 0.f;
        const float* wr0 = ws[ic][0];
        const float* wr1 = ws[ic][1];
        const float* wr2 = ws[ic][2];
        acc0 = fmaf(v00, wr0[q], fmaf(v01, wr0[q+2], fmaf(v10, wr0[4+q], fmaf(v11, wr0[4+q+2], acc0))));
        acc1 = fmaf(v00, wr1[q], fmaf(v01, wr1[q+2], fmaf(v10, wr1[4+q], fmaf(v11, wr1[4+q+2], acc1))));
        acc2 = fmaf(v00, wr2[q], fmaf(v01, wr2[q+2], fmaf(v10, wr2[4+q], fmaf(v11, wr2[4+q+2], acc2))));
    }
    long ob = ((long)bimg * 3) * 16384 + (long)oy * 128 + ox;
    float s0 = acc0 + bias[0], s1 = acc1 + bias[1], s2 = acc2 + bias[2];
    out[ob]           = 1.f / (1.f + expf(-s0));
    out[ob + 16384]   = 1.f / (1.f + expf(-s1));
    out[ob + 32768]   = 1.f / (1.f + expf(-s2));
}

// ---------------- host ----------------
extern "C" void kernel_launch(void* const* d_in, const int* in_sizes, int n_in,
                              void* d_out, int out_size)
{
    const float* x      = (const float*)d_in[0];
    const float* c1_w   = (const float*)d_in[1];
    const float* c1_b   = (const float*)d_in[2];
    const float* c2_w   = (const float*)d_in[3];
    const float* c2_b   = (const float*)d_in[4];
    const float* r0_w3  = (const float*)d_in[5];
    const float* r0_b3  = (const float*)d_in[6];
    const float* r0_w1  = (const float*)d_in[7];
    const float* r0_b1  = (const float*)d_in[8];
    const float* r1_w3  = (const float*)d_in[9];
    const float* r1_b3  = (const float*)d_in[10];
    const float* r1_w1  = (const float*)d_in[11];
    const float* r1_b1  = (const float*)d_in[12];
    const float* to_z_w = (const float*)d_in[13];
    const float* to_z_b = (const float*)d_in[14];
    const float* codebk = (const float*)d_in[15];
    const float* fz_w   = (const float*)d_in[16];
    const float* fz_b   = (const float*)d_in[17];
    const float* t1_w   = (const float*)d_in[18];
    const float* t1_b   = (const float*)d_in[19];
    const float* t2_w   = (const float*)d_in[20];
    const float* t2_b   = (const float*)d_in[21];
    float* out = (float*)d_out;

    // output layout: [out 393216][z_e 524288][e_k 524288][ids 8192]
    const long ZE_OFF  = 393216;
    const long EK_OFF  = 917504;
    const long IDS_OFF = 1441792;

    float *h1, *h2a, *h2b, *rr, *d1, *d2, *wt1;
    cudaGetSymbolAddress((void**)&h1,  g_h1);
    cudaGetSymbolAddress((void**)&h2a, g_h2a);
    cudaGetSymbolAddress((void**)&h2b, g_h2b);
    cudaGetSymbolAddress((void**)&rr,  g_rr);
    cudaGetSymbolAddress((void**)&d1,  g_d1);
    cudaGetSymbolAddress((void**)&d2,  g_d2);
    cudaGetSymbolAddress((void**)&wt1, g_wt1);

    // weight prep for t1 (independent; launch early)
    wt_kernel<<<(4 * HIDC * HIDC * 4 + 255) / 256, 256>>>(t1_w, wt1);

    // ---- encoder ----
    // c1: 3->256, k4 s2 p1, relu. K=48, N=32768 -> grid (256,4)
    conv_gemm<4, 4, false, true><<<dim3(256, 4), 256>>>(
        c1_w, x, c1_b, nullptr, h1,
        3, 128, 128, 256, 64, 64, 2, 1, 48, 1, 0, 64, 64);

    // c2: 256->256, k4 s2 p1, relu. K=4096, N=8192 -> grid (64,4)
    conv_gemm<4, 4, false, true><<<dim3(64, 4), 256>>>(
        c2_w, h1, c2_b, nullptr, h2a,
        256, 64, 64, 256, 32, 32, 2, 1, 4096, 1, 0, 32, 32);

    // res block 0
    conv_gemm<3, 3, false, true><<<dim3(64, 4), 256>>>(
        r0_w3, h2a, r0_b3, nullptr, rr,
        256, 32, 32, 256, 32, 32, 1, 1, 2304, 0, 1, 32, 32);
    conv_gemm<1, 1, false, true><<<dim3(64, 4), 256>>>(
        r0_w1, rr, r0_b1, h2a, h2b,
        256, 32, 32, 256, 32, 32, 1, 0, 256, 0, 1, 32, 32);
    // res block 1
    conv_gemm<3, 3, false, true><<<dim3(64, 4), 256>>>(
        r1_w3, h2b, r1_b3, nullptr, rr,
        256, 32, 32, 256, 32, 32, 1, 1, 2304, 0, 1, 32, 32);
    conv_gemm<1, 1, false, true><<<dim3(64, 4), 256>>>(
        r1_w1, rr, r1_b1, h2b, h2a,
        256, 32, 32, 256, 32, 32, 1, 0, 256, 0, 1, 32, 32);

    // to_z: 256->64, 1x1 -> z_e
    conv_gemm<1, 1, false, true><<<dim3(64, 1), 256>>>(
        to_z_w, h2a, to_z_b, nullptr, out + ZE_OFF,
        256, 32, 32, 64, 32, 32, 1, 0, 256, 0, 0, 32, 32);

    // VQ: ids + e_k
    vq_kernel<<<2048, 128>>>(out + ZE_OFF, codebk, out + EK_OFF, out + IDS_OFF);

    // from_z: 64->256, 1x1, relu. K=64
    conv_gemm<1, 1, false, true><<<dim3(64, 4), 256>>>(
        fz_w, out + EK_OFF, fz_b, nullptr, d1,
        64, 32, 32, 256, 32, 32, 1, 0, 64, 1, 0, 32, 32);

    // t1: convT 256->256 k4 s2 p1 as 4 subpixel 2x2 convs (grid.z = parity), relu. K=1024
    conv_gemm<2, 2, true, false><<<dim3(64, 4, 4), 256>>>(
        wt1, d1, t1_b, nullptr, d2,
        256, 32, 32, 256, 32, 32, 1, 0, 1024, 1, 0, 64, 64);

    // t2: direct transposed conv 256->3 + sigmoid
    t2_kernel<<<dim3(128, BATCH), 128>>>(d2, t2_w, t2_b, out);
}

// round 11
// speedup vs baseline: 1.0474x; 1.0474x over previous
#include <cuda_runtime.h>
#include <cuda_fp16.h>
#include <cstdint>
#include <math.h>
#include <float.h>

#define BATCH 8
#define HIDC  256
#define ZCH   64
#define KCODE 512

// ---------------- scratch (device globals; no allocation allowed) ----------------
__device__ float g_h1 [BATCH * HIDC * 64 * 64];  // after c1
__device__ float g_h2a[BATCH * HIDC * 32 * 32];  // ping
__device__ float g_h2b[BATCH * HIDC * 32 * 32];  // pong
__device__ float g_rr [BATCH * HIDC * 32 * 32];  // residual intermediate
__device__ float g_d1 [BATCH * HIDC * 32 * 32];  // decoder stage 1
__device__ float g_d2 [BATCH * HIDC * 64 * 64];  // decoder stage 2
__device__ float g_wt1[4 * HIDC * HIDC * 4];     // subpixel-decomposed t1 weights (fp32)

// fp16 split weights: per 32-k chunk: [h32 | ls32] (64 halves = 128B row piece)
__device__ __half g_wc2 [HIDC * 2 * 4096];
__device__ __half g_wr03[HIDC * 2 * 2304];
__device__ __half g_wr01[HIDC * 2 * 256];
__device__ __half g_wr13[HIDC * 2 * 2304];
__device__ __half g_wr11[HIDC * 2 * 256];
__device__ __half g_wfz [HIDC * 2 * 64];
__device__ __half g_wt1e[4 * HIDC * 2 * 1024];

// ================= helpers =================
__device__ __forceinline__ uint32_t smem_u32(const void* p) {
    uint32_t a;
    asm("{ .reg .u64 t; cvta.to.shared.u64 t, %1; cvt.u32.u64 %0, t; }" : "=r"(a) : "l"(p));
    return a;
}
#define SWZ128(o) ((o) ^ (((o) >> 3) & 0x70))
__device__ __forceinline__ void sts128(uint32_t a, uint4 v) {
    asm volatile("st.shared.v4.b32 [%0], {%1,%2,%3,%4};"
                 :: "r"(a), "r"(v.x), "r"(v.y), "r"(v.z), "r"(v.w) : "memory");
}
__device__ __forceinline__ void ldsm4(uint32_t* r, uint32_t addr) {
    asm volatile("ldmatrix.sync.aligned.m8n8.x4.shared.b16 {%0,%1,%2,%3}, [%4];"
                 : "=r"(r[0]), "=r"(r[1]), "=r"(r[2]), "=r"(r[3]) : "r"(addr));
}
__device__ __forceinline__ void mma16816(float* c, const uint32_t* a, const uint32_t* b) {
    asm volatile(
        "mma.sync.aligned.m16n8k16.row.col.f32.f16.f16.f32 "
        "{%0,%1,%2,%3}, {%4,%5,%6,%7}, {%8,%9}, {%0,%1,%2,%3};"
        : "+f"(c[0]), "+f"(c[1]), "+f"(c[2]), "+f"(c[3])
        : "r"(a[0]), "r"(a[1]), "r"(a[2]), "r"(a[3]), "r"(b[0]), "r"(b[1]));
}
__device__ __forceinline__ uint32_t pack_h2(__half a, __half b) {
    uint32_t r;
    unsigned short ua = __half_as_ushort(a), ub = __half_as_ushort(b);
    asm("mov.b32 %0, {%1, %2};" : "=r"(r) : "h"(ua), "h"(ub));
    return r;
}

// ======= weight split: fp32 -> per-32k-chunk [h32|ls32] fp16 rows =======
__global__ void wsplit16(const float* __restrict__ W, __half* __restrict__ E,
                         int Cout, int K)
{
    int i = blockIdx.x * blockDim.x + threadIdx.x;
    if (i >= Cout * K) return;
    int oc = i / K, k = i - oc * K;
    int c = k >> 5, j = k & 31;
    float v = W[i];
    __half h = __float2half_rn(v);
    __half ls = __float2half_rn((v - __half2float(h)) * 2048.0f);
    long base = (long)oc * 2 * K + (long)c * 64;
    E[base + j]      = h;
    E[base + 32 + j] = ls;
}

// =======================================================================
// mma.sync implicit-GEMM conv (fp16 2-way split w/ rescale, 3 terms).
//   CTA: 128 oc x 64 px. BK=32. 8 warps as 4(m) x 2(n); warp tile 32x32.
// smem: A[128][128B] SW128 ([h32|ls32] per row), B[64][128B]. 24 KB total.
// acc_h += ha*hb ; acc_l += ha*lsb + lsa*hb ; out = acc_h + acc_l/2048.
// =======================================================================
template<int KH, int KW, bool SUBPIX>
__global__ __launch_bounds__(256, 2) void conv_mma(
    const __half* __restrict__ Wc,   // [(SUBPIX?4:1)][Cout][2K] fp16 split
    const float* __restrict__ in,
    const float* __restrict__ bias, const float* __restrict__ res,
    float* __restrict__ out,
    int Cin, int Hin, int Win, int Cout, int Hout, int Wout,
    int stride, int pad, int K, int act, int inRelu,
    int Hfull, int Wfull)
{
    constexpr int KHW = KH * KW;
    __shared__ __align__(16) char sAm[128 * 128];
    __shared__ __align__(16) char sBm[64 * 128];

    const int tid  = threadIdx.x;
    const int wid  = tid >> 5;
    const int lane = tid & 31;
    const int m0 = blockIdx.y * 128;
    const int n0 = blockIdx.x * 64;
    const int HW = Hout * Wout;

    const uint32_t sA = smem_u32(sAm);
    const uint32_t sB = smem_u32(sBm);

    int par_y = 0, par_x = 0;
    const __half* Wb = Wc;
    if (SUBPIX) {
        int pz = blockIdx.z;
        par_y = pz >> 1; par_x = pz & 1;
        Wb += (long)pz * Cout * 2 * K;
    }

    // ---- B gather mapping: px = tid&63, seg = tid>>6 covers 8 k ----
    const int px  = tid & 63;
    const int seg = tid >> 6;
    const int n   = n0 + px;
    const int bimg = n / HW;
    const int hw   = n - bimg * HW;
    const int oy   = hw / Wout, ox = hw - oy * Wout;
    const float* inb = in + (long)bimg * Cin * Hin * Win;
    int iy0, ix0;
    if (SUBPIX) { iy0 = oy - (1 - par_y); ix0 = ox - (1 - par_x); }
    else        { iy0 = oy * stride - pad; ix0 = ox * stride - pad; }

    // ---- warp compute mapping ----
    const int wm = (wid & 3) * 32;
    const int wn = (wid >> 2) * 32;

    float acc[2][4][4];
    float accl[2][4][4];
    #pragma unroll
    for (int mt = 0; mt < 2; mt++)
        #pragma unroll
        for (int nt = 0; nt < 4; nt++)
            #pragma unroll
            for (int e = 0; e < 4; e++) { acc[mt][nt][e] = 0.f; accl[mt][nt][e] = 0.f; }

    const long K2 = 2 * (long)K;      // halves per oc row
    const int nc_iters = K / 32;

    for (int cb = 0; cb < nc_iters; cb++) {
        // ---- stage A: copy 128 rows x 128B from split weights ----
        {
            const long kb = (long)cb * 64;
            #pragma unroll
            for (int i = 0; i < 4; i++) {
                int idx = i * 256 + tid;
                int row = idx >> 3, c16 = idx & 7;
                uint4 v = *reinterpret_cast<const uint4*>(
                    Wb + (long)(m0 + row) * K2 + kb + c16 * 8);
                sts128(sA + SWZ128(row * 128 + c16 * 16), v);
            }
        }
        // ---- stage B: im2col gather + fp16 split (8 k per thread) ----
        {
            const int kb = cb * 32 + seg * 8;
            uint32_t hp[4], lp[4];
            #pragma unroll
            for (int q = 0; q < 4; q++) {
                __half hh[2], ll[2];
                #pragma unroll
                for (int e = 0; e < 2; e++) {
                    int k = kb + q * 2 + e;
                    int ic, ky, kx;
                    if (KHW == 1) { ic = k; ky = 0; kx = 0; }
                    else { ic = k / KHW; int r2 = k - ic * KHW; ky = r2 / KW; kx = r2 - ky * KW; }
                    int iy = iy0 + ky, ix = ix0 + kx;
                    float v = 0.f;
                    if ((unsigned)iy < (unsigned)Hin && (unsigned)ix < (unsigned)Win)
                        v = inb[(ic * Hin + iy) * Win + ix];
                    if (inRelu) v = fmaxf(v, 0.f);
                    __half h = __float2half_rn(v);
                    __half l = __float2half_rn((v - __half2float(h)) * 2048.0f);
                    hh[e] = h; ll[e] = l;
                }
                hp[q] = pack_h2(hh[0], hh[1]);
                lp[q] = pack_h2(ll[0], ll[1]);
            }
            sts128(sB + SWZ128(px * 128 + seg * 16),      make_uint4(hp[0], hp[1], hp[2], hp[3]));
            sts128(sB + SWZ128(px * 128 + 64 + seg * 16), make_uint4(lp[0], lp[1], lp[2], lp[3]));
        }
        __syncthreads();

        // ---- compute: 2 k16-steps x 3 terms ----
        #pragma unroll
        for (int s = 0; s < 2; s++) {
            uint32_t Ah[2][4], Al[2][4];
            #pragma unroll
            for (int mt = 0; mt < 2; mt++) {
                int row = wm + mt * 16 + (lane & 15);
                int kby = s * 32 + ((lane >> 4) << 4);
                ldsm4(Ah[mt], sA + SWZ128(row * 128 + kby));
                ldsm4(Al[mt], sA + SWZ128(row * 128 + 64 + kby));
            }
            uint32_t Bh[2][4], Bl[2][4];
            #pragma unroll
            for (int ntp = 0; ntp < 2; ntp++) {
                int nrow = wn + ntp * 16 + ((lane >> 4) << 3) + (lane & 7);
                int kby  = s * 32 + (((lane >> 3) & 1) << 4);
                ldsm4(Bh[ntp], sB + SWZ128(nrow * 128 + kby));
                ldsm4(Bl[ntp], sB + SWZ128(nrow * 128 + 64 + kby));
            }
            #pragma unroll
            for (int mt = 0; mt < 2; mt++)
                #pragma unroll
                for (int nt = 0; nt < 4; nt++) {
                    const uint32_t* bh = &Bh[nt >> 1][(nt & 1) * 2];
                    const uint32_t* bl = &Bl[nt >> 1][(nt & 1) * 2];
                    mma16816(acc[mt][nt],  Ah[mt], bh);
                    mma16816(accl[mt][nt], Ah[mt], bl);
                    mma16816(accl[mt][nt], Al[mt], bh);
                }
        }
        __syncthreads();
    }

    // ---- epilogue ----
    const float INV = 1.0f / 2048.0f;
    const long HWf = (long)Hfull * Wfull;
    const int bimg0 = n0 / HW;
    const int hw0 = n0 - bimg0 * HW;
    const long obase = (long)bimg0 * Cout * HWf;

    #pragma unroll
    for (int mt = 0; mt < 2; mt++) {
        #pragma unroll
        for (int nt = 0; nt < 4; nt++) {
            float c0 = acc[mt][nt][0] + accl[mt][nt][0] * INV;
            float c1 = acc[mt][nt][1] + accl[mt][nt][1] * INV;
            float c2 = acc[mt][nt][2] + accl[mt][nt][2] * INV;
            float c3 = acc[mt][nt][3] + accl[mt][nt][3] * INV;
            int oc0 = m0 + wm + mt * 16 + (lane >> 2);
            int oc1 = oc0 + 8;
            int ncol = hw0 + wn + nt * 8 + (lane & 3) * 2;
            float b0 = bias[oc0], b1 = bias[oc1];
            c0 += b0; c1 += b0; c2 += b1; c3 += b1;
            if (!SUBPIX) {
                long i0 = obase + (long)oc0 * HWf + ncol;
                long i1 = obase + (long)oc1 * HWf + ncol;
                if (res) {
                    float2 r0 = *reinterpret_cast<const float2*>(res + i0);
                    float2 r1 = *reinterpret_cast<const float2*>(res + i1);
                    c0 += r0.x; c1 += r0.y; c2 += r1.x; c3 += r1.y;
                }
                if (act == 1) {
                    c0 = fmaxf(c0, 0.f); c1 = fmaxf(c1, 0.f);
                    c2 = fmaxf(c2, 0.f); c3 = fmaxf(c3, 0.f);
                }
                *reinterpret_cast<float2*>(out + i0) = make_float2(c0, c1);
                *reinterpret_cast<float2*>(out + i1) = make_float2(c2, c3);
            } else {
                if (act == 1) {
                    c0 = fmaxf(c0, 0.f); c1 = fmaxf(c1, 0.f);
                    c2 = fmaxf(c2, 0.f); c3 = fmaxf(c3, 0.f);
                }
                int eoy0 = ncol / Wout, eox0 = ncol - eoy0 * Wout;
                int nc1 = ncol + 1;
                int eoy1 = nc1 / Wout, eox1 = nc1 - eoy1 * Wout;
                long fy0 = 2 * eoy0 + par_y, fx0 = 2 * eox0 + par_x;
                long fy1 = 2 * eoy1 + par_y, fx1 = 2 * eox1 + par_x;
                out[obase + (long)oc0 * HWf + fy0 * Wfull + fx0] = c0;
                out[obase + (long)oc0 * HWf + fy1 * Wfull + fx1] = c1;
                out[obase + (long)oc1 * HWf + fy0 * Wfull + fx0] = c2;
                out[obase + (long)oc1 * HWf + fy1 * Wfull + fx1] = c3;
            }
        }
    }
}

// =======================================================================
// scalar implicit-GEMM (round-6, known good) — c1 and to_z only
// =======================================================================
__device__ __forceinline__ void fma2(unsigned long long& d, unsigned long long a,
                                     unsigned long long b)
{
    asm("fma.rn.f32x2 %0, %1, %2, %0;" : "+l"(d) : "l"(a), "l"(b));
}
__device__ __forceinline__ unsigned long long dup2v(float v)
{
    unsigned long long r;
    asm("mov.b64 %0, {%1, %1};" : "=l"(r) : "f"(v));
    return r;
}

template<int KH, int KW>
__global__ __launch_bounds__(256, 2) void conv_gemm(
    const float* __restrict__ A, const float* __restrict__ in,
    const float* __restrict__ bias, const float* __restrict__ res,
    float* __restrict__ out,
    int Cin, int Hin, int Win, int Cout, int Hout, int Wout,
    int stride, int pad, int K, int act, int inRelu,
    int Hfull, int Wfull)
{
    constexpr int BM = 64, BN = 128, BK = 8, TN = 8, TP = 2;
    constexpr int KHW = KH * KW;
    __shared__ float As[2][BK][BM];
    __shared__ float Bs[2][BK][BN];

    const int tid = threadIdx.x;
    const int m0 = blockIdx.y * BM;
    const int n0 = blockIdx.x * BN;
    const int HW = Hout * Wout;

    const int bn = tid & (BN - 1);
    const int bk = (tid >> 7) << 2;
    const int n  = n0 + bn;
    const int bimg = n / HW;
    const int hw   = n - bimg * HW;
    const int oy   = hw / Wout;
    const int ox   = hw - oy * Wout;
    const float* inb = in + (long)bimg * Cin * Hin * Win;
    const int iy0 = oy * stride - pad;
    const int ix0 = ox * stride - pad;

    const int am = tid >> 1;
    const int ak = (tid & 1) << 2;
    const bool aload = (tid < 128);
    const float* Arow = aload ? (A + (long)(m0 + am) * K + ak) : A;

    const int rm = (tid & 15) * 4;
    const int rn = (tid >> 4) * TN;
    unsigned long long acc2[TP][TN];
    #pragma unroll
    for (int i = 0; i < TP; i++)
        #pragma unroll
        for (int j = 0; j < TN; j++) acc2[i][j] = 0ull;

    auto gatherB = [&](int k0, float* bv) {
        #pragma unroll
        for (int i = 0; i < 4; i++) {
            int k  = k0 + bk + i;
            int ic = k / KHW;
            int rr2 = k - ic * KHW;
            int ky = rr2 / KW;
            int kx = rr2 - ky * KW;
            int iy = iy0 + ky;
            int ix = ix0 + kx;
            float v = 0.f;
            if ((unsigned)iy < (unsigned)Hin && (unsigned)ix < (unsigned)Win)
                v = inb[(ic * Hin + iy) * Win + ix];
            if (inRelu) v = fmaxf(v, 0.f);
            bv[i] = v;
        }
    };

    const int nt = K / BK;
    float4 av;
    float  bv[4];

    if (aload) av = *reinterpret_cast<const float4*>(Arow);
    gatherB(0, bv);
    if (aload) {
        As[0][ak + 0][am] = av.x; As[0][ak + 1][am] = av.y;
        As[0][ak + 2][am] = av.z; As[0][ak + 3][am] = av.w;
    }
    #pragma unroll
    for (int i = 0; i < 4; i++) Bs[0][bk + i][bn] = bv[i];
    __syncthreads();

    int cur = 0;
    for (int t = 0; t < nt; t++) {
        if (t + 1 < nt) {
            int k0n = (t + 1) * BK;
            if (aload) av = *reinterpret_cast<const float4*>(Arow + k0n);
            gatherB(k0n, bv);
        }
        #pragma unroll
        for (int kk = 0; kk < BK; kk++) {
            ulonglong2 ua = *reinterpret_cast<const ulonglong2*>(&As[cur][kk][rm]);
            float b[TN];
            *reinterpret_cast<float4*>(&b[0]) = *reinterpret_cast<const float4*>(&Bs[cur][kk][rn]);
            *reinterpret_cast<float4*>(&b[4]) = *reinterpret_cast<const float4*>(&Bs[cur][kk][rn + 4]);
            #pragma unroll
            for (int j = 0; j < TN; j++) {
                unsigned long long bd = dup2v(b[j]);
                fma2(acc2[0][j], ua.x, bd);
                fma2(acc2[1][j], ua.y, bd);
            }
        }
        if (t + 1 < nt) {
            int nx = cur ^ 1;
            if (aload) {
                As[nx][ak + 0][am] = av.x; As[nx][ak + 1][am] = av.y;
                As[nx][ak + 2][am] = av.z; As[nx][ak + 3][am] = av.w;
            }
            #pragma unroll
            for (int i = 0; i < 4; i++) Bs[nx][bk + i][bn] = bv[i];
            __syncthreads();
            cur = nx;
        }
    }

    const int nb  = n0 + rn;
    const int b2  = nb / HW;
    const int hwb = nb - b2 * HW;
    const long HWf = (long)Hfull * Wfull;
    const long base = (long)b2 * Cout * HWf;

    #pragma unroll
    for (int i = 0; i < 4; i++) {
        const int oc = m0 + rm + i;
        const float bvs = bias[oc];
        long idx = base + (long)oc * HWf + hwb;
        #pragma unroll
        for (int j = 0; j < TN; j += 4) {
            float2 p0 = *reinterpret_cast<const float2*>(&acc2[i >> 1][j + 0]);
            float2 p1 = *reinterpret_cast<const float2*>(&acc2[i >> 1][j + 1]);
            float2 p2 = *reinterpret_cast<const float2*>(&acc2[i >> 1][j + 2]);
            float2 p3 = *reinterpret_cast<const float2*>(&acc2[i >> 1][j + 3]);
            float4 v;
            v.x = ((i & 1) ? p0.y : p0.x) + bvs;
            v.y = ((i & 1) ? p1.y : p1.x) + bvs;
            v.z = ((i & 1) ? p2.y : p2.x) + bvs;
            v.w = ((i & 1) ? p3.y : p3.x) + bvs;
            if (res) {
                float4 r = *reinterpret_cast<const float4*>(res + idx + j);
                v.x += r.x; v.y += r.y; v.z += r.z; v.w += r.w;
            }
            if (act == 1) {
                v.x = fmaxf(v.x, 0.f); v.y = fmaxf(v.y, 0.f);
                v.z = fmaxf(v.z, 0.f); v.w = fmaxf(v.w, 0.f);
            }
            *reinterpret_cast<float4*>(out + idx + j) = v;
        }
    }
}

// ---------------- VQ: one warp per z-vector ----------------
__global__ __launch_bounds__(128) void vq_kernel(
    const float* __restrict__ z, const float* __restrict__ cb,
    float* __restrict__ ek, float* __restrict__ ids_out)
{
    const int warp = threadIdx.x >> 5;
    const int lane = threadIdx.x & 31;
    const int n = blockIdx.x * 4 + warp;
    const int b  = n >> 10;
    const int hw = n & 1023;

    __shared__ float zs[4][ZCH];
    const float* zb = z + (long)b * ZCH * 1024 + hw;
    zs[warp][lane]      = zb[(long)lane * 1024];
    zs[warp][lane + 32] = zb[(long)(lane + 32) * 1024];
    __syncwarp();

    float best = FLT_MAX;
    int bi = 0;
    for (int k = lane; k < KCODE; k += 32) {
        const float* c = cb + k * ZCH;
        float s = 0.f;
        #pragma unroll 16
        for (int ci = 0; ci < ZCH; ci++) {
            float cv = c[ci];
            s = fmaf(cv, cv - 2.f * zs[warp][ci], s);
        }
        if (s < best) { best = s; bi = k; }
    }
    #pragma unroll
    for (int off = 16; off; off >>= 1) {
        float ov = __shfl_down_sync(0xffffffffu, best, off);
        int   oi = __shfl_down_sync(0xffffffffu, bi,   off);
        if (ov < best || (ov == best && oi < bi)) { best = ov; bi = oi; }
    }
    bi = __shfl_sync(0xffffffffu, bi, 0);

    if (lane == 0) ids_out[n] = (float)bi;
    const float* c = cb + bi * ZCH;
    float* ekb = ek + (long)b * ZCH * 1024 + hw;
    ekb[(long)lane * 1024]        = c[lane];
    ekb[(long)(lane + 32) * 1024] = c[lane + 32];
}

// ---------------- t1 subpixel weight prep (fp32) ----------------
__global__ void wt_kernel(const float* __restrict__ w, float* __restrict__ wf)
{
    int i = blockIdx.x * blockDim.x + threadIdx.x;
    const int total = 4 * HIDC * HIDC * 4;
    if (i >= total) return;
    int kx = i & 1, ky = (i >> 1) & 1;
    int r1 = i >> 2;
    int ic = r1 & (HIDC - 1);
    int r2 = r1 >> 8;
    int oc = r2 & (HIDC - 1);
    int pz = r2 >> 8;
    int p = pz >> 1, q = pz & 1;
    wf[i] = w[((long)(ic * HIDC + oc) << 4) + (3 - p - 2 * ky) * 4 + (3 - q - 2 * kx)];
}

// ---------------- t2: direct transposed conv 256->3 + sigmoid ----------------
__global__ __launch_bounds__(128) void t2_kernel(
    const float* __restrict__ in, const float* __restrict__ w,
    const float* __restrict__ bias, float* __restrict__ out)
{
    __shared__ float ws[HIDC][3][8];
    const int oy   = blockIdx.x;
    const int bimg = blockIdx.y;
    const int ox   = threadIdx.x;
    const int p = oy & 1;

    for (int idx = threadIdx.x; idx < HIDC * 3 * 8; idx += 128) {
        int ic = idx / 24;
        int r  = idx - ic * 24;
        int oc = r >> 3;
        int t  = r & 7;
        int kyi = t >> 2, kx = t & 3;
        int ky = p + 2 * kyi;
        ws[ic][oc][t] = w[((long)(ic * 3 + oc) << 4) + (3 - ky) * 4 + (3 - kx)];
    }
    __syncthreads();

    const int q = ox & 1;
    const int iy0 = (oy + p - 2) >> 1;
    const int iy1 = (oy + p) >> 1;
    const int ix0 = (ox + q - 2) >> 1;
    const int ix1 = (ox + q) >> 1;
    const bool vy0 = (iy0 >= 0), vy1 = (iy1 < 64);
    const bool vx0 = (ix0 >= 0), vx1 = (ix1 < 64);

    const float* inb = in + (long)bimg * HIDC * 4096;
    float acc0 = 0.f, acc1 = 0.f, acc2 = 0.f;
    for (int ic = 0; ic < HIDC; ic++) {
        const float* pl = inb + ic * 4096;
        float v00 = (vy0 && vx0) ? pl[iy0 * 64 + ix0] : 0.f;
        float v01 = (vy0 && vx1) ? pl[iy0 * 64 + ix1] : 0.f;
        float v10 = (vy1 && vx0) ? pl[iy1 * 64 + ix0] : 0.f;
        float v11 = (vy1 && vx1) ? pl[iy1 * 64 + ix1] : 0.f;
        const float* wr0 = ws[ic][0];
        const float* wr1 = ws[ic][1];
        const float* wr2 = ws[ic][2];
        acc0 = fmaf(v00, wr0[q], fmaf(v01, wr0[q+2], fmaf(v10, wr0[4+q], fmaf(v11, wr0[4+q+2], acc0))));
        acc1 = fmaf(v00, wr1[q], fmaf(v01, wr1[q+2], fmaf(v10, wr1[4+q], fmaf(v11, wr1[4+q+2], acc1))));
        acc2 = fmaf(v00, wr2[q], fmaf(v01, wr2[q+2], fmaf(v10, wr2[4+q], fmaf(v11, wr2[4+q+2], acc2))));
    }
    long ob = ((long)bimg * 3) * 16384 + (long)oy * 128 + ox;
    float s0 = acc0 + bias[0], s1 = acc1 + bias[1], s2 = acc2 + bias[2];
    out[ob]           = 1.f / (1.f + expf(-s0));
    out[ob + 16384]   = 1.f / (1.f + expf(-s1));
    out[ob + 32768]   = 1.f / (1.f + expf(-s2));
}

// ---------------- host ----------------
extern "C" void kernel_launch(void* const* d_in, const int* in_sizes, int n_in,
                              void* d_out, int out_size)
{
    const float* x      = (const float*)d_in[0];
    const float* c1_w   = (const float*)d_in[1];
    const float* c1_b   = (const float*)d_in[2];
    const float* c2_w   = (const float*)d_in[3];
    const float* c2_b   = (const float*)d_in[4];
    const float* r0_w3  = (const float*)d_in[5];
    const float* r0_b3  = (const float*)d_in[6];
    const float* r0_w1  = (const float*)d_in[7];
    const float* r0_b1  = (const float*)d_in[8];
    const float* r1_w3  = (const float*)d_in[9];
    const float* r1_b3  = (const float*)d_in[10];
    const float* r1_w1  = (const float*)d_in[11];
    const float* r1_b1  = (const float*)d_in[12];
    const float* to_z_w = (const float*)d_in[13];
    const float* to_z_b = (const float*)d_in[14];
    const float* codebk = (const float*)d_in[15];
    const float* fz_w   = (const float*)d_in[16];
    const float* fz_b   = (const float*)d_in[17];
    const float* t1_w   = (const float*)d_in[18];
    const float* t1_b   = (const float*)d_in[19];
    const float* t2_w   = (const float*)d_in[20];
    const float* t2_b   = (const float*)d_in[21];
    float* out = (float*)d_out;

    const long ZE_OFF  = 393216;
    const long EK_OFF  = 917504;
    const long IDS_OFF = 1441792;

    float *h1, *h2a, *h2b, *rr, *d1, *d2, *wt1;
    __half *wc2, *wr03, *wr01, *wr13, *wr11, *wfz, *wt1e;
    cudaGetSymbolAddress((void**)&h1,  g_h1);
    cudaGetSymbolAddress((void**)&h2a, g_h2a);
    cudaGetSymbolAddress((void**)&h2b, g_h2b);
    cudaGetSymbolAddress((void**)&rr,  g_rr);
    cudaGetSymbolAddress((void**)&d1,  g_d1);
    cudaGetSymbolAddress((void**)&d2,  g_d2);
    cudaGetSymbolAddress((void**)&wt1, g_wt1);
    cudaGetSymbolAddress((void**)&wc2,  g_wc2);
    cudaGetSymbolAddress((void**)&wr03, g_wr03);
    cudaGetSymbolAddress((void**)&wr01, g_wr01);
    cudaGetSymbolAddress((void**)&wr13, g_wr13);
    cudaGetSymbolAddress((void**)&wr11, g_wr11);
    cudaGetSymbolAddress((void**)&wfz,  g_wfz);
    cudaGetSymbolAddress((void**)&wt1e, g_wt1e);

    // ---- weight prep ----
    wt_kernel<<<(4 * HIDC * HIDC * 4 + 255) / 256, 256>>>(t1_w, wt1);
    wsplit16<<<(256 * 4096 + 255) / 256, 256>>>(c2_w,  wc2,  256, 4096);
    wsplit16<<<(256 * 2304 + 255) / 256, 256>>>(r0_w3, wr03, 256, 2304);
    wsplit16<<<(256 * 256  + 255) / 256, 256>>>(r0_w1, wr01, 256, 256);
    wsplit16<<<(256 * 2304 + 255) / 256, 256>>>(r1_w3, wr13, 256, 2304);
    wsplit16<<<(256 * 256  + 255) / 256, 256>>>(r1_w1, wr11, 256, 256);
    wsplit16<<<(256 * 64   + 255) / 256, 256>>>(fz_w,  wfz,  256, 64);
    for (int pz = 0; pz < 4; pz++)
        wsplit16<<<(256 * 1024 + 255) / 256, 256>>>(
            wt1 + (long)pz * 256 * 1024, wt1e + (long)pz * 256 * 2048, 256, 1024);

    // ---- encoder ----
    // c1: 3->256, k4 s2 p1, relu (scalar; K=48)
    conv_gemm<4, 4><<<dim3(256, 4), 256>>>(
        c1_w, x, c1_b, nullptr, h1,
        3, 128, 128, 256, 64, 64, 2, 1, 48, 1, 0, 64, 64);

    // c2: 256->256, k4 s2 p1, relu (mma)
    conv_mma<4, 4, false><<<dim3(128, 2), 256>>>(
        wc2, h1, c2_b, nullptr, h2a,
        256, 64, 64, 256, 32, 32, 2, 1, 4096, 1, 0, 32, 32);

    // res block 0
    conv_mma<3, 3, false><<<dim3(128, 2), 256>>>(
        wr03, h2a, r0_b3, nullptr, rr,
        256, 32, 32, 256, 32, 32, 1, 1, 2304, 0, 1, 32, 32);
    conv_mma<1, 1, false><<<dim3(128, 2), 256>>>(
        wr01, rr, r0_b1, h2a, h2b,
        256, 32, 32, 256, 32, 32, 1, 0, 256, 0, 1, 32, 32);
    // res block 1
    conv_mma<3, 3, false><<<dim3(128, 2), 256>>>(
        wr13, h2b, r1_b3, nullptr, rr,
        256, 32, 32, 256, 32, 32, 1, 1, 2304, 0, 1, 32, 32);
    conv_mma<1, 1, false><<<dim3(128, 2), 256>>>(
        wr11, rr, r1_b1, h2b, h2a,
        256, 32, 32, 256, 32, 32, 1, 0, 256, 0, 1, 32, 32);

    // to_z: 256->64, 1x1 (scalar fp32 -> exact z_e for VQ)
    conv_gemm<1, 1><<<dim3(64, 1), 256>>>(
        to_z_w, h2a, to_z_b, nullptr, out + ZE_OFF,
        256, 32, 32, 64, 32, 32, 1, 0, 256, 0, 0, 32, 32);

    // VQ
    vq_kernel<<<2048, 128>>>(out + ZE_OFF, codebk, out + EK_OFF, out + IDS_OFF);

    // from_z: 64->256, 1x1, relu (mma)
    conv_mma<1, 1, false><<<dim3(128, 2), 256>>>(
        wfz, out + EK_OFF, fz_b, nullptr, d1,
        64, 32, 32, 256, 32, 32, 1, 0, 64, 1, 0, 32, 32);

    // t1: convT 256->256 as 4 subpixel 2x2 convs (mma), relu
    conv_mma<2, 2, true><<<dim3(128, 2, 4), 256>>>(
        wt1e, d1, t1_b, nullptr, d2,
        256, 32, 32, 256, 32, 32, 1, 0, 1024, 1, 0, 64, 64);

    // t2: direct transposed conv 256->3 + sigmoid
    t2_kernel<<<dim3(128, BATCH), 128>>>(d2, t2_w, t2_b, out);
}

// round 12
// speedup vs baseline: 1.4626x; 1.3964x over previous
#include <cuda_runtime.h>
#include <cuda_fp16.h>
#include <cstdint>
#include <math.h>
#include <float.h>

#define BATCH 8
#define HIDC  256
#define ZCH   64
#define KCODE 512

// ---------------- scratch (device globals; no allocation allowed) ----------------
__device__ float g_h1 [BATCH * HIDC * 64 * 64];  // after c1
__device__ float g_h2a[BATCH * HIDC * 32 * 32];  // ping
__device__ float g_h2b[BATCH * HIDC * 32 * 32];  // pong
__device__ float g_rr [BATCH * HIDC * 32 * 32];  // residual intermediate
__device__ float g_d1 [BATCH * HIDC * 32 * 32];  // decoder stage 1
__device__ float g_d2 [BATCH * HIDC * 64 * 64];  // decoder stage 2
__device__ float g_wt1[4 * HIDC * HIDC * 4];     // subpixel-decomposed t1 weights (fp32)

// fp16 split weights: per 32-k chunk: [h32 | ls32] (64 halves = 128B row piece)
__device__ __half g_wc2 [HIDC * 2 * 4096];
__device__ __half g_wr03[HIDC * 2 * 2304];
__device__ __half g_wr01[HIDC * 2 * 256];
__device__ __half g_wr13[HIDC * 2 * 2304];
__device__ __half g_wr11[HIDC * 2 * 256];
__device__ __half g_wfz [HIDC * 2 * 64];
__device__ __half g_wt1e[4 * HIDC * 2 * 1024];

// ================= helpers =================
__device__ __forceinline__ uint32_t smem_u32(const void* p) {
    uint32_t a;
    asm("{ .reg .u64 t; cvta.to.shared.u64 t, %1; cvt.u32.u64 %0, t; }" : "=r"(a) : "l"(p));
    return a;
}
#define SWZ128(o) ((o) ^ (((o) >> 3) & 0x70))
__device__ __forceinline__ void sts128(uint32_t a, uint4 v) {
    asm volatile("st.shared.v4.b32 [%0], {%1,%2,%3,%4};"
                 :: "r"(a), "r"(v.x), "r"(v.y), "r"(v.z), "r"(v.w) : "memory");
}
__device__ __forceinline__ void ldsm4(uint32_t* r, uint32_t addr) {
    asm volatile("ldmatrix.sync.aligned.m8n8.x4.shared.b16 {%0,%1,%2,%3}, [%4];"
                 : "=r"(r[0]), "=r"(r[1]), "=r"(r[2]), "=r"(r[3]) : "r"(addr));
}
__device__ __forceinline__ void mma16816(float* c, const uint32_t* a, const uint32_t* b) {
    asm volatile(
        "mma.sync.aligned.m16n8k16.row.col.f32.f16.f16.f32 "
        "{%0,%1,%2,%3}, {%4,%5,%6,%7}, {%8,%9}, {%0,%1,%2,%3};"
        : "+f"(c[0]), "+f"(c[1]), "+f"(c[2]), "+f"(c[3])
        : "r"(a[0]), "r"(a[1]), "r"(a[2]), "r"(a[3]), "r"(b[0]), "r"(b[1]));
}
__device__ __forceinline__ uint32_t pack_h2(__half a, __half b) {
    uint32_t r;
    unsigned short ua = __half_as_ushort(a), ub = __half_as_ushort(b);
    asm("mov.b32 %0, {%1, %2};" : "=r"(r) : "h"(ua), "h"(ub));
    return r;
}

// ======= weight split: fp32 -> per-32k-chunk [h32|ls32] fp16 rows =======
__global__ void wsplit16(const float* __restrict__ W, __half* __restrict__ E,
                         int Cout, int K)
{
    int i = blockIdx.x * blockDim.x + threadIdx.x;
    if (i >= Cout * K) return;
    int oc = i / K, k = i - oc * K;
    int c = k >> 5, j = k & 31;
    float v = W[i];
    __half h = __float2half_rn(v);
    __half ls = __float2half_rn((v - __half2float(h)) * 2048.0f);
    long base = (long)oc * 2 * K + (long)c * 64;
    E[base + j]      = h;
    E[base + 32 + j] = ls;
}

// =======================================================================
// mma.sync implicit-GEMM conv (fp16 2-way split w/ rescale, 3 terms).
//   CTA: 64 oc x 64 px. BK=32. 8 warps as 4(m) x 2(n); warp tile 16x32.
// Round-12: tile halved vs round-11 (acc regs 64->32) to kill spills under
// the 128-reg clamp of __launch_bounds__(256,2). smem 16 KB.
// acc_h += ha*hb ; acc_l += ha*lsb + lsa*hb ; out = acc_h + acc_l/2048.
// =======================================================================
template<int KH, int KW, bool SUBPIX>
__global__ __launch_bounds__(256, 2) void conv_mma(
    const __half* __restrict__ Wc,   // [(SUBPIX?4:1)][Cout][2K] fp16 split
    const float* __restrict__ in,
    const float* __restrict__ bias, const float* __restrict__ res,
    float* __restrict__ out,
    int Cin, int Hin, int Win, int Cout, int Hout, int Wout,
    int stride, int pad, int K, int act, int inRelu,
    int Hfull, int Wfull)
{
    constexpr int KHW = KH * KW;
    __shared__ __align__(16) char sAm[64 * 128];
    __shared__ __align__(16) char sBm[64 * 128];

    const int tid  = threadIdx.x;
    const int wid  = tid >> 5;
    const int lane = tid & 31;
    const int m0 = blockIdx.y * 64;
    const int n0 = blockIdx.x * 64;
    const int HW = Hout * Wout;

    const uint32_t sA = smem_u32(sAm);
    const uint32_t sB = smem_u32(sBm);

    int par_y = 0, par_x = 0;
    const __half* Wb = Wc;
    if (SUBPIX) {
        int pz = blockIdx.z;
        par_y = pz >> 1; par_x = pz & 1;
        Wb += (long)pz * Cout * 2 * K;
    }

    // ---- B gather mapping: px = tid&63, seg = tid>>6 covers 8 k ----
    const int px  = tid & 63;
    const int seg = tid >> 6;
    const int n   = n0 + px;
    const int bimg = n / HW;
    const int hw   = n - bimg * HW;
    const int oy   = hw / Wout, ox = hw - oy * Wout;
    const float* inb = in + (long)bimg * Cin * Hin * Win;
    int iy0, ix0;
    if (SUBPIX) { iy0 = oy - (1 - par_y); ix0 = ox - (1 - par_x); }
    else        { iy0 = oy * stride - pad; ix0 = ox * stride - pad; }

    // ---- warp compute mapping: warp tile 16(m) x 32(n) ----
    const int wm = (wid & 3) * 16;
    const int wn = (wid >> 2) * 32;

    float acc[4][4];
    float accl[4][4];
    #pragma unroll
    for (int nt = 0; nt < 4; nt++)
        #pragma unroll
        for (int e = 0; e < 4; e++) { acc[nt][e] = 0.f; accl[nt][e] = 0.f; }

    const long K2 = 2 * (long)K;      // halves per oc row
    const int nc_iters = K / 32;

    for (int cb = 0; cb < nc_iters; cb++) {
        // ---- stage A: copy 64 rows x 128B from split weights ----
        {
            const long kb = (long)cb * 64;
            #pragma unroll
            for (int i = 0; i < 2; i++) {
                int idx = i * 256 + tid;
                int row = idx >> 3, c16 = idx & 7;
                uint4 v = *reinterpret_cast<const uint4*>(
                    Wb + (long)(m0 + row) * K2 + kb + c16 * 8);
                sts128(sA + SWZ128(row * 128 + c16 * 16), v);
            }
        }
        // ---- stage B: im2col gather + fp16 split (8 k per thread) ----
        {
            const int kb = cb * 32 + seg * 8;
            uint32_t hp[4], lp[4];
            #pragma unroll
            for (int q = 0; q < 4; q++) {
                __half hh[2], ll[2];
                #pragma unroll
                for (int e = 0; e < 2; e++) {
                    int k = kb + q * 2 + e;
                    int ic, ky, kx;
                    if (KHW == 1) { ic = k; ky = 0; kx = 0; }
                    else { ic = k / KHW; int r2 = k - ic * KHW; ky = r2 / KW; kx = r2 - ky * KW; }
                    int iy = iy0 + ky, ix = ix0 + kx;
                    float v = 0.f;
                    if ((unsigned)iy < (unsigned)Hin && (unsigned)ix < (unsigned)Win)
                        v = inb[(ic * Hin + iy) * Win + ix];
                    if (inRelu) v = fmaxf(v, 0.f);
                    __half h = __float2half_rn(v);
                    __half l = __float2half_rn((v - __half2float(h)) * 2048.0f);
                    hh[e] = h; ll[e] = l;
                }
                hp[q] = pack_h2(hh[0], hh[1]);
                lp[q] = pack_h2(ll[0], ll[1]);
            }
            sts128(sB + SWZ128(px * 128 + seg * 16),      make_uint4(hp[0], hp[1], hp[2], hp[3]));
            sts128(sB + SWZ128(px * 128 + 64 + seg * 16), make_uint4(lp[0], lp[1], lp[2], lp[3]));
        }
        __syncthreads();

        // ---- compute: 2 k16-steps x 3 terms ----
        #pragma unroll
        for (int s = 0; s < 2; s++) {
            uint32_t Ah[4], Al[4];
            {
                int row = wm + (lane & 15);
                int kby = s * 32 + ((lane >> 4) << 4);
                ldsm4(Ah, sA + SWZ128(row * 128 + kby));
                ldsm4(Al, sA + SWZ128(row * 128 + 64 + kby));
            }
            uint32_t Bh[2][4], Bl[2][4];
            #pragma unroll
            for (int ntp = 0; ntp < 2; ntp++) {
                int nrow = wn + ntp * 16 + ((lane >> 4) << 3) + (lane & 7);
                int kby  = s * 32 + (((lane >> 3) & 1) << 4);
                ldsm4(Bh[ntp], sB + SWZ128(nrow * 128 + kby));
                ldsm4(Bl[ntp], sB + SWZ128(nrow * 128 + 64 + kby));
            }
            #pragma unroll
            for (int nt = 0; nt < 4; nt++) {
                const uint32_t* bh = &Bh[nt >> 1][(nt & 1) * 2];
                const uint32_t* bl = &Bl[nt >> 1][(nt & 1) * 2];
                mma16816(acc[nt],  Ah, bh);
                mma16816(accl[nt], Ah, bl);
                mma16816(accl[nt], Al, bh);
            }
        }
        __syncthreads();
    }

    // ---- epilogue ----
    const float INV = 1.0f / 2048.0f;
    const long HWf = (long)Hfull * Wfull;
    const int bimg0 = n0 / HW;
    const int hw0 = n0 - bimg0 * HW;
    const long obase = (long)bimg0 * Cout * HWf;

    #pragma unroll
    for (int nt = 0; nt < 4; nt++) {
        float c0 = acc[nt][0] + accl[nt][0] * INV;
        float c1 = acc[nt][1] + accl[nt][1] * INV;
        float c2 = acc[nt][2] + accl[nt][2] * INV;
        float c3 = acc[nt][3] + accl[nt][3] * INV;
        int oc0 = m0 + wm + (lane >> 2);
        int oc1 = oc0 + 8;
        int ncol = hw0 + wn + nt * 8 + (lane & 3) * 2;
        float b0 = bias[oc0], b1 = bias[oc1];
        c0 += b0; c1 += b0; c2 += b1; c3 += b1;
        if (!SUBPIX) {
            long i0 = obase + (long)oc0 * HWf + ncol;
            long i1 = obase + (long)oc1 * HWf + ncol;
            if (res) {
                float2 r0 = *reinterpret_cast<const float2*>(res + i0);
                float2 r1 = *reinterpret_cast<const float2*>(res + i1);
                c0 += r0.x; c1 += r0.y; c2 += r1.x; c3 += r1.y;
            }
            if (act == 1) {
                c0 = fmaxf(c0, 0.f); c1 = fmaxf(c1, 0.f);
                c2 = fmaxf(c2, 0.f); c3 = fmaxf(c3, 0.f);
            }
            *reinterpret_cast<float2*>(out + i0) = make_float2(c0, c1);
            *reinterpret_cast<float2*>(out + i1) = make_float2(c2, c3);
        } else {
            if (act == 1) {
                c0 = fmaxf(c0, 0.f); c1 = fmaxf(c1, 0.f);
                c2 = fmaxf(c2, 0.f); c3 = fmaxf(c3, 0.f);
            }
            int eoy0 = ncol / Wout, eox0 = ncol - eoy0 * Wout;
            int nc1 = ncol + 1;
            int eoy1 = nc1 / Wout, eox1 = nc1 - eoy1 * Wout;
            long fy0 = 2 * eoy0 + par_y, fx0 = 2 * eox0 + par_x;
            long fy1 = 2 * eoy1 + par_y, fx1 = 2 * eox1 + par_x;
            out[obase + (long)oc0 * HWf + fy0 * Wfull + fx0] = c0;
            out[obase + (long)oc0 * HWf + fy1 * Wfull + fx1] = c1;
            out[obase + (long)oc1 * HWf + fy0 * Wfull + fx0] = c2;
            out[obase + (long)oc1 * HWf + fy1 * Wfull + fx1] = c3;
        }
    }
}

// =======================================================================
// scalar implicit-GEMM (round-6, known good) — c1 and to_z only
// =======================================================================
__device__ __forceinline__ void fma2(unsigned long long& d, unsigned long long a,
                                     unsigned long long b)
{
    asm("fma.rn.f32x2 %0, %1, %2, %0;" : "+l"(d) : "l"(a), "l"(b));
}
__device__ __forceinline__ unsigned long long dup2v(float v)
{
    unsigned long long r;
    asm("mov.b64 %0, {%1, %1};" : "=l"(r) : "f"(v));
    return r;
}

template<int KH, int KW>
__global__ __launch_bounds__(256, 2) void conv_gemm(
    const float* __restrict__ A, const float* __restrict__ in,
    const float* __restrict__ bias, const float* __restrict__ res,
    float* __restrict__ out,
    int Cin, int Hin, int Win, int Cout, int Hout, int Wout,
    int stride, int pad, int K, int act, int inRelu,
    int Hfull, int Wfull)
{
    constexpr int BM = 64, BN = 128, BK = 8, TN = 8, TP = 2;
    constexpr int KHW = KH * KW;
    __shared__ float As[2][BK][BM];
    __shared__ float Bs[2][BK][BN];

    const int tid = threadIdx.x;
    const int m0 = blockIdx.y * BM;
    const int n0 = blockIdx.x * BN;
    const int HW = Hout * Wout;

    const int bn = tid & (BN - 1);
    const int bk = (tid >> 7) << 2;
    const int n  = n0 + bn;
    const int bimg = n / HW;
    const int hw   = n - bimg * HW;
    const int oy   = hw / Wout;
    const int ox   = hw - oy * Wout;
    const float* inb = in + (long)bimg * Cin * Hin * Win;
    const int iy0 = oy * stride - pad;
    const int ix0 = ox * stride - pad;

    const int am = tid >> 1;
    const int ak = (tid & 1) << 2;
    const bool aload = (tid < 128);
    const float* Arow = aload ? (A + (long)(m0 + am) * K + ak) : A;

    const int rm = (tid & 15) * 4;
    const int rn = (tid >> 4) * TN;
    unsigned long long acc2[TP][TN];
    #pragma unroll
    for (int i = 0; i < TP; i++)
        #pragma unroll
        for (int j = 0; j < TN; j++) acc2[i][j] = 0ull;

    auto gatherB = [&](int k0, float* bv) {
        #pragma unroll
        for (int i = 0; i < 4; i++) {
            int k  = k0 + bk + i;
            int ic = k / KHW;
            int rr2 = k - ic * KHW;
            int ky = rr2 / KW;
            int kx = rr2 - ky * KW;
            int iy = iy0 + ky;
            int ix = ix0 + kx;
            float v = 0.f;
            if ((unsigned)iy < (unsigned)Hin && (unsigned)ix < (unsigned)Win)
                v = inb[(ic * Hin + iy) * Win + ix];
            if (inRelu) v = fmaxf(v, 0.f);
            bv[i] = v;
        }
    };

    const int nt = K / BK;
    float4 av;
    float  bv[4];

    if (aload) av = *reinterpret_cast<const float4*>(Arow);
    gatherB(0, bv);
    if (aload) {
        As[0][ak + 0][am] = av.x; As[0][ak + 1][am] = av.y;
        As[0][ak + 2][am] = av.z; As[0][ak + 3][am] = av.w;
    }
    #pragma unroll
    for (int i = 0; i < 4; i++) Bs[0][bk + i][bn] = bv[i];
    __syncthreads();

    int cur = 0;
    for (int t = 0; t < nt; t++) {
        if (t + 1 < nt) {
            int k0n = (t + 1) * BK;
            if (aload) av = *reinterpret_cast<const float4*>(Arow + k0n);
            gatherB(k0n, bv);
        }
        #pragma unroll
        for (int kk = 0; kk < BK; kk++) {
            ulonglong2 ua = *reinterpret_cast<const ulonglong2*>(&As[cur][kk][rm]);
            float b[TN];
            *reinterpret_cast<float4*>(&b[0]) = *reinterpret_cast<const float4*>(&Bs[cur][kk][rn]);
            *reinterpret_cast<float4*>(&b[4]) = *reinterpret_cast<const float4*>(&Bs[cur][kk][rn + 4]);
            #pragma unroll
            for (int j = 0; j < TN; j++) {
                unsigned long long bd = dup2v(b[j]);
                fma2(acc2[0][j], ua.x, bd);
                fma2(acc2[1][j], ua.y, bd);
            }
        }
        if (t + 1 < nt) {
            int nx = cur ^ 1;
            if (aload) {
                As[nx][ak + 0][am] = av.x; As[nx][ak + 1][am] = av.y;
                As[nx][ak + 2][am] = av.z; As[nx][ak + 3][am] = av.w;
            }
            #pragma unroll
            for (int i = 0; i < 4; i++) Bs[nx][bk + i][bn] = bv[i];
            __syncthreads();
            cur = nx;
        }
    }

    const int nb  = n0 + rn;
    const int b2  = nb / HW;
    const int hwb = nb - b2 * HW;
    const long HWf = (long)Hfull * Wfull;
    const long base = (long)b2 * Cout * HWf;

    #pragma unroll
    for (int i = 0; i < 4; i++) {
        const int oc = m0 + rm + i;
        const float bvs = bias[oc];
        long idx = base + (long)oc * HWf + hwb;
        #pragma unroll
        for (int j = 0; j < TN; j += 4) {
            float2 p0 = *reinterpret_cast<const float2*>(&acc2[i >> 1][j + 0]);
            float2 p1 = *reinterpret_cast<const float2*>(&acc2[i >> 1][j + 1]);
            float2 p2 = *reinterpret_cast<const float2*>(&acc2[i >> 1][j + 2]);
            float2 p3 = *reinterpret_cast<const float2*>(&acc2[i >> 1][j + 3]);
            float4 v;
            v.x = ((i & 1) ? p0.y : p0.x) + bvs;
            v.y = ((i & 1) ? p1.y : p1.x) + bvs;
            v.z = ((i & 1) ? p2.y : p2.x) + bvs;
            v.w = ((i & 1) ? p3.y : p3.x) + bvs;
            if (res) {
                float4 r = *reinterpret_cast<const float4*>(res + idx + j);
                v.x += r.x; v.y += r.y; v.z += r.z; v.w += r.w;
            }
            if (act == 1) {
                v.x = fmaxf(v.x, 0.f); v.y = fmaxf(v.y, 0.f);
                v.z = fmaxf(v.z, 0.f); v.w = fmaxf(v.w, 0.f);
            }
            *reinterpret_cast<float4*>(out + idx + j) = v;
        }
    }
}

// ---------------- VQ: one warp per z-vector ----------------
__global__ __launch_bounds__(128) void vq_kernel(
    const float* __restrict__ z, const float* __restrict__ cb,
    float* __restrict__ ek, float* __restrict__ ids_out)
{
    const int warp = threadIdx.x >> 5;
    const int lane = threadIdx.x & 31;
    const int n = blockIdx.x * 4 + warp;
    const int b  = n >> 10;
    const int hw = n & 1023;

    __shared__ float zs[4][ZCH];
    const float* zb = z + (long)b * ZCH * 1024 + hw;
    zs[warp][lane]      = zb[(long)lane * 1024];
    zs[warp][lane + 32] = zb[(long)(lane + 32) * 1024];
    __syncwarp();

    float best = FLT_MAX;
    int bi = 0;
    for (int k = lane; k < KCODE; k += 32) {
        const float* c = cb + k * ZCH;
        float s = 0.f;
        #pragma unroll 16
        for (int ci = 0; ci < ZCH; ci++) {
            float cv = c[ci];
            s = fmaf(cv, cv - 2.f * zs[warp][ci], s);
        }
        if (s < best) { best = s; bi = k; }
    }
    #pragma unroll
    for (int off = 16; off; off >>= 1) {
        float ov = __shfl_down_sync(0xffffffffu, best, off);
        int   oi = __shfl_down_sync(0xffffffffu, bi,   off);
        if (ov < best || (ov == best && oi < bi)) { best = ov; bi = oi; }
    }
    bi = __shfl_sync(0xffffffffu, bi, 0);

    if (lane == 0) ids_out[n] = (float)bi;
    const float* c = cb + bi * ZCH;
    float* ekb = ek + (long)b * ZCH * 1024 + hw;
    ekb[(long)lane * 1024]        = c[lane];
    ekb[(long)(lane + 32) * 1024] = c[lane + 32];
}

// ---------------- t1 subpixel weight prep (fp32) ----------------
__global__ void wt_kernel(const float* __restrict__ w, float* __restrict__ wf)
{
    int i = blockIdx.x * blockDim.x + threadIdx.x;
    const int total = 4 * HIDC * HIDC * 4;
    if (i >= total) return;
    int kx = i & 1, ky = (i >> 1) & 1;
    int r1 = i >> 2;
    int ic = r1 & (HIDC - 1);
    int r2 = r1 >> 8;
    int oc = r2 & (HIDC - 1);
    int pz = r2 >> 8;
    int p = pz >> 1, q = pz & 1;
    wf[i] = w[((long)(ic * HIDC + oc) << 4) + (3 - p - 2 * ky) * 4 + (3 - q - 2 * kx)];
}

// ---------------- t2: direct transposed conv 256->3 + sigmoid ----------------
__global__ __launch_bounds__(128) void t2_kernel(
    const float* __restrict__ in, const float* __restrict__ w,
    const float* __restrict__ bias, float* __restrict__ out)
{
    __shared__ float ws[HIDC][3][8];
    const int oy   = blockIdx.x;
    const int bimg = blockIdx.y;
    const int ox   = threadIdx.x;
    const int p = oy & 1;

    for (int idx = threadIdx.x; idx < HIDC * 3 * 8; idx += 128) {
        int ic = idx / 24;
        int r  = idx - ic * 24;
        int oc = r >> 3;
        int t  = r & 7;
        int kyi = t >> 2, kx = t & 3;
        int ky = p + 2 * kyi;
        ws[ic][oc][t] = w[((long)(ic * 3 + oc) << 4) + (3 - ky) * 4 + (3 - kx)];
    }
    __syncthreads();

    const int q = ox & 1;
    const int iy0 = (oy + p - 2) >> 1;
    const int iy1 = (oy + p) >> 1;
    const int ix0 = (ox + q - 2) >> 1;
    const int ix1 = (ox + q) >> 1;
    const bool vy0 = (iy0 >= 0), vy1 = (iy1 < 64);
    const bool vx0 = (ix0 >= 0), vx1 = (ix1 < 64);

    const float* inb = in + (long)bimg * HIDC * 4096;
    float acc0 = 0.f, acc1 = 0.f, acc2 = 0.f;
    for (int ic = 0; ic < HIDC; ic++) {
        const float* pl = inb + ic * 4096;
        float v00 = (vy0 && vx0) ? pl[iy0 * 64 + ix0] : 0.f;
        float v01 = (vy0 && vx1) ? pl[iy0 * 64 + ix1] : 0.f;
        float v10 = (vy1 && vx0) ? pl[iy1 * 64 + ix0] : 0.f;
        float v11 = (vy1 && vx1) ? pl[iy1 * 64 + ix1] : 0.f;
        const float* wr0 = ws[ic][0];
        const float* wr1 = ws[ic][1];
        const float* wr2 = ws[ic][2];
        acc0 = fmaf(v00, wr0[q], fmaf(v01, wr0[q+2], fmaf(v10, wr0[4+q], fmaf(v11, wr0[4+q+2], acc0))));
        acc1 = fmaf(v00, wr1[q], fmaf(v01, wr1[q+2], fmaf(v10, wr1[4+q], fmaf(v11, wr1[4+q+2], acc1))));
        acc2 = fmaf(v00, wr2[q], fmaf(v01, wr2[q+2], fmaf(v10, wr2[4+q], fmaf(v11, wr2[4+q+2], acc2))));
    }
    long ob = ((long)bimg * 3) * 16384 + (long)oy * 128 + ox;
    float s0 = acc0 + bias[0], s1 = acc1 + bias[1], s2 = acc2 + bias[2];
    out[ob]           = 1.f / (1.f + expf(-s0));
    out[ob + 16384]   = 1.f / (1.f + expf(-s1));
    out[ob + 32768]   = 1.f / (1.f + expf(-s2));
}

// ---------------- host ----------------
extern "C" void kernel_launch(void* const* d_in, const int* in_sizes, int n_in,
                              void* d_out, int out_size)
{
    const float* x      = (const float*)d_in[0];
    const float* c1_w   = (const float*)d_in[1];
    const float* c1_b   = (const float*)d_in[2];
    const float* c2_w   = (const float*)d_in[3];
    const float* c2_b   = (const float*)d_in[4];
    const float* r0_w3  = (const float*)d_in[5];
    const float* r0_b3  = (const float*)d_in[6];
    const float* r0_w1  = (const float*)d_in[7];
    const float* r0_b1  = (const float*)d_in[8];
    const float* r1_w3  = (const float*)d_in[9];
    const float* r1_b3  = (const float*)d_in[10];
    const float* r1_w1  = (const float*)d_in[11];
    const float* r1_b1  = (const float*)d_in[12];
    const float* to_z_w = (const float*)d_in[13];
    const float* to_z_b = (const float*)d_in[14];
    const float* codebk = (const float*)d_in[15];
    const float* fz_w   = (const float*)d_in[16];
    const float* fz_b   = (const float*)d_in[17];
    const float* t1_w   = (const float*)d_in[18];
    const float* t1_b   = (const float*)d_in[19];
    const float* t2_w   = (const float*)d_in[20];
    const float* t2_b   = (const float*)d_in[21];
    float* out = (float*)d_out;

    const long ZE_OFF  = 393216;
    const long EK_OFF  = 917504;
    const long IDS_OFF = 1441792;

    float *h1, *h2a, *h2b, *rr, *d1, *d2, *wt1;
    __half *wc2, *wr03, *wr01, *wr13, *wr11, *wfz, *wt1e;
    cudaGetSymbolAddress((void**)&h1,  g_h1);
    cudaGetSymbolAddress((void**)&h2a, g_h2a);
    cudaGetSymbolAddress((void**)&h2b, g_h2b);
    cudaGetSymbolAddress((void**)&rr,  g_rr);
    cudaGetSymbolAddress((void**)&d1,  g_d1);
    cudaGetSymbolAddress((void**)&d2,  g_d2);
    cudaGetSymbolAddress((void**)&wt1, g_wt1);
    cudaGetSymbolAddress((void**)&wc2,  g_wc2);
    cudaGetSymbolAddress((void**)&wr03, g_wr03);
    cudaGetSymbolAddress((void**)&wr01, g_wr01);
    cudaGetSymbolAddress((void**)&wr13, g_wr13);
    cudaGetSymbolAddress((void**)&wr11, g_wr11);
    cudaGetSymbolAddress((void**)&wfz,  g_wfz);
    cudaGetSymbolAddress((void**)&wt1e, g_wt1e);

    // ---- launch order arranged so ncu (-s 5 -c 1) captures the r0 3x3 conv_mma ----
    // (1) c2 weight split
    wsplit16<<<(256 * 4096 + 255) / 256, 256>>>(c2_w,  wc2,  256, 4096);
    // (2) r0 3x3 weight split
    wsplit16<<<(256 * 2304 + 255) / 256, 256>>>(r0_w3, wr03, 256, 2304);
    // (3) c1: 3->256, k4 s2 p1, relu (scalar; K=48)
    conv_gemm<4, 4><<<dim3(256, 4), 256>>>(
        c1_w, x, c1_b, nullptr, h1,
        3, 128, 128, 256, 64, 64, 2, 1, 48, 1, 0, 64, 64);
    // (4) c2: 256->256, k4 s2 p1, relu (mma)
    conv_mma<4, 4, false><<<dim3(128, 4), 256>>>(
        wc2, h1, c2_b, nullptr, h2a,
        256, 64, 64, 256, 32, 32, 2, 1, 4096, 1, 0, 32, 32);
    // (5) r0 1x1 weight split
    wsplit16<<<(256 * 256  + 255) / 256, 256>>>(r0_w1, wr01, 256, 256);
    // (6) r0 3x3 conv (mma)  <-- profiled launch
    conv_mma<3, 3, false><<<dim3(128, 4), 256>>>(
        wr03, h2a, r0_b3, nullptr, rr,
        256, 32, 32, 256, 32, 32, 1, 1, 2304, 0, 1, 32, 32);
    // r0 1x1 (mma)
    conv_mma<1, 1, false><<<dim3(128, 4), 256>>>(
        wr01, rr, r0_b1, h2a, h2b,
        256, 32, 32, 256, 32, 32, 1, 0, 256, 0, 1, 32, 32);
    // r1 weight splits + convs
    wsplit16<<<(256 * 2304 + 255) / 256, 256>>>(r1_w3, wr13, 256, 2304);
    conv_mma<3, 3, false><<<dim3(128, 4), 256>>>(
        wr13, h2b, r1_b3, nullptr, rr,
        256, 32, 32, 256, 32, 32, 1, 1, 2304, 0, 1, 32, 32);
    wsplit16<<<(256 * 256  + 255) / 256, 256>>>(r1_w1, wr11, 256, 256);
    conv_mma<1, 1, false><<<dim3(128, 4), 256>>>(
        wr11, rr, r1_b1, h2b, h2a,
        256, 32, 32, 256, 32, 32, 1, 0, 256, 0, 1, 32, 32);

    // to_z: 256->64, 1x1 (scalar fp32 -> exact z_e for VQ)
    conv_gemm<1, 1><<<dim3(64, 1), 256>>>(
        to_z_w, h2a, to_z_b, nullptr, out + ZE_OFF,
        256, 32, 32, 64, 32, 32, 1, 0, 256, 0, 0, 32, 32);

    // VQ
    vq_kernel<<<2048, 128>>>(out + ZE_OFF, codebk, out + EK_OFF, out + IDS_OFF);

    // from_z: 64->256, 1x1, relu (mma)
    wsplit16<<<(256 * 64 + 255) / 256, 256>>>(fz_w, wfz, 256, 64);
    conv_mma<1, 1, false><<<dim3(128, 4), 256>>>(
        wfz, out + EK_OFF, fz_b, nullptr, d1,
        64, 32, 32, 256, 32, 32, 1, 0, 64, 1, 0, 32, 32);

    // t1: convT 256->256 as 4 subpixel 2x2 convs (mma), relu
    wt_kernel<<<(4 * HIDC * HIDC * 4 + 255) / 256, 256>>>(t1_w, wt1);
    for (int pz = 0; pz < 4; pz++)
        wsplit16<<<(256 * 1024 + 255) / 256, 256>>>(
            wt1 + (long)pz * 256 * 1024, wt1e + (long)pz * 256 * 2048, 256, 1024);
    conv_mma<2, 2, true><<<dim3(128, 4, 4), 256>>>(
        wt1e, d1, t1_b, nullptr, d2,
        256, 32, 32, 256, 32, 32, 1, 0, 1024, 1, 0, 64, 64);

    // t2: direct transposed conv 256->3 + sigmoid
    t2_kernel<<<dim3(128, BATCH), 128>>>(d2, t2_w, t2_b, out);
}

// round 13
// speedup vs baseline: 1.5484x; 1.0587x over previous
#include <cuda_runtime.h>
#include <cuda_fp16.h>
#include <cstdint>
#include <math.h>
#include <float.h>

#define BATCH 8
#define HIDC  256
#define ZCH   64
#define KCODE 512

// ---------------- scratch (device globals; no allocation allowed) ----------------
__device__ float g_h1 [BATCH * HIDC * 64 * 64];  // after c1
__device__ float g_h2a[BATCH * HIDC * 32 * 32];  // ping
__device__ float g_h2b[BATCH * HIDC * 32 * 32];  // pong
__device__ float g_rr [BATCH * HIDC * 32 * 32];  // residual intermediate
__device__ float g_d1 [BATCH * HIDC * 32 * 32];  // decoder stage 1
__device__ float g_d2 [BATCH * HIDC * 64 * 64];  // decoder stage 2
__device__ float g_wt1[4 * HIDC * HIDC * 4];     // subpixel-decomposed t1 weights (fp32)

// packed split activations: per element u32 = {h:lo16 | l:hi16}
__device__ uint32_t g_sp1[BATCH * HIDC * 64 * 64];  // c2 input (32 MB)
__device__ uint32_t g_sp2[BATCH * HIDC * 32 * 32];  // reused by all 32x32 layers

// fp16 split weights: per 32-k chunk: [h32 | ls32] (64 halves = 128B row piece)
__device__ __half g_wc2 [HIDC * 2 * 4096];
__device__ __half g_wr03[HIDC * 2 * 2304];
__device__ __half g_wr01[HIDC * 2 * 256];
__device__ __half g_wr13[HIDC * 2 * 2304];
__device__ __half g_wr11[HIDC * 2 * 256];
__device__ __half g_wfz [HIDC * 2 * 64];
__device__ __half g_wt1e[4 * HIDC * 2 * 1024];

// ================= helpers =================
__device__ __forceinline__ uint32_t smem_u32(const void* p) {
    uint32_t a;
    asm("{ .reg .u64 t; cvta.to.shared.u64 t, %1; cvt.u32.u64 %0, t; }" : "=r"(a) : "l"(p));
    return a;
}
#define SWZ128(o) ((o) ^ (((o) >> 3) & 0x70))
__device__ __forceinline__ void sts128(uint32_t a, uint4 v) {
    asm volatile("st.shared.v4.b32 [%0], {%1,%2,%3,%4};"
                 :: "r"(a), "r"(v.x), "r"(v.y), "r"(v.z), "r"(v.w) : "memory");
}
__device__ __forceinline__ void ldsm4(uint32_t* r, uint32_t addr) {
    asm volatile("ldmatrix.sync.aligned.m8n8.x4.shared.b16 {%0,%1,%2,%3}, [%4];"
                 : "=r"(r[0]), "=r"(r[1]), "=r"(r[2]), "=r"(r[3]) : "r"(addr));
}
__device__ __forceinline__ void mma16816(float* c, const uint32_t* a, const uint32_t* b) {
    asm volatile(
        "mma.sync.aligned.m16n8k16.row.col.f32.f16.f16.f32 "
        "{%0,%1,%2,%3}, {%4,%5,%6,%7}, {%8,%9}, {%0,%1,%2,%3};"
        : "+f"(c[0]), "+f"(c[1]), "+f"(c[2]), "+f"(c[3])
        : "r"(a[0]), "r"(a[1]), "r"(a[2]), "r"(a[3]), "r"(b[0]), "r"(b[1]));
}
__device__ __forceinline__ uint32_t prmt(uint32_t a, uint32_t b, uint32_t sel) {
    uint32_t r;
    asm("prmt.b32 %0, %1, %2, %3;" : "=r"(r) : "r"(a), "r"(b), "r"(sel));
    return r;
}
__device__ __forceinline__ uint32_t packsplit(float v) {
    __half h = __float2half_rn(v);
    __half l = __float2half_rn((v - __half2float(h)) * 2048.0f);
    return (uint32_t)__half_as_ushort(h) | ((uint32_t)__half_as_ushort(l) << 16);
}

// ======= weight split: fp32 -> per-32k-chunk [h32|ls32] fp16 rows =======
__global__ void wsplit16(const float* __restrict__ W, __half* __restrict__ E,
                         int Cout, int K)
{
    int i = blockIdx.x * blockDim.x + threadIdx.x;
    if (i >= Cout * K) return;
    int oc = i / K, k = i - oc * K;
    int c = k >> 5, j = k & 31;
    float v = W[i];
    __half h = __float2half_rn(v);
    __half ls = __float2half_rn((v - __half2float(h)) * 2048.0f);
    long base = (long)oc * 2 * K + (long)c * 64;
    E[base + j]      = h;
    E[base + 32 + j] = ls;
}

// ======= activation split: fp32 NCHW -> packed {h,l} u32 NCHW (vectorized) =======
__global__ void asplit(const float* __restrict__ in, uint32_t* __restrict__ outp,
                       int n4, int relu)
{
    int i = blockIdx.x * blockDim.x + threadIdx.x;
    if (i >= n4) return;
    float4 v = reinterpret_cast<const float4*>(in)[i];
    if (relu) {
        v.x = fmaxf(v.x, 0.f); v.y = fmaxf(v.y, 0.f);
        v.z = fmaxf(v.z, 0.f); v.w = fmaxf(v.w, 0.f);
    }
    uint4 o;
    o.x = packsplit(v.x); o.y = packsplit(v.y);
    o.z = packsplit(v.z); o.w = packsplit(v.w);
    reinterpret_cast<uint4*>(outp)[i] = o;
}

// =======================================================================
// mma.sync implicit-GEMM conv (fp16 2-way split w/ rescale, 3 terms).
//   CTA: 64 oc x 64 px. BK=32. 8 warps as 4(m) x 2(n); warp tile 16x32.
// Round-13: input pre-split to packed u32 (no cvt in gather; prmt unpack),
// and register-prefetch software pipeline (LDGs overlap the mma block).
// acc_h += ha*hb ; acc_l += ha*lsb + lsa*hb ; out = acc_h + acc_l/2048.
// =======================================================================
template<int KH, int KW, bool SUBPIX>
__global__ __launch_bounds__(256, 2) void conv_mma(
    const __half* __restrict__ Wc,      // [(SUBPIX?4:1)][Cout][2K] fp16 split
    const uint32_t* __restrict__ inp,   // packed {h,l} per element, NCHW
    const float* __restrict__ bias, const float* __restrict__ res,
    float* __restrict__ out,
    int Cin, int Hin, int Win, int Cout, int Hout, int Wout,
    int stride, int pad, int K, int act,
    int Hfull, int Wfull)
{
    constexpr int KHW = KH * KW;
    __shared__ __align__(16) char sAm[64 * 128];
    __shared__ __align__(16) char sBm[64 * 128];

    const int tid  = threadIdx.x;
    const int wid  = tid >> 5;
    const int lane = tid & 31;
    const int m0 = blockIdx.y * 64;
    const int n0 = blockIdx.x * 64;
    const int HW = Hout * Wout;

    const uint32_t sA = smem_u32(sAm);
    const uint32_t sB = smem_u32(sBm);

    int par_y = 0, par_x = 0;
    const __half* Wb = Wc;
    if (SUBPIX) {
        int pz = blockIdx.z;
        par_y = pz >> 1; par_x = pz & 1;
        Wb += (long)pz * Cout * 2 * K;
    }

    // ---- B gather mapping: px = tid&63, seg = tid>>6 covers 8 k ----
    const int px  = tid & 63;
    const int seg = tid >> 6;
    const int n   = n0 + px;
    const int bimg = n / HW;
    const int hw   = n - bimg * HW;
    const int oy   = hw / Wout, ox = hw - oy * Wout;
    const uint32_t* inb = inp + (long)bimg * Cin * Hin * Win;
    int iy0, ix0;
    if (SUBPIX) { iy0 = oy - (1 - par_y); ix0 = ox - (1 - par_x); }
    else        { iy0 = oy * stride - pad; ix0 = ox * stride - pad; }

    // ---- warp compute mapping: warp tile 16(m) x 32(n) ----
    const int wm = (wid & 3) * 16;
    const int wn = (wid >> 2) * 32;

    float acc[4][4];
    float accl[4][4];
    #pragma unroll
    for (int nt = 0; nt < 4; nt++)
        #pragma unroll
        for (int e = 0; e < 4; e++) { acc[nt][e] = 0.f; accl[nt][e] = 0.f; }

    const long K2 = 2 * (long)K;      // halves per oc row
    const int nc_iters = K / 32;

    // A load mapping (constant across chunks)
    const int arow = tid >> 3;
    const int ac16 = tid & 7;
    const __half* Arow0 = Wb + (long)(m0 + arow) * K2 + ac16 * 8;
    const __half* Arow1 = Wb + (long)(m0 + arow + 32) * K2 + ac16 * 8;

    uint4 av[2];
    uint32_t raw[8];

    auto loadA = [&](int cb) {
        const long kb = (long)cb * 64;
        av[0] = *reinterpret_cast<const uint4*>(Arow0 + kb);
        av[1] = *reinterpret_cast<const uint4*>(Arow1 + kb);
    };
    auto loadB = [&](int cb) {
        const int kb = cb * 32 + seg * 8;
        #pragma unroll
        for (int e = 0; e < 8; e++) {
            int k = kb + e;
            int ic, ky, kx;
            if (KHW == 1) { ic = k; ky = 0; kx = 0; }
            else { ic = k / KHW; int r2 = k - ic * KHW; ky = r2 / KW; kx = r2 - ky * KW; }
            int iy = iy0 + ky, ix = ix0 + kx;
            uint32_t pv = 0;
            if ((unsigned)iy < (unsigned)Hin && (unsigned)ix < (unsigned)Win)
                pv = inb[(ic * Hin + iy) * Win + ix];
            raw[e] = pv;
        }
    };
    auto storeTiles = [&]() {
        sts128(sA + SWZ128(arow * 128 + ac16 * 16), av[0]);
        sts128(sA + SWZ128((arow + 32) * 128 + ac16 * 16), av[1]);
        uint32_t hp[4], lp[4];
        #pragma unroll
        for (int q = 0; q < 4; q++) {
            hp[q] = prmt(raw[2 * q], raw[2 * q + 1], 0x5410);
            lp[q] = prmt(raw[2 * q], raw[2 * q + 1], 0x7632);
        }
        sts128(sB + SWZ128(px * 128 + seg * 16),      make_uint4(hp[0], hp[1], hp[2], hp[3]));
        sts128(sB + SWZ128(px * 128 + 64 + seg * 16), make_uint4(lp[0], lp[1], lp[2], lp[3]));
    };

    loadA(0);
    loadB(0);

    for (int cb = 0; cb < nc_iters; cb++) {
        storeTiles();
        __syncthreads();
        if (cb + 1 < nc_iters) {      // prefetch next chunk; LDGs overlap mma below
            loadA(cb + 1);
            loadB(cb + 1);
        }
        // ---- compute: 2 k16-steps x 3 terms ----
        #pragma unroll
        for (int s = 0; s < 2; s++) {
            uint32_t Ah[4], Al[4];
            {
                int row = wm + (lane & 15);
                int kby = s * 32 + ((lane >> 4) << 4);
                ldsm4(Ah, sA + SWZ128(row * 128 + kby));
                ldsm4(Al, sA + SWZ128(row * 128 + 64 + kby));
            }
            uint32_t Bh[2][4], Bl[2][4];
            #pragma unroll
            for (int ntp = 0; ntp < 2; ntp++) {
                int nrow = wn + ntp * 16 + ((lane >> 4) << 3) + (lane & 7);
                int kby  = s * 32 + (((lane >> 3) & 1) << 4);
                ldsm4(Bh[ntp], sB + SWZ128(nrow * 128 + kby));
                ldsm4(Bl[ntp], sB + SWZ128(nrow * 128 + 64 + kby));
            }
            #pragma unroll
            for (int nt = 0; nt < 4; nt++) {
                const uint32_t* bh = &Bh[nt >> 1][(nt & 1) * 2];
                const uint32_t* bl = &Bl[nt >> 1][(nt & 1) * 2];
                mma16816(acc[nt],  Ah, bh);
                mma16816(accl[nt], Ah, bl);
                mma16816(accl[nt], Al, bh);
            }
        }
        __syncthreads();
    }

    // ---- epilogue ----
    const float INV = 1.0f / 2048.0f;
    const long HWf = (long)Hfull * Wfull;
    const int bimg0 = n0 / HW;
    const int hw0 = n0 - bimg0 * HW;
    const long obase = (long)bimg0 * Cout * HWf;

    #pragma unroll
    for (int nt = 0; nt < 4; nt++) {
        float c0 = acc[nt][0] + accl[nt][0] * INV;
        float c1 = acc[nt][1] + accl[nt][1] * INV;
        float c2 = acc[nt][2] + accl[nt][2] * INV;
        float c3 = acc[nt][3] + accl[nt][3] * INV;
        int oc0 = m0 + wm + (lane >> 2);
        int oc1 = oc0 + 8;
        int ncol = hw0 + wn + nt * 8 + (lane & 3) * 2;
        float b0 = bias[oc0], b1 = bias[oc1];
        c0 += b0; c1 += b0; c2 += b1; c3 += b1;
        if (!SUBPIX) {
            long i0 = obase + (long)oc0 * HWf + ncol;
            long i1 = obase + (long)oc1 * HWf + ncol;
            if (res) {
                float2 r0 = *reinterpret_cast<const float2*>(res + i0);
                float2 r1 = *reinterpret_cast<const float2*>(res + i1);
                c0 += r0.x; c1 += r0.y; c2 += r1.x; c3 += r1.y;
            }
            if (act == 1) {
                c0 = fmaxf(c0, 0.f); c1 = fmaxf(c1, 0.f);
                c2 = fmaxf(c2, 0.f); c3 = fmaxf(c3, 0.f);
            }
            *reinterpret_cast<float2*>(out + i0) = make_float2(c0, c1);
            *reinterpret_cast<float2*>(out + i1) = make_float2(c2, c3);
        } else {
            if (act == 1) {
                c0 = fmaxf(c0, 0.f); c1 = fmaxf(c1, 0.f);
                c2 = fmaxf(c2, 0.f); c3 = fmaxf(c3, 0.f);
            }
            int eoy0 = ncol / Wout, eox0 = ncol - eoy0 * Wout;
            int nc1 = ncol + 1;
            int eoy1 = nc1 / Wout, eox1 = nc1 - eoy1 * Wout;
            long fy0 = 2 * eoy0 + par_y, fx0 = 2 * eox0 + par_x;
            long fy1 = 2 * eoy1 + par_y, fx1 = 2 * eox1 + par_x;
            out[obase + (long)oc0 * HWf + fy0 * Wfull + fx0] = c0;
            out[obase + (long)oc0 * HWf + fy1 * Wfull + fx1] = c1;
            out[obase + (long)oc1 * HWf + fy0 * Wfull + fx0] = c2;
            out[obase + (long)oc1 * HWf + fy1 * Wfull + fx1] = c3;
        }
    }
}

// =======================================================================
// scalar implicit-GEMM (round-6, known good) — c1 and to_z only
// =======================================================================
__device__ __forceinline__ void fma2(unsigned long long& d, unsigned long long a,
                                     unsigned long long b)
{
    asm("fma.rn.f32x2 %0, %1, %2, %0;" : "+l"(d) : "l"(a), "l"(b));
}
__device__ __forceinline__ unsigned long long dup2v(float v)
{
    unsigned long long r;
    asm("mov.b64 %0, {%1, %1};" : "=l"(r) : "f"(v));
    return r;
}

template<int KH, int KW>
__global__ __launch_bounds__(256, 2) void conv_gemm(
    const float* __restrict__ A, const float* __restrict__ in,
    const float* __restrict__ bias, const float* __restrict__ res,
    float* __restrict__ out,
    int Cin, int Hin, int Win, int Cout, int Hout, int Wout,
    int stride, int pad, int K, int act, int inRelu,
    int Hfull, int Wfull)
{
    constexpr int BM = 64, BN = 128, BK = 8, TN = 8, TP = 2;
    constexpr int KHW = KH * KW;
    __shared__ float As[2][BK][BM];
    __shared__ float Bs[2][BK][BN];

    const int tid = threadIdx.x;
    const int m0 = blockIdx.y * BM;
    const int n0 = blockIdx.x * BN;
    const int HW = Hout * Wout;

    const int bn = tid & (BN - 1);
    const int bk = (tid >> 7) << 2;
    const int n  = n0 + bn;
    const int bimg = n / HW;
    const int hw   = n - bimg * HW;
    const int oy   = hw / Wout;
    const int ox   = hw - oy * Wout;
    const float* inb = in + (long)bimg * Cin * Hin * Win;
    const int iy0 = oy * stride - pad;
    const int ix0 = ox * stride - pad;

    const int am = tid >> 1;
    const int ak = (tid & 1) << 2;
    const bool aload = (tid < 128);
    const float* Arow = aload ? (A + (long)(m0 + am) * K + ak) : A;

    const int rm = (tid & 15) * 4;
    const int rn = (tid >> 4) * TN;
    unsigned long long acc2[TP][TN];
    #pragma unroll
    for (int i = 0; i < TP; i++)
        #pragma unroll
        for (int j = 0; j < TN; j++) acc2[i][j] = 0ull;

    auto gatherB = [&](int k0, float* bv) {
        #pragma unroll
        for (int i = 0; i < 4; i++) {
            int k  = k0 + bk + i;
            int ic = k / KHW;
            int rr2 = k - ic * KHW;
            int ky = rr2 / KW;
            int kx = rr2 - ky * KW;
            int iy = iy0 + ky;
            int ix = ix0 + kx;
            float v = 0.f;
            if ((unsigned)iy < (unsigned)Hin && (unsigned)ix < (unsigned)Win)
                v = inb[(ic * Hin + iy) * Win + ix];
            if (inRelu) v = fmaxf(v, 0.f);
            bv[i] = v;
        }
    };

    const int nt = K / BK;
    float4 av;
    float  bv[4];

    if (aload) av = *reinterpret_cast<const float4*>(Arow);
    gatherB(0, bv);
    if (aload) {
        As[0][ak + 0][am] = av.x; As[0][ak + 1][am] = av.y;
        As[0][ak + 2][am] = av.z; As[0][ak + 3][am] = av.w;
    }
    #pragma unroll
    for (int i = 0; i < 4; i++) Bs[0][bk + i][bn] = bv[i];
    __syncthreads();

    int cur = 0;
    for (int t = 0; t < nt; t++) {
        if (t + 1 < nt) {
            int k0n = (t + 1) * BK;
            if (aload) av = *reinterpret_cast<const float4*>(Arow + k0n);
            gatherB(k0n, bv);
        }
        #pragma unroll
        for (int kk = 0; kk < BK; kk++) {
            ulonglong2 ua = *reinterpret_cast<const ulonglong2*>(&As[cur][kk][rm]);
            float b[TN];
            *reinterpret_cast<float4*>(&b[0]) = *reinterpret_cast<const float4*>(&Bs[cur][kk][rn]);
            *reinterpret_cast<float4*>(&b[4]) = *reinterpret_cast<const float4*>(&Bs[cur][kk][rn + 4]);
            #pragma unroll
            for (int j = 0; j < TN; j++) {
                unsigned long long bd = dup2v(b[j]);
                fma2(acc2[0][j], ua.x, bd);
                fma2(acc2[1][j], ua.y, bd);
            }
        }
        if (t + 1 < nt) {
            int nx = cur ^ 1;
            if (aload) {
                As[nx][ak + 0][am] = av.x; As[nx][ak + 1][am] = av.y;
                As[nx][ak + 2][am] = av.z; As[nx][ak + 3][am] = av.w;
            }
            #pragma unroll
            for (int i = 0; i < 4; i++) Bs[nx][bk + i][bn] = bv[i];
            __syncthreads();
            cur = nx;
        }
    }

    const int nb  = n0 + rn;
    const int b2  = nb / HW;
    const int hwb = nb - b2 * HW;
    const long HWf = (long)Hfull * Wfull;
    const long base = (long)b2 * Cout * HWf;

    #pragma unroll
    for (int i = 0; i < 4; i++) {
        const int oc = m0 + rm + i;
        const float bvs = bias[oc];
        long idx = base + (long)oc * HWf + hwb;
        #pragma unroll
        for (int j = 0; j < TN; j += 4) {
            float2 p0 = *reinterpret_cast<const float2*>(&acc2[i >> 1][j + 0]);
            float2 p1 = *reinterpret_cast<const float2*>(&acc2[i >> 1][j + 1]);
            float2 p2 = *reinterpret_cast<const float2*>(&acc2[i >> 1][j + 2]);
            float2 p3 = *reinterpret_cast<const float2*>(&acc2[i >> 1][j + 3]);
            float4 v;
            v.x = ((i & 1) ? p0.y : p0.x) + bvs;
            v.y = ((i & 1) ? p1.y : p1.x) + bvs;
            v.z = ((i & 1) ? p2.y : p2.x) + bvs;
            v.w = ((i & 1) ? p3.y : p3.x) + bvs;
            if (res) {
                float4 r = *reinterpret_cast<const float4*>(res + idx + j);
                v.x += r.x; v.y += r.y; v.z += r.z; v.w += r.w;
            }
            if (act == 1) {
                v.x = fmaxf(v.x, 0.f); v.y = fmaxf(v.y, 0.f);
                v.z = fmaxf(v.z, 0.f); v.w = fmaxf(v.w, 0.f);
            }
            *reinterpret_cast<float4*>(out + idx + j) = v;
        }
    }
}

// ---------------- VQ: one warp per z-vector ----------------
__global__ __launch_bounds__(128) void vq_kernel(
    const float* __restrict__ z, const float* __restrict__ cb,
    float* __restrict__ ek, float* __restrict__ ids_out)
{
    const int warp = threadIdx.x >> 5;
    const int lane = threadIdx.x & 31;
    const int n = blockIdx.x * 4 + warp;
    const int b  = n >> 10;
    const int hw = n & 1023;

    __shared__ float zs[4][ZCH];
    const float* zb = z + (long)b * ZCH * 1024 + hw;
    zs[warp][lane]      = zb[(long)lane * 1024];
    zs[warp][lane + 32] = zb[(long)(lane + 32) * 1024];
    __syncwarp();

    float best = FLT_MAX;
    int bi = 0;
    for (int k = lane; k < KCODE; k += 32) {
        const float* c = cb + k * ZCH;
        float s = 0.f;
        #pragma unroll 16
        for (int ci = 0; ci < ZCH; ci++) {
            float cv = c[ci];
            s = fmaf(cv, cv - 2.f * zs[warp][ci], s);
        }
        if (s < best) { best = s; bi = k; }
    }
    #pragma unroll
    for (int off = 16; off; off >>= 1) {
        float ov = __shfl_down_sync(0xffffffffu, best, off);
        int   oi = __shfl_down_sync(0xffffffffu, bi,   off);
        if (ov < best || (ov == best && oi < bi)) { best = ov; bi = oi; }
    }
    bi = __shfl_sync(0xffffffffu, bi, 0);

    if (lane == 0) ids_out[n] = (float)bi;
    const float* c = cb + bi * ZCH;
    float* ekb = ek + (long)b * ZCH * 1024 + hw;
    ekb[(long)lane * 1024]        = c[lane];
    ekb[(long)(lane + 32) * 1024] = c[lane + 32];
}

// ---------------- t1 subpixel weight prep (fp32) ----------------
__global__ void wt_kernel(const float* __restrict__ w, float* __restrict__ wf)
{
    int i = blockIdx.x * blockDim.x + threadIdx.x;
    const int total = 4 * HIDC * HIDC * 4;
    if (i >= total) return;
    int kx = i & 1, ky = (i >> 1) & 1;
    int r1 = i >> 2;
    int ic = r1 & (HIDC - 1);
    int r2 = r1 >> 8;
    int oc = r2 & (HIDC - 1);
    int pz = r2 >> 8;
    int p = pz >> 1, q = pz & 1;
    wf[i] = w[((long)(ic * HIDC + oc) << 4) + (3 - p - 2 * ky) * 4 + (3 - q - 2 * kx)];
}

// ---------------- t2: direct transposed conv 256->3 + sigmoid ----------------
__global__ __launch_bounds__(128) void t2_kernel(
    const float* __restrict__ in, const float* __restrict__ w,
    const float* __restrict__ bias, float* __restrict__ out)
{
    __shared__ float ws[HIDC][3][8];
    const int oy   = blockIdx.x;
    const int bimg = blockIdx.y;
    const int ox   = threadIdx.x;
    const int p = oy & 1;

    for (int idx = threadIdx.x; idx < HIDC * 3 * 8; idx += 128) {
        int ic = idx / 24;
        int r  = idx - ic * 24;
        int oc = r >> 3;
        int t  = r & 7;
        int kyi = t >> 2, kx = t & 3;
        int ky = p + 2 * kyi;
        ws[ic][oc][t] = w[((long)(ic * 3 + oc) << 4) + (3 - ky) * 4 + (3 - kx)];
    }
    __syncthreads();

    const int q = ox & 1;
    const int iy0 = (oy + p - 2) >> 1;
    const int iy1 = (oy + p) >> 1;
    const int ix0 = (ox + q - 2) >> 1;
    const int ix1 = (ox + q) >> 1;
    const bool vy0 = (iy0 >= 0), vy1 = (iy1 < 64);
    const bool vx0 = (ix0 >= 0), vx1 = (ix1 < 64);

    const float* inb = in + (long)bimg * HIDC * 4096;
    float acc0 = 0.f, acc1 = 0.f, acc2 = 0.f;
    for (int ic = 0; ic < HIDC; ic++) {
        const float* pl = inb + ic * 4096;
        float v00 = (vy0 && vx0) ? pl[iy0 * 64 + ix0] : 0.f;
        float v01 = (vy0 && vx1) ? pl[iy0 * 64 + ix1] : 0.f;
        float v10 = (vy1 && vx0) ? pl[iy1 * 64 + ix0] : 0.f;
        float v11 = (vy1 && vx1) ? pl[iy1 * 64 + ix1] : 0.f;
        const float* wr0 = ws[ic][0];
        const float* wr1 = ws[ic][1];
        const float* wr2 = ws[ic][2];
        acc0 = fmaf(v00, wr0[q], fmaf(v01, wr0[q+2], fmaf(v10, wr0[4+q], fmaf(v11, wr0[4+q+2], acc0))));
        acc1 = fmaf(v00, wr1[q], fmaf(v01, wr1[q+2], fmaf(v10, wr1[4+q], fmaf(v11, wr1[4+q+2], acc1))));
        acc2 = fmaf(v00, wr2[q], fmaf(v01, wr2[q+2], fmaf(v10, wr2[4+q], fmaf(v11, wr2[4+q+2], acc2))));
    }
    long ob = ((long)bimg * 3) * 16384 + (long)oy * 128 + ox;
    float s0 = acc0 + bias[0], s1 = acc1 + bias[1], s2 = acc2 + bias[2];
    out[ob]           = 1.f / (1.f + expf(-s0));
    out[ob + 16384]   = 1.f / (1.f + expf(-s1));
    out[ob + 32768]   = 1.f / (1.f + expf(-s2));
}

// ---------------- host ----------------
extern "C" void kernel_launch(void* const* d_in, const int* in_sizes, int n_in,
                              void* d_out, int out_size)
{
    const float* x      = (const float*)d_in[0];
    const float* c1_w   = (const float*)d_in[1];
    const float* c1_b   = (const float*)d_in[2];
    const float* c2_w   = (const float*)d_in[3];
    const float* c2_b   = (const float*)d_in[4];
    const float* r0_w3  = (const float*)d_in[5];
    const float* r0_b3  = (const float*)d_in[6];
    const float* r0_w1  = (const float*)d_in[7];
    const float* r0_b1  = (const float*)d_in[8];
    const float* r1_w3  = (const float*)d_in[9];
    const float* r1_b3  = (const float*)d_in[10];
    const float* r1_w1  = (const float*)d_in[11];
    const float* r1_b1  = (const float*)d_in[12];
    const float* to_z_w = (const float*)d_in[13];
    const float* to_z_b = (const float*)d_in[14];
    const float* codebk = (const float*)d_in[15];
    const float* fz_w   = (const float*)d_in[16];
    const float* fz_b   = (const float*)d_in[17];
    const float* t1_w   = (const float*)d_in[18];
    const float* t1_b   = (const float*)d_in[19];
    const float* t2_w   = (const float*)d_in[20];
    const float* t2_b   = (const float*)d_in[21];
    float* out = (float*)d_out;

    const long ZE_OFF  = 393216;
    const long EK_OFF  = 917504;
    const long IDS_OFF = 1441792;

    float *h1, *h2a, *h2b, *rr, *d1, *d2, *wt1;
    uint32_t *sp1, *sp2;
    __half *wc2, *wr03, *wr01, *wr13, *wr11, *wfz, *wt1e;
    cudaGetSymbolAddress((void**)&h1,  g_h1);
    cudaGetSymbolAddress((void**)&h2a, g_h2a);
    cudaGetSymbolAddress((void**)&h2b, g_h2b);
    cudaGetSymbolAddress((void**)&rr,  g_rr);
    cudaGetSymbolAddress((void**)&d1,  g_d1);
    cudaGetSymbolAddress((void**)&d2,  g_d2);
    cudaGetSymbolAddress((void**)&wt1, g_wt1);
    cudaGetSymbolAddress((void**)&sp1, g_sp1);
    cudaGetSymbolAddress((void**)&sp2, g_sp2);
    cudaGetSymbolAddress((void**)&wc2,  g_wc2);
    cudaGetSymbolAddress((void**)&wr03, g_wr03);
    cudaGetSymbolAddress((void**)&wr01, g_wr01);
    cudaGetSymbolAddress((void**)&wr13, g_wr13);
    cudaGetSymbolAddress((void**)&wr11, g_wr11);
    cudaGetSymbolAddress((void**)&wfz,  g_wfz);
    cudaGetSymbolAddress((void**)&wt1e, g_wt1e);

    const int N1 = BATCH * HIDC * 4096;   // h1 elements
    const int N2 = BATCH * HIDC * 1024;   // 32x32 layer elements
    const int NZ = BATCH * ZCH  * 1024;   // ek elements

    // ---- launch order arranged so ncu (-s 5 -c 1) captures c2 conv_mma ----
    // (1) c2 weight split
    wsplit16<<<(256 * 4096 + 255) / 256, 256>>>(c2_w,  wc2,  256, 4096);
    // (2) r0 3x3 weight split
    wsplit16<<<(256 * 2304 + 255) / 256, 256>>>(r0_w3, wr03, 256, 2304);
    // (3) c1: 3->256, k4 s2 p1, relu (scalar; K=48)
    conv_gemm<4, 4><<<dim3(256, 4), 256>>>(
        c1_w, x, c1_b, nullptr, h1,
        3, 128, 128, 256, 64, 64, 2, 1, 48, 1, 0, 64, 64);
    // (4) split h1 (already relu'd)
    asplit<<<(N1 / 4 + 255) / 256, 256>>>(h1, sp1, N1 / 4, 0);
    // (5) r0 1x1 weight split
    wsplit16<<<(256 * 256  + 255) / 256, 256>>>(r0_w1, wr01, 256, 256);
    // (6) c2: 256->256, k4 s2 p1, relu (mma)  <-- profiled launch
    conv_mma<4, 4, false><<<dim3(128, 4), 256>>>(
        wc2, sp1, c2_b, nullptr, h2a,
        256, 64, 64, 256, 32, 32, 2, 1, 4096, 1, 32, 32);

    // r0 3x3: input relu(h2a)
    asplit<<<(N2 / 4 + 255) / 256, 256>>>(h2a, sp2, N2 / 4, 1);
    conv_mma<3, 3, false><<<dim3(128, 4), 256>>>(
        wr03, sp2, r0_b3, nullptr, rr,
        256, 32, 32, 256, 32, 32, 1, 1, 2304, 0, 32, 32);
    // r0 1x1: input relu(rr), res = h2a
    asplit<<<(N2 / 4 + 255) / 256, 256>>>(rr, sp2, N2 / 4, 1);
    conv_mma<1, 1, false><<<dim3(128, 4), 256>>>(
        wr01, sp2, r0_b1, h2a, h2b,
        256, 32, 32, 256, 32, 32, 1, 0, 256, 0, 32, 32);
    // r1 3x3
    wsplit16<<<(256 * 2304 + 255) / 256, 256>>>(r1_w3, wr13, 256, 2304);
    asplit<<<(N2 / 4 + 255) / 256, 256>>>(h2b, sp2, N2 / 4, 1);
    conv_mma<3, 3, false><<<dim3(128, 4), 256>>>(
        wr13, sp2, r1_b3, nullptr, rr,
        256, 32, 32, 256, 32, 32, 1, 1, 2304, 0, 32, 32);
    // r1 1x1
    wsplit16<<<(256 * 256  + 255) / 256, 256>>>(r1_w1, wr11, 256, 256);
    asplit<<<(N2 / 4 + 255) / 256, 256>>>(rr, sp2, N2 / 4, 1);
    conv_mma<1, 1, false><<<dim3(128, 4), 256>>>(
        wr11, sp2, r1_b1, h2b, h2a,
        256, 32, 32, 256, 32, 32, 1, 0, 256, 0, 32, 32);

    // to_z: 256->64, 1x1 (scalar fp32 -> exact z_e for VQ)
    conv_gemm<1, 1><<<dim3(64, 1), 256>>>(
        to_z_w, h2a, to_z_b, nullptr, out + ZE_OFF,
        256, 32, 32, 64, 32, 32, 1, 0, 256, 0, 0, 32, 32);

    // VQ
    vq_kernel<<<2048, 128>>>(out + ZE_OFF, codebk, out + EK_OFF, out + IDS_OFF);

    // from_z: 64->256, 1x1, relu (mma)
    wsplit16<<<(256 * 64 + 255) / 256, 256>>>(fz_w, wfz, 256, 64);
    asplit<<<(NZ / 4 + 255) / 256, 256>>>(out + EK_OFF, sp2, NZ / 4, 0);
    conv_mma<1, 1, false><<<dim3(128, 4), 256>>>(
        wfz, sp2, fz_b, nullptr, d1,
        64, 32, 32, 256, 32, 32, 1, 0, 64, 1, 32, 32);

    // t1: convT 256->256 as 4 subpixel 2x2 convs (mma), relu
    wt_kernel<<<(4 * HIDC * HIDC * 4 + 255) / 256, 256>>>(t1_w, wt1);
    for (int pz = 0; pz < 4; pz++)
        wsplit16<<<(256 * 1024 + 255) / 256, 256>>>(
            wt1 + (long)pz * 256 * 1024, wt1e + (long)pz * 256 * 2048, 256, 1024);
    asplit<<<(N2 / 4 + 255) / 256, 256>>>(d1, sp2, N2 / 4, 0);
    conv_mma<2, 2, true><<<dim3(128, 4, 4), 256>>>(
        wt1e, sp2, t1_b, nullptr, d2,
        256, 32, 32, 256, 32, 32, 1, 0, 1024, 1, 64, 64);

    // t2: direct transposed conv 256->3 + sigmoid
    t2_kernel<<<dim3(128, BATCH), 128>>>(d2, t2_w, t2_b, out);
}

// round 14
// speedup vs baseline: 1.5729x; 1.0158x over previous
#include <cuda_runtime.h>
#include <cuda_fp16.h>
#include <cstdint>
#include <math.h>
#include <float.h>

#define BATCH 8
#define HIDC  256
#define ZCH   64
#define KCODE 512

// ---------------- scratch (device globals; no allocation allowed) ----------------
__device__ float g_h1 [BATCH * HIDC * 64 * 64];  // after c1
__device__ float g_h2a[BATCH * HIDC * 32 * 32];  // ping
__device__ float g_h2b[BATCH * HIDC * 32 * 32];  // pong
__device__ float g_rr [BATCH * HIDC * 32 * 32];  // residual intermediate
__device__ float g_d1 [BATCH * HIDC * 32 * 32];  // decoder stage 1
__device__ float g_d2 [BATCH * HIDC * 64 * 64];  // decoder stage 2
__device__ float g_wt1[4 * HIDC * HIDC * 4];     // subpixel-decomposed t1 weights (fp32)

// packed split activations: per element u32 = {h:lo16 | l:hi16}
__device__ uint32_t g_sp1[BATCH * HIDC * 64 * 64];  // c2 input (32 MB)
__device__ uint32_t g_sp2[BATCH * HIDC * 32 * 32];  // reused by all 32x32 layers

// fp16 split weights: per 32-k chunk: [h32 | ls32] (64 halves = 128B row piece)
__device__ __half g_wc2 [HIDC * 2 * 4096];
__device__ __half g_wr03[HIDC * 2 * 2304];
__device__ __half g_wr01[HIDC * 2 * 256];
__device__ __half g_wr13[HIDC * 2 * 2304];
__device__ __half g_wr11[HIDC * 2 * 256];
__device__ __half g_wfz [HIDC * 2 * 64];
__device__ __half g_wt1e[4 * HIDC * 2 * 1024];

// ================= helpers =================
__device__ __forceinline__ uint32_t smem_u32(const void* p) {
    uint32_t a;
    asm("{ .reg .u64 t; cvta.to.shared.u64 t, %1; cvt.u32.u64 %0, t; }" : "=r"(a) : "l"(p));
    return a;
}
#define SWZ128(o) ((o) ^ (((o) >> 3) & 0x70))
__device__ __forceinline__ void sts128(uint32_t a, uint4 v) {
    asm volatile("st.shared.v4.b32 [%0], {%1,%2,%3,%4};"
                 :: "r"(a), "r"(v.x), "r"(v.y), "r"(v.z), "r"(v.w) : "memory");
}
__device__ __forceinline__ void ldsm4(uint32_t* r, uint32_t addr) {
    asm volatile("ldmatrix.sync.aligned.m8n8.x4.shared.b16 {%0,%1,%2,%3}, [%4];"
                 : "=r"(r[0]), "=r"(r[1]), "=r"(r[2]), "=r"(r[3]) : "r"(addr));
}
__device__ __forceinline__ void mma16816(float* c, const uint32_t* a, const uint32_t* b) {
    asm volatile(
        "mma.sync.aligned.m16n8k16.row.col.f32.f16.f16.f32 "
        "{%0,%1,%2,%3}, {%4,%5,%6,%7}, {%8,%9}, {%0,%1,%2,%3};"
        : "+f"(c[0]), "+f"(c[1]), "+f"(c[2]), "+f"(c[3])
        : "r"(a[0]), "r"(a[1]), "r"(a[2]), "r"(a[3]), "r"(b[0]), "r"(b[1]));
}
__device__ __forceinline__ uint32_t prmt(uint32_t a, uint32_t b, uint32_t sel) {
    uint32_t r;
    asm("prmt.b32 %0, %1, %2, %3;" : "=r"(r) : "r"(a), "r"(b), "r"(sel));
    return r;
}
__device__ __forceinline__ uint32_t packsplit(float v) {
    __half h = __float2half_rn(v);
    __half l = __float2half_rn((v - __half2float(h)) * 2048.0f);
    return (uint32_t)__half_as_ushort(h) | ((uint32_t)__half_as_ushort(l) << 16);
}

// ======= weight split: fp32 -> per-32k-chunk [h32|ls32] fp16 rows =======
__global__ void wsplit16(const float* __restrict__ W, __half* __restrict__ E,
                         int Cout, int K)
{
    int i = blockIdx.x * blockDim.x + threadIdx.x;
    if (i >= Cout * K) return;
    int oc = i / K, k = i - oc * K;
    int c = k >> 5, j = k & 31;
    float v = W[i];
    __half h = __float2half_rn(v);
    __half ls = __float2half_rn((v - __half2float(h)) * 2048.0f);
    long base = (long)oc * 2 * K + (long)c * 64;
    E[base + j]      = h;
    E[base + 32 + j] = ls;
}

// ======= activation split: fp32 NCHW -> packed {h,l} u32 NCHW (vectorized) =======
__global__ void asplit(const float* __restrict__ in, uint32_t* __restrict__ outp,
                       int n4, int relu)
{
    int i = blockIdx.x * blockDim.x + threadIdx.x;
    if (i >= n4) return;
    float4 v = reinterpret_cast<const float4*>(in)[i];
    if (relu) {
        v.x = fmaxf(v.x, 0.f); v.y = fmaxf(v.y, 0.f);
        v.z = fmaxf(v.z, 0.f); v.w = fmaxf(v.w, 0.f);
    }
    uint4 o;
    o.x = packsplit(v.x); o.y = packsplit(v.y);
    o.z = packsplit(v.z); o.w = packsplit(v.w);
    reinterpret_cast<uint4*>(outp)[i] = o;
}

// =======================================================================
// mma.sync implicit-GEMM conv (fp16 2-way split w/ rescale, 3 terms).
//   CTA: 64 oc x 64 px. BK=32. 8 warps as 4(m) x 2(n); warp tile 16x32.
// Round-14: DOUBLE-BUFFERED smem (one barrier per chunk; STS of next chunk
// overlaps the mma block of the current one). 32 KB smem, 2 CTAs/SM.
// acc_h += ha*hb ; acc_l += ha*lsb + lsa*hb ; out = acc_h + acc_l/2048.
// =======================================================================
template<int KH, int KW, bool SUBPIX>
__global__ __launch_bounds__(256, 2) void conv_mma(
    const __half* __restrict__ Wc,      // [(SUBPIX?4:1)][Cout][2K] fp16 split
    const uint32_t* __restrict__ inp,   // packed {h,l} per element, NCHW
    const float* __restrict__ bias, const float* __restrict__ res,
    float* __restrict__ out,
    int Cin, int Hin, int Win, int Cout, int Hout, int Wout,
    int stride, int pad, int K, int act,
    int Hfull, int Wfull)
{
    constexpr int KHW = KH * KW;
    __shared__ __align__(16) char sAm[2][64 * 128];
    __shared__ __align__(16) char sBm[2][64 * 128];

    const int tid  = threadIdx.x;
    const int wid  = tid >> 5;
    const int lane = tid & 31;
    const int m0 = blockIdx.y * 64;
    const int n0 = blockIdx.x * 64;
    const int HW = Hout * Wout;

    uint32_t sAb[2], sBb[2];
    sAb[0] = smem_u32(sAm[0]); sAb[1] = smem_u32(sAm[1]);
    sBb[0] = smem_u32(sBm[0]); sBb[1] = smem_u32(sBm[1]);

    int par_y = 0, par_x = 0;
    const __half* Wb = Wc;
    if (SUBPIX) {
        int pz = blockIdx.z;
        par_y = pz >> 1; par_x = pz & 1;
        Wb += (long)pz * Cout * 2 * K;
    }

    // ---- B gather mapping: px = tid&63, seg = tid>>6 covers 8 k ----
    const int px  = tid & 63;
    const int seg = tid >> 6;
    const int n   = n0 + px;
    const int bimg = n / HW;
    const int hw   = n - bimg * HW;
    const int oy   = hw / Wout, ox = hw - oy * Wout;
    const uint32_t* inb = inp + (long)bimg * Cin * Hin * Win;
    int iy0, ix0;
    if (SUBPIX) { iy0 = oy - (1 - par_y); ix0 = ox - (1 - par_x); }
    else        { iy0 = oy * stride - pad; ix0 = ox * stride - pad; }

    // ---- warp compute mapping: warp tile 16(m) x 32(n) ----
    const int wm = (wid & 3) * 16;
    const int wn = (wid >> 2) * 32;

    float acc[4][4];
    float accl[4][4];
    #pragma unroll
    for (int nt = 0; nt < 4; nt++)
        #pragma unroll
        for (int e = 0; e < 4; e++) { acc[nt][e] = 0.f; accl[nt][e] = 0.f; }

    const long K2 = 2 * (long)K;      // halves per oc row
    const int nc_iters = K / 32;

    // A load mapping (constant across chunks)
    const int arow = tid >> 3;
    const int ac16 = tid & 7;
    const __half* Arow0 = Wb + (long)(m0 + arow) * K2 + ac16 * 8;
    const __half* Arow1 = Wb + (long)(m0 + arow + 32) * K2 + ac16 * 8;

    uint4 av[2];
    uint32_t raw[8];

    auto loadA = [&](int cb) {
        const long kb = (long)cb * 64;
        av[0] = *reinterpret_cast<const uint4*>(Arow0 + kb);
        av[1] = *reinterpret_cast<const uint4*>(Arow1 + kb);
    };
    auto loadB = [&](int cb) {
        const int kb = cb * 32 + seg * 8;
        #pragma unroll
        for (int e = 0; e < 8; e++) {
            int k = kb + e;
            int ic, ky, kx;
            if (KHW == 1) { ic = k; ky = 0; kx = 0; }
            else { ic = k / KHW; int r2 = k - ic * KHW; ky = r2 / KW; kx = r2 - ky * KW; }
            int iy = iy0 + ky, ix = ix0 + kx;
            uint32_t pv = 0;
            if ((unsigned)iy < (unsigned)Hin && (unsigned)ix < (unsigned)Win)
                pv = inb[(ic * Hin + iy) * Win + ix];
            raw[e] = pv;
        }
    };
    auto storeTiles = [&](int buf) {
        sts128(sAb[buf] + SWZ128(arow * 128 + ac16 * 16), av[0]);
        sts128(sAb[buf] + SWZ128((arow + 32) * 128 + ac16 * 16), av[1]);
        uint32_t hp[4], lp[4];
        #pragma unroll
        for (int q = 0; q < 4; q++) {
            hp[q] = prmt(raw[2 * q], raw[2 * q + 1], 0x5410);
            lp[q] = prmt(raw[2 * q], raw[2 * q + 1], 0x7632);
        }
        sts128(sBb[buf] + SWZ128(px * 128 + seg * 16),      make_uint4(hp[0], hp[1], hp[2], hp[3]));
        sts128(sBb[buf] + SWZ128(px * 128 + 64 + seg * 16), make_uint4(lp[0], lp[1], lp[2], lp[3]));
    };

    loadA(0);
    loadB(0);
    storeTiles(0);
    __syncthreads();

    int cur = 0;
    for (int cb = 0; cb < nc_iters; cb++) {
        if (cb + 1 < nc_iters) {      // prefetch next chunk (LDGs overlap mma below)
            loadA(cb + 1);
            loadB(cb + 1);
        }
        const uint32_t sA = sAb[cur];
        const uint32_t sB = sBb[cur];
        // ---- compute: 2 k16-steps x 3 terms ----
        #pragma unroll
        for (int s = 0; s < 2; s++) {
            uint32_t Ah[4], Al[4];
            {
                int row = wm + (lane & 15);
                int kby = s * 32 + ((lane >> 4) << 4);
                ldsm4(Ah, sA + SWZ128(row * 128 + kby));
                ldsm4(Al, sA + SWZ128(row * 128 + 64 + kby));
            }
            uint32_t Bh[2][4], Bl[2][4];
            #pragma unroll
            for (int ntp = 0; ntp < 2; ntp++) {
                int nrow = wn + ntp * 16 + ((lane >> 4) << 3) + (lane & 7);
                int kby  = s * 32 + (((lane >> 3) & 1) << 4);
                ldsm4(Bh[ntp], sB + SWZ128(nrow * 128 + kby));
                ldsm4(Bl[ntp], sB + SWZ128(nrow * 128 + 64 + kby));
            }
            #pragma unroll
            for (int nt = 0; nt < 4; nt++) {
                const uint32_t* bh = &Bh[nt >> 1][(nt & 1) * 2];
                const uint32_t* bl = &Bl[nt >> 1][(nt & 1) * 2];
                mma16816(acc[nt],  Ah, bh);
                mma16816(accl[nt], Ah, bl);
                mma16816(accl[nt], Al, bh);
            }
        }
        if (cb + 1 < nc_iters) {
            storeTiles(cur ^ 1);      // write OTHER buffer; no pre-barrier needed
            __syncthreads();          // single barrier per chunk
            cur ^= 1;
        }
    }

    // ---- epilogue ----
    const float INV = 1.0f / 2048.0f;
    const long HWf = (long)Hfull * Wfull;
    const int bimg0 = n0 / HW;
    const int hw0 = n0 - bimg0 * HW;
    const long obase = (long)bimg0 * Cout * HWf;

    #pragma unroll
    for (int nt = 0; nt < 4; nt++) {
        float c0 = acc[nt][0] + accl[nt][0] * INV;
        float c1 = acc[nt][1] + accl[nt][1] * INV;
        float c2 = acc[nt][2] + accl[nt][2] * INV;
        float c3 = acc[nt][3] + accl[nt][3] * INV;
        int oc0 = m0 + wm + (lane >> 2);
        int oc1 = oc0 + 8;
        int ncol = hw0 + wn + nt * 8 + (lane & 3) * 2;
        float b0 = bias[oc0], b1 = bias[oc1];
        c0 += b0; c1 += b0; c2 += b1; c3 += b1;
        if (!SUBPIX) {
            long i0 = obase + (long)oc0 * HWf + ncol;
            long i1 = obase + (long)oc1 * HWf + ncol;
            if (res) {
                float2 r0 = *reinterpret_cast<const float2*>(res + i0);
                float2 r1 = *reinterpret_cast<const float2*>(res + i1);
                c0 += r0.x; c1 += r0.y; c2 += r1.x; c3 += r1.y;
            }
            if (act == 1) {
                c0 = fmaxf(c0, 0.f); c1 = fmaxf(c1, 0.f);
                c2 = fmaxf(c2, 0.f); c3 = fmaxf(c3, 0.f);
            }
            *reinterpret_cast<float2*>(out + i0) = make_float2(c0, c1);
            *reinterpret_cast<float2*>(out + i1) = make_float2(c2, c3);
        } else {
            if (act == 1) {
                c0 = fmaxf(c0, 0.f); c1 = fmaxf(c1, 0.f);
                c2 = fmaxf(c2, 0.f); c3 = fmaxf(c3, 0.f);
            }
            int eoy0 = ncol / Wout, eox0 = ncol - eoy0 * Wout;
            int nc1 = ncol + 1;
            int eoy1 = nc1 / Wout, eox1 = nc1 - eoy1 * Wout;
            long fy0 = 2 * eoy0 + par_y, fx0 = 2 * eox0 + par_x;
            long fy1 = 2 * eoy1 + par_y, fx1 = 2 * eox1 + par_x;
            out[obase + (long)oc0 * HWf + fy0 * Wfull + fx0] = c0;
            out[obase + (long)oc0 * HWf + fy1 * Wfull + fx1] = c1;
            out[obase + (long)oc1 * HWf + fy0 * Wfull + fx0] = c2;
            out[obase + (long)oc1 * HWf + fy1 * Wfull + fx1] = c3;
        }
    }
}

// =======================================================================
// scalar implicit-GEMM (round-6, known good) — c1 and to_z only
// =======================================================================
__device__ __forceinline__ void fma2(unsigned long long& d, unsigned long long a,
                                     unsigned long long b)
{
    asm("fma.rn.f32x2 %0, %1, %2, %0;" : "+l"(d) : "l"(a), "l"(b));
}
__device__ __forceinline__ unsigned long long dup2v(float v)
{
    unsigned long long r;
    asm("mov.b64 %0, {%1, %1};" : "=l"(r) : "f"(v));
    return r;
}

template<int KH, int KW>
__global__ __launch_bounds__(256, 2) void conv_gemm(
    const float* __restrict__ A, const float* __restrict__ in,
    const float* __restrict__ bias, const float* __restrict__ res,
    float* __restrict__ out,
    int Cin, int Hin, int Win, int Cout, int Hout, int Wout,
    int stride, int pad, int K, int act, int inRelu,
    int Hfull, int Wfull)
{
    constexpr int BM = 64, BN = 128, BK = 8, TN = 8, TP = 2;
    constexpr int KHW = KH * KW;
    __shared__ float As[2][BK][BM];
    __shared__ float Bs[2][BK][BN];

    const int tid = threadIdx.x;
    const int m0 = blockIdx.y * BM;
    const int n0 = blockIdx.x * BN;
    const int HW = Hout * Wout;

    const int bn = tid & (BN - 1);
    const int bk = (tid >> 7) << 2;
    const int n  = n0 + bn;
    const int bimg = n / HW;
    const int hw   = n - bimg * HW;
    const int oy   = hw / Wout;
    const int ox   = hw - oy * Wout;
    const float* inb = in + (long)bimg * Cin * Hin * Win;
    const int iy0 = oy * stride - pad;
    const int ix0 = ox * stride - pad;

    const int am = tid >> 1;
    const int ak = (tid & 1) << 2;
    const bool aload = (tid < 128);
    const float* Arow = aload ? (A + (long)(m0 + am) * K + ak) : A;

    const int rm = (tid & 15) * 4;
    const int rn = (tid >> 4) * TN;
    unsigned long long acc2[TP][TN];
    #pragma unroll
    for (int i = 0; i < TP; i++)
        #pragma unroll
        for (int j = 0; j < TN; j++) acc2[i][j] = 0ull;

    auto gatherB = [&](int k0, float* bv) {
        #pragma unroll
        for (int i = 0; i < 4; i++) {
            int k  = k0 + bk + i;
            int ic = k / KHW;
            int rr2 = k - ic * KHW;
            int ky = rr2 / KW;
            int kx = rr2 - ky * KW;
            int iy = iy0 + ky;
            int ix = ix0 + kx;
            float v = 0.f;
            if ((unsigned)iy < (unsigned)Hin && (unsigned)ix < (unsigned)Win)
                v = inb[(ic * Hin + iy) * Win + ix];
            if (inRelu) v = fmaxf(v, 0.f);
            bv[i] = v;
        }
    };

    const int nt = K / BK;
    float4 av;
    float  bv[4];

    if (aload) av = *reinterpret_cast<const float4*>(Arow);
    gatherB(0, bv);
    if (aload) {
        As[0][ak + 0][am] = av.x; As[0][ak + 1][am] = av.y;
        As[0][ak + 2][am] = av.z; As[0][ak + 3][am] = av.w;
    }
    #pragma unroll
    for (int i = 0; i < 4; i++) Bs[0][bk + i][bn] = bv[i];
    __syncthreads();

    int cur = 0;
    for (int t = 0; t < nt; t++) {
        if (t + 1 < nt) {
            int k0n = (t + 1) * BK;
            if (aload) av = *reinterpret_cast<const float4*>(Arow + k0n);
            gatherB(k0n, bv);
        }
        #pragma unroll
        for (int kk = 0; kk < BK; kk++) {
            ulonglong2 ua = *reinterpret_cast<const ulonglong2*>(&As[cur][kk][rm]);
            float b[TN];
            *reinterpret_cast<float4*>(&b[0]) = *reinterpret_cast<const float4*>(&Bs[cur][kk][rn]);
            *reinterpret_cast<float4*>(&b[4]) = *reinterpret_cast<const float4*>(&Bs[cur][kk][rn + 4]);
            #pragma unroll
            for (int j = 0; j < TN; j++) {
                unsigned long long bd = dup2v(b[j]);
                fma2(acc2[0][j], ua.x, bd);
                fma2(acc2[1][j], ua.y, bd);
            }
        }
        if (t + 1 < nt) {
            int nx = cur ^ 1;
            if (aload) {
                As[nx][ak + 0][am] = av.x; As[nx][ak + 1][am] = av.y;
                As[nx][ak + 2][am] = av.z; As[nx][ak + 3][am] = av.w;
            }
            #pragma unroll
            for (int i = 0; i < 4; i++) Bs[nx][bk + i][bn] = bv[i];
            __syncthreads();
            cur = nx;
        }
    }

    const int nb  = n0 + rn;
    const int b2  = nb / HW;
    const int hwb = nb - b2 * HW;
    const long HWf = (long)Hfull * Wfull;
    const long base = (long)b2 * Cout * HWf;

    #pragma unroll
    for (int i = 0; i < 4; i++) {
        const int oc = m0 + rm + i;
        const float bvs = bias[oc];
        long idx = base + (long)oc * HWf + hwb;
        #pragma unroll
        for (int j = 0; j < TN; j += 4) {
            float2 p0 = *reinterpret_cast<const float2*>(&acc2[i >> 1][j + 0]);
            float2 p1 = *reinterpret_cast<const float2*>(&acc2[i >> 1][j + 1]);
            float2 p2 = *reinterpret_cast<const float2*>(&acc2[i >> 1][j + 2]);
            float2 p3 = *reinterpret_cast<const float2*>(&acc2[i >> 1][j + 3]);
            float4 v;
            v.x = ((i & 1) ? p0.y : p0.x) + bvs;
            v.y = ((i & 1) ? p1.y : p1.x) + bvs;
            v.z = ((i & 1) ? p2.y : p2.x) + bvs;
            v.w = ((i & 1) ? p3.y : p3.x) + bvs;
            if (res) {
                float4 r = *reinterpret_cast<const float4*>(res + idx + j);
                v.x += r.x; v.y += r.y; v.z += r.z; v.w += r.w;
            }
            if (act == 1) {
                v.x = fmaxf(v.x, 0.f); v.y = fmaxf(v.y, 0.f);
                v.z = fmaxf(v.z, 0.f); v.w = fmaxf(v.w, 0.f);
            }
            *reinterpret_cast<float4*>(out + idx + j) = v;
        }
    }
}

// ---------------- VQ: one warp per z-vector ----------------
__global__ __launch_bounds__(128) void vq_kernel(
    const float* __restrict__ z, const float* __restrict__ cb,
    float* __restrict__ ek, float* __restrict__ ids_out)
{
    const int warp = threadIdx.x >> 5;
    const int lane = threadIdx.x & 31;
    const int n = blockIdx.x * 4 + warp;
    const int b  = n >> 10;
    const int hw = n & 1023;

    __shared__ float zs[4][ZCH];
    const float* zb = z + (long)b * ZCH * 1024 + hw;
    zs[warp][lane]      = zb[(long)lane * 1024];
    zs[warp][lane + 32] = zb[(long)(lane + 32) * 1024];
    __syncwarp();

    float best = FLT_MAX;
    int bi = 0;
    for (int k = lane; k < KCODE; k += 32) {
        const float* c = cb + k * ZCH;
        float s = 0.f;
        #pragma unroll 16
        for (int ci = 0; ci < ZCH; ci++) {
            float cv = c[ci];
            s = fmaf(cv, cv - 2.f * zs[warp][ci], s);
        }
        if (s < best) { best = s; bi = k; }
    }
    #pragma unroll
    for (int off = 16; off; off >>= 1) {
        float ov = __shfl_down_sync(0xffffffffu, best, off);
        int   oi = __shfl_down_sync(0xffffffffu, bi,   off);
        if (ov < best || (ov == best && oi < bi)) { best = ov; bi = oi; }
    }
    bi = __shfl_sync(0xffffffffu, bi, 0);

    if (lane == 0) ids_out[n] = (float)bi;
    const float* c = cb + bi * ZCH;
    float* ekb = ek + (long)b * ZCH * 1024 + hw;
    ekb[(long)lane * 1024]        = c[lane];
    ekb[(long)(lane + 32) * 1024] = c[lane + 32];
}

// ---------------- t1 subpixel weight prep (fp32) ----------------
__global__ void wt_kernel(const float* __restrict__ w, float* __restrict__ wf)
{
    int i = blockIdx.x * blockDim.x + threadIdx.x;
    const int total = 4 * HIDC * HIDC * 4;
    if (i >= total) return;
    int kx = i & 1, ky = (i >> 1) & 1;
    int r1 = i >> 2;
    int ic = r1 & (HIDC - 1);
    int r2 = r1 >> 8;
    int oc = r2 & (HIDC - 1);
    int pz = r2 >> 8;
    int p = pz >> 1, q = pz & 1;
    wf[i] = w[((long)(ic * HIDC + oc) << 4) + (3 - p - 2 * ky) * 4 + (3 - q - 2 * kx)];
}

// ---------------- t2: direct transposed conv 256->3 + sigmoid ----------------
__global__ __launch_bounds__(128) void t2_kernel(
    const float* __restrict__ in, const float* __restrict__ w,
    const float* __restrict__ bias, float* __restrict__ out)
{
    __shared__ float ws[HIDC][3][8];
    const int oy   = blockIdx.x;
    const int bimg = blockIdx.y;
    const int ox   = threadIdx.x;
    const int p = oy & 1;

    for (int idx = threadIdx.x; idx < HIDC * 3 * 8; idx += 128) {
        int ic = idx / 24;
        int r  = idx - ic * 24;
        int oc = r >> 3;
        int t  = r & 7;
        int kyi = t >> 2, kx = t & 3;
        int ky = p + 2 * kyi;
        ws[ic][oc][t] = w[((long)(ic * 3 + oc) << 4) + (3 - ky) * 4 + (3 - kx)];
    }
    __syncthreads();

    const int q = ox & 1;
    const int iy0 = (oy + p - 2) >> 1;
    const int iy1 = (oy + p) >> 1;
    const int ix0 = (ox + q - 2) >> 1;
    const int ix1 = (ox + q) >> 1;
    const bool vy0 = (iy0 >= 0), vy1 = (iy1 < 64);
    const bool vx0 = (ix0 >= 0), vx1 = (ix1 < 64);

    const float* inb = in + (long)bimg * HIDC * 4096;
    float acc0 = 0.f, acc1 = 0.f, acc2 = 0.f;
    for (int ic = 0; ic < HIDC; ic++) {
        const float* pl = inb + ic * 4096;
        float v00 = (vy0 && vx0) ? pl[iy0 * 64 + ix0] : 0.f;
        float v01 = (vy0 && vx1) ? pl[iy0 * 64 + ix1] : 0.f;
        float v10 = (vy1 && vx0) ? pl[iy1 * 64 + ix0] : 0.f;
        float v11 = (vy1 && vx1) ? pl[iy1 * 64 + ix1] : 0.f;
        const float* wr0 = ws[ic][0];
        const float* wr1 = ws[ic][1];
        const float* wr2 = ws[ic][2];
        acc0 = fmaf(v00, wr0[q], fmaf(v01, wr0[q+2], fmaf(v10, wr0[4+q], fmaf(v11, wr0[4+q+2], acc0))));
        acc1 = fmaf(v00, wr1[q], fmaf(v01, wr1[q+2], fmaf(v10, wr1[4+q], fmaf(v11, wr1[4+q+2], acc1))));
        acc2 = fmaf(v00, wr2[q], fmaf(v01, wr2[q+2], fmaf(v10, wr2[4+q], fmaf(v11, wr2[4+q+2], acc2))));
    }
    long ob = ((long)bimg * 3) * 16384 + (long)oy * 128 + ox;
    float s0 = acc0 + bias[0], s1 = acc1 + bias[1], s2 = acc2 + bias[2];
    out[ob]           = 1.f / (1.f + expf(-s0));
    out[ob + 16384]   = 1.f / (1.f + expf(-s1));
    out[ob + 32768]   = 1.f / (1.f + expf(-s2));
}

// ---------------- host ----------------
extern "C" void kernel_launch(void* const* d_in, const int* in_sizes, int n_in,
                              void* d_out, int out_size)
{
    const float* x      = (const float*)d_in[0];
    const float* c1_w   = (const float*)d_in[1];
    const float* c1_b   = (const float*)d_in[2];
    const float* c2_w   = (const float*)d_in[3];
    const float* c2_b   = (const float*)d_in[4];
    const float* r0_w3  = (const float*)d_in[5];
    const float* r0_b3  = (const float*)d_in[6];
    const float* r0_w1  = (const float*)d_in[7];
    const float* r0_b1  = (const float*)d_in[8];
    const float* r1_w3  = (const float*)d_in[9];
    const float* r1_b3  = (const float*)d_in[10];
    const float* r1_w1  = (const float*)d_in[11];
    const float* r1_b1  = (const float*)d_in[12];
    const float* to_z_w = (const float*)d_in[13];
    const float* to_z_b = (const float*)d_in[14];
    const float* codebk = (const float*)d_in[15];
    const float* fz_w   = (const float*)d_in[16];
    const float* fz_b   = (const float*)d_in[17];
    const float* t1_w   = (const float*)d_in[18];
    const float* t1_b   = (const float*)d_in[19];
    const float* t2_w   = (const float*)d_in[20];
    const float* t2_b   = (const float*)d_in[21];
    float* out = (float*)d_out;

    const long ZE_OFF  = 393216;
    const long EK_OFF  = 917504;
    const long IDS_OFF = 1441792;

    float *h1, *h2a, *h2b, *rr, *d1, *d2, *wt1;
    uint32_t *sp1, *sp2;
    __half *wc2, *wr03, *wr01, *wr13, *wr11, *wfz, *wt1e;
    cudaGetSymbolAddress((void**)&h1,  g_h1);
    cudaGetSymbolAddress((void**)&h2a, g_h2a);
    cudaGetSymbolAddress((void**)&h2b, g_h2b);
    cudaGetSymbolAddress((void**)&rr,  g_rr);
    cudaGetSymbolAddress((void**)&d1,  g_d1);
    cudaGetSymbolAddress((void**)&d2,  g_d2);
    cudaGetSymbolAddress((void**)&wt1, g_wt1);
    cudaGetSymbolAddress((void**)&sp1, g_sp1);
    cudaGetSymbolAddress((void**)&sp2, g_sp2);
    cudaGetSymbolAddress((void**)&wc2,  g_wc2);
    cudaGetSymbolAddress((void**)&wr03, g_wr03);
    cudaGetSymbolAddress((void**)&wr01, g_wr01);
    cudaGetSymbolAddress((void**)&wr13, g_wr13);
    cudaGetSymbolAddress((void**)&wr11, g_wr11);
    cudaGetSymbolAddress((void**)&wfz,  g_wfz);
    cudaGetSymbolAddress((void**)&wt1e, g_wt1e);

    const int N1 = BATCH * HIDC * 4096;   // h1 elements
    const int N2 = BATCH * HIDC * 1024;   // 32x32 layer elements
    const int NZ = BATCH * ZCH  * 1024;   // ek elements

    // ---- launch order: c2 conv_mma is the 4th launch (ncu captures #4) ----
    // (1) c2 weight split
    wsplit16<<<(256 * 4096 + 255) / 256, 256>>>(c2_w,  wc2,  256, 4096);
    // (2) c1: 3->256, k4 s2 p1, relu (scalar; K=48)
    conv_gemm<4, 4><<<dim3(256, 4), 256>>>(
        c1_w, x, c1_b, nullptr, h1,
        3, 128, 128, 256, 64, 64, 2, 1, 48, 1, 0, 64, 64);
    // (3) split h1 (already relu'd)
    asplit<<<(N1 / 4 + 255) / 256, 256>>>(h1, sp1, N1 / 4, 0);
    // (4) c2: 256->256, k4 s2 p1, relu (mma)  <-- profiled launch
    conv_mma<4, 4, false><<<dim3(128, 4), 256>>>(
        wc2, sp1, c2_b, nullptr, h2a,
        256, 64, 64, 256, 32, 32, 2, 1, 4096, 1, 32, 32);

    // r0 3x3
    wsplit16<<<(256 * 2304 + 255) / 256, 256>>>(r0_w3, wr03, 256, 2304);
    asplit<<<(N2 / 4 + 255) / 256, 256>>>(h2a, sp2, N2 / 4, 1);
    conv_mma<3, 3, false><<<dim3(128, 4), 256>>>(
        wr03, sp2, r0_b3, nullptr, rr,
        256, 32, 32, 256, 32, 32, 1, 1, 2304, 0, 32, 32);
    // r0 1x1
    wsplit16<<<(256 * 256  + 255) / 256, 256>>>(r0_w1, wr01, 256, 256);
    asplit<<<(N2 / 4 + 255) / 256, 256>>>(rr, sp2, N2 / 4, 1);
    conv_mma<1, 1, false><<<dim3(128, 4), 256>>>(
        wr01, sp2, r0_b1, h2a, h2b,
        256, 32, 32, 256, 32, 32, 1, 0, 256, 0, 32, 32);
    // r1 3x3
    wsplit16<<<(256 * 2304 + 255) / 256, 256>>>(r1_w3, wr13, 256, 2304);
    asplit<<<(N2 / 4 + 255) / 256, 256>>>(h2b, sp2, N2 / 4, 1);
    conv_mma<3, 3, false><<<dim3(128, 4), 256>>>(
        wr13, sp2, r1_b3, nullptr, rr,
        256, 32, 32, 256, 32, 32, 1, 1, 2304, 0, 32, 32);
    // r1 1x1
    wsplit16<<<(256 * 256  + 255) / 256, 256>>>(r1_w1, wr11, 256, 256);
    asplit<<<(N2 / 4 + 255) / 256, 256>>>(rr, sp2, N2 / 4, 1);
    conv_mma<1, 1, false><<<dim3(128, 4), 256>>>(
        wr11, sp2, r1_b1, h2b, h2a,
        256, 32, 32, 256, 32, 32, 1, 0, 256, 0, 32, 32);

    // to_z: 256->64, 1x1 (scalar fp32 -> exact z_e for VQ)
    conv_gemm<1, 1><<<dim3(64, 1), 256>>>(
        to_z_w, h2a, to_z_b, nullptr, out + ZE_OFF,
        256, 32, 32, 64, 32, 32, 1, 0, 256, 0, 0, 32, 32);

    // VQ
    vq_kernel<<<2048, 128>>>(out + ZE_OFF, codebk, out + EK_OFF, out + IDS_OFF);

    // from_z: 64->256, 1x1, relu (mma)
    wsplit16<<<(256 * 64 + 255) / 256, 256>>>(fz_w, wfz, 256, 64);
    asplit<<<(NZ / 4 + 255) / 256, 256>>>(out + EK_OFF, sp2, NZ / 4, 0);
    conv_mma<1, 1, false><<<dim3(128, 4), 256>>>(
        wfz, sp2, fz_b, nullptr, d1,
        64, 32, 32, 256, 32, 32, 1, 0, 64, 1, 32, 32);

    // t1: convT 256->256 as 4 subpixel 2x2 convs (mma), relu
    wt_kernel<<<(4 * HIDC * HIDC * 4 + 255) / 256, 256>>>(t1_w, wt1);
    for (int pz = 0; pz < 4; pz++)
        wsplit16<<<(256 * 1024 + 255) / 256, 256>>>(
            wt1 + (long)pz * 256 * 1024, wt1e + (long)pz * 256 * 2048, 256, 1024);
    asplit<<<(N2 / 4 + 255) / 256, 256>>>(d1, sp2, N2 / 4, 0);
    conv_mma<2, 2, true><<<dim3(128, 4, 4), 256>>>(
        wt1e, sp2, t1_b, nullptr, d2,
        256, 32, 32, 256, 32, 32, 1, 0, 1024, 1, 64, 64);

    // t2: direct transposed conv 256->3 + sigmoid
    t2_kernel<<<dim3(128, BATCH), 128>>>(d2, t2_w, t2_b, out);
}

// round 15
// speedup vs baseline: 1.5766x; 1.0023x over previous
#include <cuda_runtime.h>
#include <cuda_fp16.h>
#include <cstdint>
#include <math.h>
#include <float.h>

#define BATCH 8
#define HIDC  256
#define ZCH   64
#define KCODE 512

// ---------------- scratch (device globals; no allocation allowed) ----------------
__device__ float g_h1 [BATCH * HIDC * 64 * 64];  // after c1
__device__ float g_h2a[BATCH * HIDC * 32 * 32];  // ping
__device__ float g_h2b[BATCH * HIDC * 32 * 32];  // pong
__device__ float g_rr [BATCH * HIDC * 32 * 32];  // residual intermediate
__device__ float g_d1 [BATCH * HIDC * 32 * 32];  // decoder stage 1
__device__ float g_d2 [BATCH * HIDC * 64 * 64];  // decoder stage 2
__device__ float g_wt1[4 * HIDC * HIDC * 4];     // subpixel-decomposed t1 weights (fp32)

// packed split activations: per element u32 = {h:lo16 | l:hi16}
__device__ uint32_t g_sp1[BATCH * HIDC * 64 * 64];  // c2 input (32 MB)
__device__ uint32_t g_sp2[BATCH * HIDC * 32 * 32];  // reused by all 32x32 layers

// fp16 split weights: per 32-k chunk: [h32 | ls32] (64 halves = 128B row piece)
__device__ __half g_wc2 [HIDC * 2 * 4096];
__device__ __half g_wr03[HIDC * 2 * 2304];
__device__ __half g_wr01[HIDC * 2 * 256];
__device__ __half g_wr13[HIDC * 2 * 2304];
__device__ __half g_wr11[HIDC * 2 * 256];
__device__ __half g_wfz [HIDC * 2 * 64];
__device__ __half g_wt1e[4 * HIDC * 2 * 1024];

// ================= helpers =================
__device__ __forceinline__ uint32_t smem_u32(const void* p) {
    uint32_t a;
    asm("{ .reg .u64 t; cvta.to.shared.u64 t, %1; cvt.u32.u64 %0, t; }" : "=r"(a) : "l"(p));
    return a;
}
#define SWZ128(o) ((o) ^ (((o) >> 3) & 0x70))
__device__ __forceinline__ void sts128(uint32_t a, uint4 v) {
    asm volatile("st.shared.v4.b32 [%0], {%1,%2,%3,%4};"
                 :: "r"(a), "r"(v.x), "r"(v.y), "r"(v.z), "r"(v.w) : "memory");
}
__device__ __forceinline__ void cpasync16(uint32_t saddr, const void* gaddr) {
    asm volatile("cp.async.cg.shared.global [%0], [%1], 16;"
                 :: "r"(saddr), "l"(gaddr) : "memory");
}
__device__ __forceinline__ void cpcommit() {
    asm volatile("cp.async.commit_group;" ::: "memory");
}
__device__ __forceinline__ void cpwait0() {
    asm volatile("cp.async.wait_group 0;" ::: "memory");
}
__device__ __forceinline__ void ldsm4(uint32_t* r, uint32_t addr) {
    asm volatile("ldmatrix.sync.aligned.m8n8.x4.shared.b16 {%0,%1,%2,%3}, [%4];"
                 : "=r"(r[0]), "=r"(r[1]), "=r"(r[2]), "=r"(r[3]) : "r"(addr));
}
__device__ __forceinline__ void mma16816(float* c, const uint32_t* a, const uint32_t* b) {
    asm volatile(
        "mma.sync.aligned.m16n8k16.row.col.f32.f16.f16.f32 "
        "{%0,%1,%2,%3}, {%4,%5,%6,%7}, {%8,%9}, {%0,%1,%2,%3};"
        : "+f"(c[0]), "+f"(c[1]), "+f"(c[2]), "+f"(c[3])
        : "r"(a[0]), "r"(a[1]), "r"(a[2]), "r"(a[3]), "r"(b[0]), "r"(b[1]));
}
__device__ __forceinline__ uint32_t prmt(uint32_t a, uint32_t b, uint32_t sel) {
    uint32_t r;
    asm("prmt.b32 %0, %1, %2, %3;" : "=r"(r) : "r"(a), "r"(b), "r"(sel));
    return r;
}
__device__ __forceinline__ uint32_t packsplit(float v) {
    __half h = __float2half_rn(v);
    __half l = __float2half_rn((v - __half2float(h)) * 2048.0f);
    return (uint32_t)__half_as_ushort(h) | ((uint32_t)__half_as_ushort(l) << 16);
}

// ======= weight split: fp32 -> per-32k-chunk [h32|ls32] fp16 rows =======
__global__ void wsplit16(const float* __restrict__ W, __half* __restrict__ E,
                         int Cout, int K)
{
    int i = blockIdx.x * blockDim.x + threadIdx.x;
    if (i >= Cout * K) return;
    int oc = i / K, k = i - oc * K;
    int c = k >> 5, j = k & 31;
    float v = W[i];
    __half h = __float2half_rn(v);
    __half ls = __float2half_rn((v - __half2float(h)) * 2048.0f);
    long base = (long)oc * 2 * K + (long)c * 64;
    E[base + j]      = h;
    E[base + 32 + j] = ls;
}

// ======= activation split: fp32 NCHW -> packed {h,l} u32 NCHW (vectorized) =======
__global__ void asplit(const float* __restrict__ in, uint32_t* __restrict__ outp,
                       int n4, int relu)
{
    int i = blockIdx.x * blockDim.x + threadIdx.x;
    if (i >= n4) return;
    float4 v = reinterpret_cast<const float4*>(in)[i];
    if (relu) {
        v.x = fmaxf(v.x, 0.f); v.y = fmaxf(v.y, 0.f);
        v.z = fmaxf(v.z, 0.f); v.w = fmaxf(v.w, 0.f);
    }
    uint4 o;
    o.x = packsplit(v.x); o.y = packsplit(v.y);
    o.z = packsplit(v.z); o.w = packsplit(v.w);
    reinterpret_cast<uint4*>(outp)[i] = o;
}

// =======================================================================
// mma.sync implicit-GEMM conv (fp16 2-way split w/ rescale, 3 terms).
//   CTA: 64 oc x 64 px. BK=32. 8 warps as 4(m) x 2(n); warp tile 16x32.
// Round-15:
//  * KHW|32 layers: gather addressing hoisted out of the loop (pbase[8] +
//    validity mask precomputed once; per chunk = 1 IMAD + 8 predicated LDGs).
//  * A weight tile staged via cp.async (no reg round-trip, fewer issue slots).
//  * Double-buffered smem (round-14), one barrier per chunk.
// acc_h += ha*hb ; acc_l += ha*lsb + lsa*hb ; out = acc_h + acc_l/2048.
// =======================================================================
template<int KH, int KW, bool SUBPIX>
__global__ __launch_bounds__(256, 2) void conv_mma(
    const __half* __restrict__ Wc,      // [(SUBPIX?4:1)][Cout][2K] fp16 split
    const uint32_t* __restrict__ inp,   // packed {h,l} per element, NCHW
    const float* __restrict__ bias, const float* __restrict__ res,
    float* __restrict__ out,
    int Cin, int Hin, int Win, int Cout, int Hout, int Wout,
    int stride, int pad, int K, int act,
    int Hfull, int Wfull)
{
    constexpr int KHW = KH * KW;
    constexpr bool REGP = (32 % KHW) == 0;   // ky/kx invariant across chunks
    __shared__ __align__(16) char sAm[2][64 * 128];
    __shared__ __align__(16) char sBm[2][64 * 128];

    const int tid  = threadIdx.x;
    const int wid  = tid >> 5;
    const int lane = tid & 31;
    const int m0 = blockIdx.y * 64;
    const int n0 = blockIdx.x * 64;
    const int HW = Hout * Wout;

    uint32_t sAb[2], sBb[2];
    sAb[0] = smem_u32(sAm[0]); sAb[1] = smem_u32(sAm[1]);
    sBb[0] = smem_u32(sBm[0]); sBb[1] = smem_u32(sBm[1]);

    int par_y = 0, par_x = 0;
    const __half* Wb = Wc;
    if (SUBPIX) {
        int pz = blockIdx.z;
        par_y = pz >> 1; par_x = pz & 1;
        Wb += (long)pz * Cout * 2 * K;
    }

    // ---- B gather mapping: px = tid&63, seg = tid>>6 covers 8 k ----
    const int px  = tid & 63;
    const int seg = tid >> 6;
    const int n   = n0 + px;
    const int bimg = n / HW;
    const int hw   = n - bimg * HW;
    const int oy   = hw / Wout, ox = hw - oy * Wout;
    const uint32_t* inb = inp + (long)bimg * Cin * Hin * Win;
    int iy0, ix0;
    if (SUBPIX) { iy0 = oy - (1 - par_y); ix0 = ox - (1 - par_x); }
    else        { iy0 = oy * stride - pad; ix0 = ox * stride - pad; }

    // ---- hoisted gather (REGP path): pbase/validity fixed across chunks ----
    int pbase[8];
    unsigned vmask = 0;
    if (REGP) {
        #pragma unroll
        for (int e = 0; e < 8; e++) {
            int kk = seg * 8 + e;
            int ic0 = kk / KHW;
            int rr = kk - ic0 * KHW;
            int ky = rr / KW, kx = rr - ky * KW;
            int iy = iy0 + ky, ix = ix0 + kx;
            pbase[e] = ic0 * Hin * Win + iy * Win + ix;
            if ((unsigned)iy < (unsigned)Hin && (unsigned)ix < (unsigned)Win)
                vmask |= (1u << e);
        }
    }
    const int dic = REGP ? (32 / KHW) * Hin * Win : 0;

    // ---- warp compute mapping: warp tile 16(m) x 32(n) ----
    const int wm = (wid & 3) * 16;
    const int wn = (wid >> 2) * 32;

    float acc[4][4];
    float accl[4][4];
    #pragma unroll
    for (int nt = 0; nt < 4; nt++)
        #pragma unroll
        for (int e = 0; e < 4; e++) { acc[nt][e] = 0.f; accl[nt][e] = 0.f; }

    const long K2 = 2 * (long)K;      // halves per oc row
    const int nc_iters = K / 32;

    // A staging mapping (constant across chunks)
    const int arow = tid >> 3;
    const int ac16 = tid & 7;
    const __half* Arow0 = Wb + (long)(m0 + arow) * K2 + ac16 * 8;
    const __half* Arow1 = Wb + (long)(m0 + arow + 32) * K2 + ac16 * 8;
    const uint32_t sA0off = SWZ128(arow * 128 + ac16 * 16);
    const uint32_t sA1off = SWZ128((arow + 32) * 128 + ac16 * 16);

    uint32_t raw[8];

    auto issueA = [&](int cb, int buf) {
        const long kb = (long)cb * 64;
        cpasync16(sAb[buf] + sA0off, Arow0 + kb);
        cpasync16(sAb[buf] + sA1off, Arow1 + kb);
    };
    auto loadB = [&](int cb) {
        if (REGP) {
            const int off = cb * dic;
            #pragma unroll
            for (int e = 0; e < 8; e++)
                raw[e] = ((vmask >> e) & 1) ? inb[off + pbase[e]] : 0u;
        } else {
            const int kb = cb * 32 + seg * 8;
            #pragma unroll
            for (int e = 0; e < 8; e++) {
                int k = kb + e;
                int ic = k / KHW;
                int r2 = k - ic * KHW;
                int ky = r2 / KW, kx = r2 - ky * KW;
                int iy = iy0 + ky, ix = ix0 + kx;
                uint32_t pv = 0;
                if ((unsigned)iy < (unsigned)Hin && (unsigned)ix < (unsigned)Win)
                    pv = inb[(ic * Hin + iy) * Win + ix];
                raw[e] = pv;
            }
        }
    };
    auto storeB = [&](int buf) {
        uint32_t hp[4], lp[4];
        #pragma unroll
        for (int q = 0; q < 4; q++) {
            hp[q] = prmt(raw[2 * q], raw[2 * q + 1], 0x5410);
            lp[q] = prmt(raw[2 * q], raw[2 * q + 1], 0x7632);
        }
        sts128(sBb[buf] + SWZ128(px * 128 + seg * 16),      make_uint4(hp[0], hp[1], hp[2], hp[3]));
        sts128(sBb[buf] + SWZ128(px * 128 + 64 + seg * 16), make_uint4(lp[0], lp[1], lp[2], lp[3]));
    };

    issueA(0, 0);
    cpcommit();
    loadB(0);
    cpwait0();
    storeB(0);
    __syncthreads();

    int cur = 0;
    for (int cb = 0; cb < nc_iters; cb++) {
        if (cb + 1 < nc_iters) {      // prefetch next chunk; overlaps mma below
            issueA(cb + 1, cur ^ 1);
            cpcommit();
            loadB(cb + 1);
        }
        const uint32_t sA = sAb[cur];
        const uint32_t sB = sBb[cur];
        // ---- compute: 2 k16-steps x 3 terms ----
        #pragma unroll
        for (int s = 0; s < 2; s++) {
            uint32_t Ah[4], Al[4];
            {
                int row = wm + (lane & 15);
                int kby = s * 32 + ((lane >> 4) << 4);
                ldsm4(Ah, sA + SWZ128(row * 128 + kby));
                ldsm4(Al, sA + SWZ128(row * 128 + 64 + kby));
            }
            uint32_t Bh[2][4], Bl[2][4];
            #pragma unroll
            for (int ntp = 0; ntp < 2; ntp++) {
                int nrow = wn + ntp * 16 + ((lane >> 4) << 3) + (lane & 7);
                int kby  = s * 32 + (((lane >> 3) & 1) << 4);
                ldsm4(Bh[ntp], sB + SWZ128(nrow * 128 + kby));
                ldsm4(Bl[ntp], sB + SWZ128(nrow * 128 + 64 + kby));
            }
            #pragma unroll
            for (int nt = 0; nt < 4; nt++) {
                const uint32_t* bh = &Bh[nt >> 1][(nt & 1) * 2];
                const uint32_t* bl = &Bl[nt >> 1][(nt & 1) * 2];
                mma16816(acc[nt],  Ah, bh);
                mma16816(accl[nt], Ah, bl);
                mma16816(accl[nt], Al, bh);
            }
        }
        if (cb + 1 < nc_iters) {
            cpwait0();                // A tile of next buffer landed
            storeB(cur ^ 1);          // write OTHER buffer
            __syncthreads();          // single barrier per chunk
            cur ^= 1;
        }
    }

    // ---- epilogue ----
    const float INV = 1.0f / 2048.0f;
    const long HWf = (long)Hfull * Wfull;
    const int bimg0 = n0 / HW;
    const int hw0 = n0 - bimg0 * HW;
    const long obase = (long)bimg0 * Cout * HWf;

    #pragma unroll
    for (int nt = 0; nt < 4; nt++) {
        float c0 = acc[nt][0] + accl[nt][0] * INV;
        float c1 = acc[nt][1] + accl[nt][1] * INV;
        float c2 = acc[nt][2] + accl[nt][2] * INV;
        float c3 = acc[nt][3] + accl[nt][3] * INV;
        int oc0 = m0 + wm + (lane >> 2);
        int oc1 = oc0 + 8;
        int ncol = hw0 + wn + nt * 8 + (lane & 3) * 2;
        float b0 = bias[oc0], b1 = bias[oc1];
        c0 += b0; c1 += b0; c2 += b1; c3 += b1;
        if (!SUBPIX) {
            long i0 = obase + (long)oc0 * HWf + ncol;
            long i1 = obase + (long)oc1 * HWf + ncol;
            if (res) {
                float2 r0 = *reinterpret_cast<const float2*>(res + i0);
                float2 r1 = *reinterpret_cast<const float2*>(res + i1);
                c0 += r0.x; c1 += r0.y; c2 += r1.x; c3 += r1.y;
            }
            if (act == 1) {
                c0 = fmaxf(c0, 0.f); c1 = fmaxf(c1, 0.f);
                c2 = fmaxf(c2, 0.f); c3 = fmaxf(c3, 0.f);
            }
            *reinterpret_cast<float2*>(out + i0) = make_float2(c0, c1);
            *reinterpret_cast<float2*>(out + i1) = make_float2(c2, c3);
        } else {
            if (act == 1) {
                c0 = fmaxf(c0, 0.f); c1 = fmaxf(c1, 0.f);
                c2 = fmaxf(c2, 0.f); c3 = fmaxf(c3, 0.f);
            }
            int eoy0 = ncol / Wout, eox0 = ncol - eoy0 * Wout;
            int nc1 = ncol + 1;
            int eoy1 = nc1 / Wout, eox1 = nc1 - eoy1 * Wout;
            long fy0 = 2 * eoy0 + par_y, fx0 = 2 * eox0 + par_x;
            long fy1 = 2 * eoy1 + par_y, fx1 = 2 * eox1 + par_x;
            out[obase + (long)oc0 * HWf + fy0 * Wfull + fx0] = c0;
            out[obase + (long)oc0 * HWf + fy1 * Wfull + fx1] = c1;
            out[obase + (long)oc1 * HWf + fy0 * Wfull + fx0] = c2;
            out[obase + (long)oc1 * HWf + fy1 * Wfull + fx1] = c3;
        }
    }
}

// =======================================================================
// scalar implicit-GEMM (round-6, known good) — c1 and to_z only
// =======================================================================
__device__ __forceinline__ void fma2(unsigned long long& d, unsigned long long a,
                                     unsigned long long b)
{
    asm("fma.rn.f32x2 %0, %1, %2, %0;" : "+l"(d) : "l"(a), "l"(b));
}
__device__ __forceinline__ unsigned long long dup2v(float v)
{
    unsigned long long r;
    asm("mov.b64 %0, {%1, %1};" : "=l"(r) : "f"(v));
    return r;
}

template<int KH, int KW>
__global__ __launch_bounds__(256, 2) void conv_gemm(
    const float* __restrict__ A, const float* __restrict__ in,
    const float* __restrict__ bias, const float* __restrict__ res,
    float* __restrict__ out,
    int Cin, int Hin, int Win, int Cout, int Hout, int Wout,
    int stride, int pad, int K, int act, int inRelu,
    int Hfull, int Wfull)
{
    constexpr int BM = 64, BN = 128, BK = 8, TN = 8, TP = 2;
    constexpr int KHW = KH * KW;
    __shared__ float As[2][BK][BM];
    __shared__ float Bs[2][BK][BN];

    const int tid = threadIdx.x;
    const int m0 = blockIdx.y * BM;
    const int n0 = blockIdx.x * BN;
    const int HW = Hout * Wout;

    const int bn = tid & (BN - 1);
    const int bk = (tid >> 7) << 2;
    const int n  = n0 + bn;
    const int bimg = n / HW;
    const int hw   = n - bimg * HW;
    const int oy   = hw / Wout;
    const int ox   = hw - oy * Wout;
    const float* inb = in + (long)bimg * Cin * Hin * Win;
    const int iy0 = oy * stride - pad;
    const int ix0 = ox * stride - pad;

    const int am = tid >> 1;
    const int ak = (tid & 1) << 2;
    const bool aload = (tid < 128);
    const float* Arow = aload ? (A + (long)(m0 + am) * K + ak) : A;

    const int rm = (tid & 15) * 4;
    const int rn = (tid >> 4) * TN;
    unsigned long long acc2[TP][TN];
    #pragma unroll
    for (int i = 0; i < TP; i++)
        #pragma unroll
        for (int j = 0; j < TN; j++) acc2[i][j] = 0ull;

    auto gatherB = [&](int k0, float* bv) {
        #pragma unroll
        for (int i = 0; i < 4; i++) {
            int k  = k0 + bk + i;
            int ic = k / KHW;
            int rr2 = k - ic * KHW;
            int ky = rr2 / KW;
            int kx = rr2 - ky * KW;
            int iy = iy0 + ky;
            int ix = ix0 + kx;
            float v = 0.f;
            if ((unsigned)iy < (unsigned)Hin && (unsigned)ix < (unsigned)Win)
                v = inb[(ic * Hin + iy) * Win + ix];
            if (inRelu) v = fmaxf(v, 0.f);
            bv[i] = v;
        }
    };

    const int nt = K / BK;
    float4 av;
    float  bv[4];

    if (aload) av = *reinterpret_cast<const float4*>(Arow);
    gatherB(0, bv);
    if (aload) {
        As[0][ak + 0][am] = av.x; As[0][ak + 1][am] = av.y;
        As[0][ak + 2][am] = av.z; As[0][ak + 3][am] = av.w;
    }
    #pragma unroll
    for (int i = 0; i < 4; i++) Bs[0][bk + i][bn] = bv[i];
    __syncthreads();

    int cur = 0;
    for (int t = 0; t < nt; t++) {
        if (t + 1 < nt) {
            int k0n = (t + 1) * BK;
            if (aload) av = *reinterpret_cast<const float4*>(Arow + k0n);
            gatherB(k0n, bv);
        }
        #pragma unroll
        for (int kk = 0; kk < BK; kk++) {
            ulonglong2 ua = *reinterpret_cast<const ulonglong2*>(&As[cur][kk][rm]);
            float b[TN];
            *reinterpret_cast<float4*>(&b[0]) = *reinterpret_cast<const float4*>(&Bs[cur][kk][rn]);
            *reinterpret_cast<float4*>(&b[4]) = *reinterpret_cast<const float4*>(&Bs[cur][kk][rn + 4]);
            #pragma unroll
            for (int j = 0; j < TN; j++) {
                unsigned long long bd = dup2v(b[j]);
                fma2(acc2[0][j], ua.x, bd);
                fma2(acc2[1][j], ua.y, bd);
            }
        }
        if (t + 1 < nt) {
            int nx = cur ^ 1;
            if (aload) {
                As[nx][ak + 0][am] = av.x; As[nx][ak + 1][am] = av.y;
                As[nx][ak + 2][am] = av.z; As[nx][ak + 3][am] = av.w;
            }
            #pragma unroll
            for (int i = 0; i < 4; i++) Bs[nx][bk + i][bn] = bv[i];
            __syncthreads();
            cur = nx;
        }
    }

    const int nb  = n0 + rn;
    const int b2  = nb / HW;
    const int hwb = nb - b2 * HW;
    const long HWf = (long)Hfull * Wfull;
    const long base = (long)b2 * Cout * HWf;

    #pragma unroll
    for (int i = 0; i < 4; i++) {
        const int oc = m0 + rm + i;
        const float bvs = bias[oc];
        long idx = base + (long)oc * HWf + hwb;
        #pragma unroll
        for (int j = 0; j < TN; j += 4) {
            float2 p0 = *reinterpret_cast<const float2*>(&acc2[i >> 1][j + 0]);
            float2 p1 = *reinterpret_cast<const float2*>(&acc2[i >> 1][j + 1]);
            float2 p2 = *reinterpret_cast<const float2*>(&acc2[i >> 1][j + 2]);
            float2 p3 = *reinterpret_cast<const float2*>(&acc2[i >> 1][j + 3]);
            float4 v;
            v.x = ((i & 1) ? p0.y : p0.x) + bvs;
            v.y = ((i & 1) ? p1.y : p1.x) + bvs;
            v.z = ((i & 1) ? p2.y : p2.x) + bvs;
            v.w = ((i & 1) ? p3.y : p3.x) + bvs;
            if (res) {
                float4 r = *reinterpret_cast<const float4*>(res + idx + j);
                v.x += r.x; v.y += r.y; v.z += r.z; v.w += r.w;
            }
            if (act == 1) {
                v.x = fmaxf(v.x, 0.f); v.y = fmaxf(v.y, 0.f);
                v.z = fmaxf(v.z, 0.f); v.w = fmaxf(v.w, 0.f);
            }
            *reinterpret_cast<float4*>(out + idx + j) = v;
        }
    }
}

// ---------------- VQ: one warp per z-vector ----------------
__global__ __launch_bounds__(128) void vq_kernel(
    const float* __restrict__ z, const float* __restrict__ cb,
    float* __restrict__ ek, float* __restrict__ ids_out)
{
    const int warp = threadIdx.x >> 5;
    const int lane = threadIdx.x & 31;
    const int n = blockIdx.x * 4 + warp;
    const int b  = n >> 10;
    const int hw = n & 1023;

    __shared__ float zs[4][ZCH];
    const float* zb = z + (long)b * ZCH * 1024 + hw;
    zs[warp][lane]      = zb[(long)lane * 1024];
    zs[warp][lane + 32] = zb[(long)(lane + 32) * 1024];
    __syncwarp();

    float best = FLT_MAX;
    int bi = 0;
    for (int k = lane; k < KCODE; k += 32) {
        const float* c = cb + k * ZCH;
        float s = 0.f;
        #pragma unroll 16
        for (int ci = 0; ci < ZCH; ci++) {
            float cv = c[ci];
            s = fmaf(cv, cv - 2.f * zs[warp][ci], s);
        }
        if (s < best) { best = s; bi = k; }
    }
    #pragma unroll
    for (int off = 16; off; off >>= 1) {
        float ov = __shfl_down_sync(0xffffffffu, best, off);
        int   oi = __shfl_down_sync(0xffffffffu, bi,   off);
        if (ov < best || (ov == best && oi < bi)) { best = ov; bi = oi; }
    }
    bi = __shfl_sync(0xffffffffu, bi, 0);

    if (lane == 0) ids_out[n] = (float)bi;
    const float* c = cb + bi * ZCH;
    float* ekb = ek + (long)b * ZCH * 1024 + hw;
    ekb[(long)lane * 1024]        = c[lane];
    ekb[(long)(lane + 32) * 1024] = c[lane + 32];
}

// ---------------- t1 subpixel weight prep (fp32) ----------------
__global__ void wt_kernel(const float* __restrict__ w, float* __restrict__ wf)
{
    int i = blockIdx.x * blockDim.x + threadIdx.x;
    const int total = 4 * HIDC * HIDC * 4;
    if (i >= total) return;
    int kx = i & 1, ky = (i >> 1) & 1;
    int r1 = i >> 2;
    int ic = r1 & (HIDC - 1);
    int r2 = r1 >> 8;
    int oc = r2 & (HIDC - 1);
    int pz = r2 >> 8;
    int p = pz >> 1, q = pz & 1;
    wf[i] = w[((long)(ic * HIDC + oc) << 4) + (3 - p - 2 * ky) * 4 + (3 - q - 2 * kx)];
}

// ---------------- t2: direct transposed conv 256->3 + sigmoid ----------------
__global__ __launch_bounds__(128) void t2_kernel(
    const float* __restrict__ in, const float* __restrict__ w,
    const float* __restrict__ bias, float* __restrict__ out)
{
    __shared__ float ws[HIDC][3][8];
    const int oy   = blockIdx.x;
    const int bimg = blockIdx.y;
    const int ox   = threadIdx.x;
    const int p = oy & 1;

    for (int idx = threadIdx.x; idx < HIDC * 3 * 8; idx += 128) {
        int ic = idx / 24;
        int r  = idx - ic * 24;
        int oc = r >> 3;
        int t  = r & 7;
        int kyi = t >> 2, kx = t & 3;
        int ky = p + 2 * kyi;
        ws[ic][oc][t] = w[((long)(ic * 3 + oc) << 4) + (3 - ky) * 4 + (3 - kx)];
    }
    __syncthreads();

    const int q = ox & 1;
    const int iy0 = (oy + p - 2) >> 1;
    const int iy1 = (oy + p) >> 1;
    const int ix0 = (ox + q - 2) >> 1;
    const int ix1 = (ox + q) >> 1;
    const bool vy0 = (iy0 >= 0), vy1 = (iy1 < 64);
    const bool vx0 = (ix0 >= 0), vx1 = (ix1 < 64);

    const float* inb = in + (long)bimg * HIDC * 4096;
    float acc0 = 0.f, acc1 = 0.f, acc2 = 0.f;
    for (int ic = 0; ic < HIDC; ic++) {
        const float* pl = inb + ic * 4096;
        float v00 = (vy0 && vx0) ? pl[iy0 * 64 + ix0] : 0.f;
        float v01 = (vy0 && vx1) ? pl[iy0 * 64 + ix1] : 0.f;
        float v10 = (vy1 && vx0) ? pl[iy1 * 64 + ix0] : 0.f;
        float v11 = (vy1 && vx1) ? pl[iy1 * 64 + ix1] : 0.f;
        const float* wr0 = ws[ic][0];
        const float* wr1 = ws[ic][1];
        const float* wr2 = ws[ic][2];
        acc0 = fmaf(v00, wr0[q], fmaf(v01, wr0[q+2], fmaf(v10, wr0[4+q], fmaf(v11, wr0[4+q+2], acc0))));
        acc1 = fmaf(v00, wr1[q], fmaf(v01, wr1[q+2], fmaf(v10, wr1[4+q], fmaf(v11, wr1[4+q+2], acc1))));
        acc2 = fmaf(v00, wr2[q], fmaf(v01, wr2[q+2], fmaf(v10, wr2[4+q], fmaf(v11, wr2[4+q+2], acc2))));
    }
    long ob = ((long)bimg * 3) * 16384 + (long)oy * 128 + ox;
    float s0 = acc0 + bias[0], s1 = acc1 + bias[1], s2 = acc2 + bias[2];
    out[ob]           = 1.f / (1.f + expf(-s0));
    out[ob + 16384]   = 1.f / (1.f + expf(-s1));
    out[ob + 32768]   = 1.f / (1.f + expf(-s2));
}

// ---------------- host ----------------
extern "C" void kernel_launch(void* const* d_in, const int* in_sizes, int n_in,
                              void* d_out, int out_size)
{
    const float* x      = (const float*)d_in[0];
    const float* c1_w   = (const float*)d_in[1];
    const float* c1_b   = (const float*)d_in[2];
    const float* c2_w   = (const float*)d_in[3];
    const float* c2_b   = (const float*)d_in[4];
    const float* r0_w3  = (const float*)d_in[5];
    const float* r0_b3  = (const float*)d_in[6];
    const float* r0_w1  = (const float*)d_in[7];
    const float* r0_b1  = (const float*)d_in[8];
    const float* r1_w3  = (const float*)d_in[9];
    const float* r1_b3  = (const float*)d_in[10];
    const float* r1_w1  = (const float*)d_in[11];
    const float* r1_b1  = (const float*)d_in[12];
    const float* to_z_w = (const float*)d_in[13];
    const float* to_z_b = (const float*)d_in[14];
    const float* codebk = (const float*)d_in[15];
    const float* fz_w   = (const float*)d_in[16];
    const float* fz_b   = (const float*)d_in[17];
    const float* t1_w   = (const float*)d_in[18];
    const float* t1_b   = (const float*)d_in[19];
    const float* t2_w   = (const float*)d_in[20];
    const float* t2_b   = (const float*)d_in[21];
    float* out = (float*)d_out;

    const long ZE_OFF  = 393216;
    const long EK_OFF  = 917504;
    const long IDS_OFF = 1441792;

    float *h1, *h2a, *h2b, *rr, *d1, *d2, *wt1;
    uint32_t *sp1, *sp2;
    __half *wc2, *wr03, *wr01, *wr13, *wr11, *wfz, *wt1e;
    cudaGetSymbolAddress((void**)&h1,  g_h1);
    cudaGetSymbolAddress((void**)&h2a, g_h2a);
    cudaGetSymbolAddress((void**)&h2b, g_h2b);
    cudaGetSymbolAddress((void**)&rr,  g_rr);
    cudaGetSymbolAddress((void**)&d1,  g_d1);
    cudaGetSymbolAddress((void**)&d2,  g_d2);
    cudaGetSymbolAddress((void**)&wt1, g_wt1);
    cudaGetSymbolAddress((void**)&sp1, g_sp1);
    cudaGetSymbolAddress((void**)&sp2, g_sp2);
    cudaGetSymbolAddress((void**)&wc2,  g_wc2);
    cudaGetSymbolAddress((void**)&wr03, g_wr03);
    cudaGetSymbolAddress((void**)&wr01, g_wr01);
    cudaGetSymbolAddress((void**)&wr13, g_wr13);
    cudaGetSymbolAddress((void**)&wr11, g_wr11);
    cudaGetSymbolAddress((void**)&wfz,  g_wfz);
    cudaGetSymbolAddress((void**)&wt1e, g_wt1e);

    const int N1 = BATCH * HIDC * 4096;   // h1 elements
    const int N2 = BATCH * HIDC * 1024;   // 32x32 layer elements
    const int NZ = BATCH * ZCH  * 1024;   // ek elements

    // ---- launch order: c2 conv_mma is the 4th launch (ncu captures #4) ----
    // (1) c2 weight split
    wsplit16<<<(256 * 4096 + 255) / 256, 256>>>(c2_w,  wc2,  256, 4096);
    // (2) c1: 3->256, k4 s2 p1, relu (scalar; K=48)
    conv_gemm<4, 4><<<dim3(256, 4), 256>>>(
        c1_w, x, c1_b, nullptr, h1,
        3, 128, 128, 256, 64, 64, 2, 1, 48, 1, 0, 64, 64);
    // (3) split h1 (already relu'd)
    asplit<<<(N1 / 4 + 255) / 256, 256>>>(h1, sp1, N1 / 4, 0);
    // (4) c2: 256->256, k4 s2 p1, relu (mma)  <-- profiled launch
    conv_mma<4, 4, false><<<dim3(128, 4), 256>>>(
        wc2, sp1, c2_b, nullptr, h2a,
        256, 64, 64, 256, 32, 32, 2, 1, 4096, 1, 32, 32);

    // r0 3x3
    wsplit16<<<(256 * 2304 + 255) / 256, 256>>>(r0_w3, wr03, 256, 2304);
    asplit<<<(N2 / 4 + 255) / 256, 256>>>(h2a, sp2, N2 / 4, 1);
    conv_mma<3, 3, false><<<dim3(128, 4), 256>>>(
        wr03, sp2, r0_b3, nullptr, rr,
        256, 32, 32, 256, 32, 32, 1, 1, 2304, 0, 32, 32);
    // r0 1x1
    wsplit16<<<(256 * 256  + 255) / 256, 256>>>(r0_w1, wr01, 256, 256);
    asplit<<<(N2 / 4 + 255) / 256, 256>>>(rr, sp2, N2 / 4, 1);
    conv_mma<1, 1, false><<<dim3(128, 4), 256>>>(
        wr01, sp2, r0_b1, h2a, h2b,
        256, 32, 32, 256, 32, 32, 1, 0, 256, 0, 32, 32);
    // r1 3x3
    wsplit16<<<(256 * 2304 + 255) / 256, 256>>>(r1_w3, wr13, 256, 2304);
    asplit<<<(N2 / 4 + 255) / 256, 256>>>(h2b, sp2, N2 / 4, 1);
    conv_mma<3, 3, false><<<dim3(128, 4), 256>>>(
        wr13, sp2, r1_b3, nullptr, rr,
        256, 32, 32, 256, 32, 32, 1, 1, 2304, 0, 32, 32);
    // r1 1x1
    wsplit16<<<(256 * 256  + 255) / 256, 256>>>(r1_w1, wr11, 256, 256);
    asplit<<<(N2 / 4 + 255) / 256, 256>>>(rr, sp2, N2 / 4, 1);
    conv_mma<1, 1, false><<<dim3(128, 4), 256>>>(
        wr11, sp2, r1_b1, h2b, h2a,
        256, 32, 32, 256, 32, 32, 1, 0, 256, 0, 32, 32);

    // to_z: 256->64, 1x1 (scalar fp32 -> exact z_e for VQ)
    conv_gemm<1, 1><<<dim3(64, 1), 256>>>(
        to_z_w, h2a, to_z_b, nullptr, out + ZE_OFF,
        256, 32, 32, 64, 32, 32, 1, 0, 256, 0, 0, 32, 32);

    // VQ
    vq_kernel<<<2048, 128>>>(out + ZE_OFF, codebk, out + EK_OFF, out + IDS_OFF);

    // from_z: 64->256, 1x1, relu (mma)
    wsplit16<<<(256 * 64 + 255) / 256, 256>>>(fz_w, wfz, 256, 64);
    asplit<<<(NZ / 4 + 255) / 256, 256>>>(out + EK_OFF, sp2, NZ / 4, 0);
    conv_mma<1, 1, false><<<dim3(128, 4), 256>>>(
        wfz, sp2, fz_b, nullptr, d1,
        64, 32, 32, 256, 32, 32, 1, 0, 64, 1, 32, 32);

    // t1: convT 256->256 as 4 subpixel 2x2 convs (mma), relu
    wt_kernel<<<(4 * HIDC * HIDC * 4 + 255) / 256, 256>>>(t1_w, wt1);
    for (int pz = 0; pz < 4; pz++)
        wsplit16<<<(256 * 1024 + 255) / 256, 256>>>(
            wt1 + (long)pz * 256 * 1024, wt1e + (long)pz * 256 * 2048, 256, 1024);
    asplit<<<(N2 / 4 + 255) / 256, 256>>>(d1, sp2, N2 / 4, 0);
    conv_mma<2, 2, true><<<dim3(128, 4, 4), 256>>>(
        wt1e, sp2, t1_b, nullptr, d2,
        256, 32, 32, 256, 32, 32, 1, 0, 1024, 1, 64, 64);

    // t2: direct transposed conv 256->3 + sigmoid
    t2_kernel<<<dim3(128, BATCH), 128>>>(d2, t2_w, t2_b, out);
}

// round 16
// speedup vs baseline: 1.6162x; 1.0251x over previous
#include <cuda_runtime.h>
#include <cuda_fp16.h>
#include <cstdint>
#include <math.h>
#include <float.h>

#define BATCH 8
#define HIDC  256
#define ZCH   64
#define KCODE 512

// ---------------- scratch (device globals; no allocation allowed) ----------------
__device__ float g_h2a[BATCH * HIDC * 32 * 32];  // c2 out (residual source)
__device__ float g_h2b[BATCH * HIDC * 32 * 32];  // r0 out (residual source)
__device__ float g_d2 [BATCH * HIDC * 64 * 64];  // decoder stage 2 (t2 input)
__device__ float g_wt1[4 * HIDC * HIDC * 4];     // subpixel-decomposed t1 weights (fp32)

// packed split activations: per element u32 = {h:lo16 | l:hi16}  (ping-pong)
__device__ uint32_t g_sp1[BATCH * HIDC * 64 * 64];  // 33 MB
__device__ uint32_t g_sp2[BATCH * HIDC * 64 * 64];  // 33 MB

// fp16 split weights: per 32-k chunk: [h32 | ls32]
__device__ __half g_wc1 [HIDC * 2 * 64];
__device__ __half g_wc2 [HIDC * 2 * 4096];
__device__ __half g_wr03[HIDC * 2 * 2304];
__device__ __half g_wr01[HIDC * 2 * 256];
__device__ __half g_wr13[HIDC * 2 * 2304];
__device__ __half g_wr11[HIDC * 2 * 256];
__device__ __half g_wtz [ZCH  * 2 * 256];
__device__ __half g_wfz [HIDC * 2 * 64];
__device__ __half g_wt1e[4 * HIDC * 2 * 1024];

// ================= helpers =================
__device__ __forceinline__ uint32_t smem_u32(const void* p) {
    uint32_t a;
    asm("{ .reg .u64 t; cvta.to.shared.u64 t, %1; cvt.u32.u64 %0, t; }" : "=r"(a) : "l"(p));
    return a;
}
#define SWZ128(o) ((o) ^ (((o) >> 3) & 0x70))
__device__ __forceinline__ void sts128(uint32_t a, uint4 v) {
    asm volatile("st.shared.v4.b32 [%0], {%1,%2,%3,%4};"
                 :: "r"(a), "r"(v.x), "r"(v.y), "r"(v.z), "r"(v.w) : "memory");
}
__device__ __forceinline__ void cpasync16(uint32_t saddr, const void* gaddr) {
    asm volatile("cp.async.cg.shared.global [%0], [%1], 16;"
                 :: "r"(saddr), "l"(gaddr) : "memory");
}
__device__ __forceinline__ void cpcommit() {
    asm volatile("cp.async.commit_group;" ::: "memory");
}
__device__ __forceinline__ void cpwait0() {
    asm volatile("cp.async.wait_group 0;" ::: "memory");
}
__device__ __forceinline__ void ldsm4(uint32_t* r, uint32_t addr) {
    asm volatile("ldmatrix.sync.aligned.m8n8.x4.shared.b16 {%0,%1,%2,%3}, [%4];"
                 : "=r"(r[0]), "=r"(r[1]), "=r"(r[2]), "=r"(r[3]) : "r"(addr));
}
__device__ __forceinline__ void mma16816(float* c, const uint32_t* a, const uint32_t* b) {
    asm volatile(
        "mma.sync.aligned.m16n8k16.row.col.f32.f16.f16.f32 "
        "{%0,%1,%2,%3}, {%4,%5,%6,%7}, {%8,%9}, {%0,%1,%2,%3};"
        : "+f"(c[0]), "+f"(c[1]), "+f"(c[2]), "+f"(c[3])
        : "r"(a[0]), "r"(a[1]), "r"(a[2]), "r"(a[3]), "r"(b[0]), "r"(b[1]));
}
__device__ __forceinline__ uint32_t prmt(uint32_t a, uint32_t b, uint32_t sel) {
    uint32_t r;
    asm("prmt.b32 %0, %1, %2, %3;" : "=r"(r) : "r"(a), "r"(b), "r"(sel));
    return r;
}
__device__ __forceinline__ uint32_t packsplit(float v) {
    __half h = __float2half_rn(v);
    __half l = __float2half_rn((v - __half2float(h)) * 2048.0f);
    return (uint32_t)__half_as_ushort(h) | ((uint32_t)__half_as_ushort(l) << 16);
}

// ======= weight split: fp32 -> per-32k-chunk [h32|ls32] fp16 rows =======
__global__ void wsplit16(const float* __restrict__ W, __half* __restrict__ E,
                         int Cout, int K)
{
    int i = blockIdx.x * blockDim.x + threadIdx.x;
    if (i >= Cout * K) return;
    int oc = i / K, k = i - oc * K;
    int c = k >> 5, j = k & 31;
    float v = W[i];
    __half h = __float2half_rn(v);
    __half ls = __float2half_rn((v - __half2float(h)) * 2048.0f);
    long base = (long)oc * 2 * K + (long)c * 64;
    E[base + j]      = h;
    E[base + 32 + j] = ls;
}

// c1 weights: source K=48 (3ch x 16 taps), emitted K=64 with zero pad (ch 3)
__global__ void wsplit_c1(const float* __restrict__ W, __half* __restrict__ E)
{
    int i = blockIdx.x * blockDim.x + threadIdx.x;
    if (i >= 256 * 64) return;
    int oc = i >> 6, k = i & 63;
    float v = (k < 48) ? W[oc * 48 + k] : 0.f;
    __half h = __float2half_rn(v);
    __half ls = __float2half_rn((v - __half2float(h)) * 2048.0f);
    int c = k >> 5, j = k & 31;
    long base = (long)oc * 128 + c * 64;
    E[base + j]      = h;
    E[base + 32 + j] = ls;
}

// x split with channel pad 3->4: out [8][4][16384] packed
__global__ void asplit_pad(const float* __restrict__ x, uint32_t* __restrict__ outp)
{
    int i = blockIdx.x * blockDim.x + threadIdx.x;   // over 8*4*16384/4
    if (i >= 8 * 4 * 4096) return;
    int hw4 = i & 4095;
    int r = i >> 12;
    int c = r & 3;
    int b = r >> 2;
    uint4 o = make_uint4(0, 0, 0, 0);
    if (c < 3) {
        float4 v = reinterpret_cast<const float4*>(x + ((long)(b * 3 + c) << 14))[hw4];
        o.x = packsplit(v.x); o.y = packsplit(v.y);
        o.z = packsplit(v.z); o.w = packsplit(v.w);
    }
    reinterpret_cast<uint4*>(outp)[((long)r << 12) + hw4] = o;
}

// =======================================================================
// mma.sync implicit-GEMM conv (fp16 2-way split w/ rescale, 3 terms).
//   CTA: 64 oc x 64 px. BK=32. 8 warps as 4(m) x 2(n); warp tile 16x32.
// Round-16: epilogue dual-store — optional fp32 store (storef) + optional
// packed-split store (spout, with srelu) so consumers read split directly.
// =======================================================================
template<int KH, int KW, bool SUBPIX>
__global__ __launch_bounds__(256, 2) void conv_mma(
    const __half* __restrict__ Wc,
    const uint32_t* __restrict__ inp,
    const float* __restrict__ bias, const float* __restrict__ res,
    float* __restrict__ out, uint32_t* __restrict__ spout,
    int storef, int srelu,
    int Cin, int Hin, int Win, int Cout, int Hout, int Wout,
    int stride, int pad, int K, int act,
    int Hfull, int Wfull)
{
    constexpr int KHW = KH * KW;
    constexpr bool REGP = (32 % KHW) == 0;
    __shared__ __align__(16) char sAm[2][64 * 128];
    __shared__ __align__(16) char sBm[2][64 * 128];

    const int tid  = threadIdx.x;
    const int wid  = tid >> 5;
    const int lane = tid & 31;
    const int m0 = blockIdx.y * 64;
    const int n0 = blockIdx.x * 64;
    const int HW = Hout * Wout;

    uint32_t sAb[2], sBb[2];
    sAb[0] = smem_u32(sAm[0]); sAb[1] = smem_u32(sAm[1]);
    sBb[0] = smem_u32(sBm[0]); sBb[1] = smem_u32(sBm[1]);

    int par_y = 0, par_x = 0;
    const __half* Wb = Wc;
    if (SUBPIX) {
        int pz = blockIdx.z;
        par_y = pz >> 1; par_x = pz & 1;
        Wb += (long)pz * Cout * 2 * K;
    }

    const int px  = tid & 63;
    const int seg = tid >> 6;
    const int n   = n0 + px;
    const int bimg = n / HW;
    const int hw   = n - bimg * HW;
    const int oy   = hw / Wout, ox = hw - oy * Wout;
    const uint32_t* inb = inp + (long)bimg * Cin * Hin * Win;
    int iy0, ix0;
    if (SUBPIX) { iy0 = oy - (1 - par_y); ix0 = ox - (1 - par_x); }
    else        { iy0 = oy * stride - pad; ix0 = ox * stride - pad; }

    int pbase[8];
    unsigned vmask = 0;
    if (REGP) {
        #pragma unroll
        for (int e = 0; e < 8; e++) {
            int kk = seg * 8 + e;
            int ic0 = kk / KHW;
            int rr = kk - ic0 * KHW;
            int ky = rr / KW, kx = rr - ky * KW;
            int iy = iy0 + ky, ix = ix0 + kx;
            pbase[e] = ic0 * Hin * Win + iy * Win + ix;
            if ((unsigned)iy < (unsigned)Hin && (unsigned)ix < (unsigned)Win)
                vmask |= (1u << e);
        }
    }
    const int dic = REGP ? (32 / KHW) * Hin * Win : 0;

    const int wm = (wid & 3) * 16;
    const int wn = (wid >> 2) * 32;

    float acc[4][4];
    float accl[4][4];
    #pragma unroll
    for (int nt = 0; nt < 4; nt++)
        #pragma unroll
        for (int e = 0; e < 4; e++) { acc[nt][e] = 0.f; accl[nt][e] = 0.f; }

    const long K2 = 2 * (long)K;
    const int nc_iters = K / 32;

    const int arow = tid >> 3;
    const int ac16 = tid & 7;
    const __half* Arow0 = Wb + (long)(m0 + arow) * K2 + ac16 * 8;
    const __half* Arow1 = Wb + (long)(m0 + arow + 32) * K2 + ac16 * 8;
    const uint32_t sA0off = SWZ128(arow * 128 + ac16 * 16);
    const uint32_t sA1off = SWZ128((arow + 32) * 128 + ac16 * 16);

    uint32_t raw[8];

    auto issueA = [&](int cb, int buf) {
        const long kb = (long)cb * 64;
        cpasync16(sAb[buf] + sA0off, Arow0 + kb);
        cpasync16(sAb[buf] + sA1off, Arow1 + kb);
    };
    auto loadB = [&](int cb) {
        if (REGP) {
            const int off = cb * dic;
            #pragma unroll
            for (int e = 0; e < 8; e++)
                raw[e] = ((vmask >> e) & 1) ? inb[off + pbase[e]] : 0u;
        } else {
            const int kb = cb * 32 + seg * 8;
            #pragma unroll
            for (int e = 0; e < 8; e++) {
                int k = kb + e;
                int ic = k / KHW;
                int r2 = k - ic * KHW;
                int ky = r2 / KW, kx = r2 - ky * KW;
                int iy = iy0 + ky, ix = ix0 + kx;
                uint32_t pv = 0;
                if ((unsigned)iy < (unsigned)Hin && (unsigned)ix < (unsigned)Win)
                    pv = inb[(ic * Hin + iy) * Win + ix];
                raw[e] = pv;
            }
        }
    };
    auto storeB = [&](int buf) {
        uint32_t hp[4], lp[4];
        #pragma unroll
        for (int q = 0; q < 4; q++) {
            hp[q] = prmt(raw[2 * q], raw[2 * q + 1], 0x5410);
            lp[q] = prmt(raw[2 * q], raw[2 * q + 1], 0x7632);
        }
        sts128(sBb[buf] + SWZ128(px * 128 + seg * 16),      make_uint4(hp[0], hp[1], hp[2], hp[3]));
        sts128(sBb[buf] + SWZ128(px * 128 + 64 + seg * 16), make_uint4(lp[0], lp[1], lp[2], lp[3]));
    };

    issueA(0, 0);
    cpcommit();
    loadB(0);
    cpwait0();
    storeB(0);
    __syncthreads();

    int cur = 0;
    for (int cb = 0; cb < nc_iters; cb++) {
        if (cb + 1 < nc_iters) {
            issueA(cb + 1, cur ^ 1);
            cpcommit();
            loadB(cb + 1);
        }
        const uint32_t sA = sAb[cur];
        const uint32_t sB = sBb[cur];
        #pragma unroll
        for (int s = 0; s < 2; s++) {
            uint32_t Ah[4], Al[4];
            {
                int row = wm + (lane & 15);
                int kby = s * 32 + ((lane >> 4) << 4);
                ldsm4(Ah, sA + SWZ128(row * 128 + kby));
                ldsm4(Al, sA + SWZ128(row * 128 + 64 + kby));
            }
            uint32_t Bh[2][4], Bl[2][4];
            #pragma unroll
            for (int ntp = 0; ntp < 2; ntp++) {
                int nrow = wn + ntp * 16 + ((lane >> 4) << 3) + (lane & 7);
                int kby  = s * 32 + (((lane >> 3) & 1) << 4);
                ldsm4(Bh[ntp], sB + SWZ128(nrow * 128 + kby));
                ldsm4(Bl[ntp], sB + SWZ128(nrow * 128 + 64 + kby));
            }
            #pragma unroll
            for (int nt = 0; nt < 4; nt++) {
                const uint32_t* bh = &Bh[nt >> 1][(nt & 1) * 2];
                const uint32_t* bl = &Bl[nt >> 1][(nt & 1) * 2];
                mma16816(acc[nt],  Ah, bh);
                mma16816(accl[nt], Ah, bl);
                mma16816(accl[nt], Al, bh);
            }
        }
        if (cb + 1 < nc_iters) {
            cpwait0();
            storeB(cur ^ 1);
            __syncthreads();
            cur ^= 1;
        }
    }

    // ---- epilogue ----
    const float INV = 1.0f / 2048.0f;
    const long HWf = (long)Hfull * Wfull;
    const int bimg0 = n0 / HW;
    const int hw0 = n0 - bimg0 * HW;
    const long obase = (long)bimg0 * Cout * HWf;

    #pragma unroll
    for (int nt = 0; nt < 4; nt++) {
        float c0 = acc[nt][0] + accl[nt][0] * INV;
        float c1 = acc[nt][1] + accl[nt][1] * INV;
        float c2 = acc[nt][2] + accl[nt][2] * INV;
        float c3 = acc[nt][3] + accl[nt][3] * INV;
        int oc0 = m0 + wm + (lane >> 2);
        int oc1 = oc0 + 8;
        int ncol = hw0 + wn + nt * 8 + (lane & 3) * 2;
        float b0 = bias[oc0], b1 = bias[oc1];
        c0 += b0; c1 += b0; c2 += b1; c3 += b1;
        if (!SUBPIX) {
            long i0 = obase + (long)oc0 * HWf + ncol;
            long i1 = obase + (long)oc1 * HWf + ncol;
            if (res) {
                float2 r0 = *reinterpret_cast<const float2*>(res + i0);
                float2 r1 = *reinterpret_cast<const float2*>(res + i1);
                c0 += r0.x; c1 += r0.y; c2 += r1.x; c3 += r1.y;
            }
            float f0 = c0, f1 = c1, f2 = c2, f3 = c3;
            if (act == 1) {
                f0 = fmaxf(c0, 0.f); f1 = fmaxf(c1, 0.f);
                f2 = fmaxf(c2, 0.f); f3 = fmaxf(c3, 0.f);
            }
            if (storef) {
                *reinterpret_cast<float2*>(out + i0) = make_float2(f0, f1);
                *reinterpret_cast<float2*>(out + i1) = make_float2(f2, f3);
            }
            if (spout) {
                float s0 = f0, s1 = f1, s2 = f2, s3 = f3;
                if (act == 0 && srelu) {
                    s0 = fmaxf(c0, 0.f); s1 = fmaxf(c1, 0.f);
                    s2 = fmaxf(c2, 0.f); s3 = fmaxf(c3, 0.f);
                }
                uint2 p0 = make_uint2(packsplit(s0), packsplit(s1));
                uint2 p1 = make_uint2(packsplit(s2), packsplit(s3));
                *reinterpret_cast<uint2*>(spout + i0) = p0;
                *reinterpret_cast<uint2*>(spout + i1) = p1;
            }
        } else {
            if (act == 1) {
                c0 = fmaxf(c0, 0.f); c1 = fmaxf(c1, 0.f);
                c2 = fmaxf(c2, 0.f); c3 = fmaxf(c3, 0.f);
            }
            int eoy0 = ncol / Wout, eox0 = ncol - eoy0 * Wout;
            int nc1 = ncol + 1;
            int eoy1 = nc1 / Wout, eox1 = nc1 - eoy1 * Wout;
            long fy0 = 2 * eoy0 + par_y, fx0 = 2 * eox0 + par_x;
            long fy1 = 2 * eoy1 + par_y, fx1 = 2 * eox1 + par_x;
            out[obase + (long)oc0 * HWf + fy0 * Wfull + fx0] = c0;
            out[obase + (long)oc0 * HWf + fy1 * Wfull + fx1] = c1;
            out[obase + (long)oc1 * HWf + fy0 * Wfull + fx0] = c2;
            out[obase + (long)oc1 * HWf + fy1 * Wfull + fx1] = c3;
        }
    }
}

// ---------------- VQ: one warp per z-vector; emits ids, e_k fp32 + split ----------------
__global__ __launch_bounds__(128) void vq_kernel(
    const float* __restrict__ z, const float* __restrict__ cb,
    float* __restrict__ ek, float* __restrict__ ids_out,
    uint32_t* __restrict__ eksp)
{
    const int warp = threadIdx.x >> 5;
    const int lane = threadIdx.x & 31;
    const int n = blockIdx.x * 4 + warp;
    const int b  = n >> 10;
    const int hw = n & 1023;

    __shared__ float zs[4][ZCH];
    const float* zb = z + (long)b * ZCH * 1024 + hw;
    zs[warp][lane]      = zb[(long)lane * 1024];
    zs[warp][lane + 32] = zb[(long)(lane + 32) * 1024];
    __syncwarp();

    float best = FLT_MAX;
    int bi = 0;
    for (int k = lane; k < KCODE; k += 32) {
        const float* c = cb + k * ZCH;
        float s = 0.f;
        #pragma unroll 16
        for (int ci = 0; ci < ZCH; ci++) {
            float cv = c[ci];
            s = fmaf(cv, cv - 2.f * zs[warp][ci], s);
        }
        if (s < best) { best = s; bi = k; }
    }
    #pragma unroll
    for (int off = 16; off; off >>= 1) {
        float ov = __shfl_down_sync(0xffffffffu, best, off);
        int   oi = __shfl_down_sync(0xffffffffu, bi,   off);
        if (ov < best || (ov == best && oi < bi)) { best = ov; bi = oi; }
    }
    bi = __shfl_sync(0xffffffffu, bi, 0);

    if (lane == 0) ids_out[n] = (float)bi;
    const float* c = cb + bi * ZCH;
    float* ekb = ek + (long)b * ZCH * 1024 + hw;
    uint32_t* spb = eksp + (long)b * ZCH * 1024 + hw;
    float v0 = c[lane], v1 = c[lane + 32];
    ekb[(long)lane * 1024]        = v0;
    ekb[(long)(lane + 32) * 1024] = v1;
    spb[(long)lane * 1024]        = packsplit(v0);
    spb[(long)(lane + 32) * 1024] = packsplit(v1);
}

// ---------------- t1 subpixel weight prep (fp32) ----------------
__global__ void wt_kernel(const float* __restrict__ w, float* __restrict__ wf)
{
    int i = blockIdx.x * blockDim.x + threadIdx.x;
    const int total = 4 * HIDC * HIDC * 4;
    if (i >= total) return;
    int kx = i & 1, ky = (i >> 1) & 1;
    int r1 = i >> 2;
    int ic = r1 & (HIDC - 1);
    int r2 = r1 >> 8;
    int oc = r2 & (HIDC - 1);
    int pz = r2 >> 8;
    int p = pz >> 1, q = pz & 1;
    wf[i] = w[((long)(ic * HIDC + oc) << 4) + (3 - p - 2 * ky) * 4 + (3 - q - 2 * kx)];
}

// ---------------- t2: direct transposed conv 256->3 + sigmoid ----------------
__global__ __launch_bounds__(128) void t2_kernel(
    const float* __restrict__ in, const float* __restrict__ w,
    const float* __restrict__ bias, float* __restrict__ out)
{
    __shared__ float ws[HIDC][3][8];
    const int oy   = blockIdx.x;
    const int bimg = blockIdx.y;
    const int ox   = threadIdx.x;
    const int p = oy & 1;

    for (int idx = threadIdx.x; idx < HIDC * 3 * 8; idx += 128) {
        int ic = idx / 24;
        int r  = idx - ic * 24;
        int oc = r >> 3;
        int t  = r & 7;
        int kyi = t >> 2, kx = t & 3;
        int ky = p + 2 * kyi;
        ws[ic][oc][t] = w[((long)(ic * 3 + oc) << 4) + (3 - ky) * 4 + (3 - kx)];
    }
    __syncthreads();

    const int q = ox & 1;
    const int iy0 = (oy + p - 2) >> 1;
    const int iy1 = (oy + p) >> 1;
    const int ix0 = (ox + q - 2) >> 1;
    const int ix1 = (ox + q) >> 1;
    const bool vy0 = (iy0 >= 0), vy1 = (iy1 < 64);
    const bool vx0 = (ix0 >= 0), vx1 = (ix1 < 64);

    const float* inb = in + (long)bimg * HIDC * 4096;
    float acc0 = 0.f, acc1 = 0.f, acc2 = 0.f;
    for (int ic = 0; ic < HIDC; ic++) {
        const float* pl = inb + ic * 4096;
        float v00 = (vy0 && vx0) ? pl[iy0 * 64 + ix0] : 0.f;
        float v01 = (vy0 && vx1) ? pl[iy0 * 64 + ix1] : 0.f;
        float v10 = (vy1 && vx0) ? pl[iy1 * 64 + ix0] : 0.f;
        float v11 = (vy1 && vx1) ? pl[iy1 * 64 + ix1] : 0.f;
        const float* wr0 = ws[ic][0];
        const float* wr1 = ws[ic][1];
        const float* wr2 = ws[ic][2];
        acc0 = fmaf(v00, wr0[q], fmaf(v01, wr0[q+2], fmaf(v10, wr0[4+q], fmaf(v11, wr0[4+q+2], acc0))));
        acc1 = fmaf(v00, wr1[q], fmaf(v01, wr1[q+2], fmaf(v10, wr1[4+q], fmaf(v11, wr1[4+q+2], acc1))));
        acc2 = fmaf(v00, wr2[q], fmaf(v01, wr2[q+2], fmaf(v10, wr2[4+q], fmaf(v11, wr2[4+q+2], acc2))));
    }
    long ob = ((long)bimg * 3) * 16384 + (long)oy * 128 + ox;
    float s0 = acc0 + bias[0], s1 = acc1 + bias[1], s2 = acc2 + bias[2];
    out[ob]           = 1.f / (1.f + expf(-s0));
    out[ob + 16384]   = 1.f / (1.f + expf(-s1));
    out[ob + 32768]   = 1.f / (1.f + expf(-s2));
}

// ---------------- host ----------------
extern "C" void kernel_launch(void* const* d_in, const int* in_sizes, int n_in,
                              void* d_out, int out_size)
{
    const float* x      = (const float*)d_in[0];
    const float* c1_w   = (const float*)d_in[1];
    const float* c1_b   = (const float*)d_in[2];
    const float* c2_w   = (const float*)d_in[3];
    const float* c2_b   = (const float*)d_in[4];
    const float* r0_w3  = (const float*)d_in[5];
    const float* r0_b3  = (const float*)d_in[6];
    const float* r0_w1  = (const float*)d_in[7];
    const float* r0_b1  = (const float*)d_in[8];
    const float* r1_w3  = (const float*)d_in[9];
    const float* r1_b3  = (const float*)d_in[10];
    const float* r1_w1  = (const float*)d_in[11];
    const float* r1_b1  = (const float*)d_in[12];
    const float* to_z_w = (const float*)d_in[13];
    const float* to_z_b = (const float*)d_in[14];
    const float* codebk = (const float*)d_in[15];
    const float* fz_w   = (const float*)d_in[16];
    const float* fz_b   = (const float*)d_in[17];
    const float* t1_w   = (const float*)d_in[18];
    const float* t1_b   = (const float*)d_in[19];
    const float* t2_w   = (const float*)d_in[20];
    const float* t2_b   = (const float*)d_in[21];
    float* out = (float*)d_out;

    const long ZE_OFF  = 393216;
    const long EK_OFF  = 917504;
    const long IDS_OFF = 1441792;

    float *h2a, *h2b, *d2, *wt1;
    uint32_t *sp1, *sp2;
    __half *wc1, *wc2, *wr03, *wr01, *wr13, *wr11, *wtz, *wfz, *wt1e;
    cudaGetSymbolAddress((void**)&h2a, g_h2a);
    cudaGetSymbolAddress((void**)&h2b, g_h2b);
    cudaGetSymbolAddress((void**)&d2,  g_d2);
    cudaGetSymbolAddress((void**)&wt1, g_wt1);
    cudaGetSymbolAddress((void**)&sp1, g_sp1);
    cudaGetSymbolAddress((void**)&sp2, g_sp2);
    cudaGetSymbolAddress((void**)&wc1,  g_wc1);
    cudaGetSymbolAddress((void**)&wc2,  g_wc2);
    cudaGetSymbolAddress((void**)&wr03, g_wr03);
    cudaGetSymbolAddress((void**)&wr01, g_wr01);
    cudaGetSymbolAddress((void**)&wr13, g_wr13);
    cudaGetSymbolAddress((void**)&wr11, g_wr11);
    cudaGetSymbolAddress((void**)&wtz,  g_wtz);
    cudaGetSymbolAddress((void**)&wfz,  g_wfz);
    cudaGetSymbolAddress((void**)&wt1e, g_wt1e);

    // (1) c2 weight split
    wsplit16<<<(256 * 4096 + 255) / 256, 256>>>(c2_w, wc2, 256, 4096);
    // (2) x split (channel-padded) -> sp2
    asplit_pad<<<(8 * 4 * 4096 + 255) / 256, 256>>>(x, sp2);
    // (3) c1 weight split (K padded 48->64)
    wsplit_c1<<<(256 * 64 + 255) / 256, 256>>>(c1_w, wc1);
    // (4) c1: 4->256, k4 s2 p1, relu (mma); split-only out -> sp1   <-- profiled
    conv_mma<4, 4, false><<<dim3(512, 4), 256>>>(
        wc1, sp2, c1_b, nullptr, nullptr, sp1, 0, 0,
        4, 128, 128, 256, 64, 64, 2, 1, 64, 1, 64, 64);
    // (5) c2: f32 h2a + split sp2
    conv_mma<4, 4, false><<<dim3(128, 4), 256>>>(
        wc2, sp1, c2_b, nullptr, h2a, sp2, 1, 0,
        256, 64, 64, 256, 32, 32, 2, 1, 4096, 1, 32, 32);

    // r0 3x3: split-only (relu'd) -> sp1
    wsplit16<<<(256 * 2304 + 255) / 256, 256>>>(r0_w3, wr03, 256, 2304);
    conv_mma<3, 3, false><<<dim3(128, 4), 256>>>(
        wr03, sp2, r0_b3, nullptr, nullptr, sp1, 0, 1,
        256, 32, 32, 256, 32, 32, 1, 1, 2304, 0, 32, 32);
    // r0 1x1: res h2a; f32 h2b + split(relu) sp2
    wsplit16<<<(256 * 256 + 255) / 256, 256>>>(r0_w1, wr01, 256, 256);
    conv_mma<1, 1, false><<<dim3(128, 4), 256>>>(
        wr01, sp1, r0_b1, h2a, h2b, sp2, 1, 1,
        256, 32, 32, 256, 32, 32, 1, 0, 256, 0, 32, 32);
    // r1 3x3: split-only (relu'd) -> sp1
    wsplit16<<<(256 * 2304 + 255) / 256, 256>>>(r1_w3, wr13, 256, 2304);
    conv_mma<3, 3, false><<<dim3(128, 4), 256>>>(
        wr13, sp2, r1_b3, nullptr, nullptr, sp1, 0, 1,
        256, 32, 32, 256, 32, 32, 1, 1, 2304, 0, 32, 32);
    // r1 1x1: res h2b; split-only (no relu) -> sp2
    wsplit16<<<(256 * 256 + 255) / 256, 256>>>(r1_w1, wr11, 256, 256);
    conv_mma<1, 1, false><<<dim3(128, 4), 256>>>(
        wr11, sp1, r1_b1, h2b, nullptr, sp2, 0, 0,
        256, 32, 32, 256, 32, 32, 1, 0, 256, 0, 32, 32);

    // to_z: 256->64 (mma), f32 -> z_e
    wsplit16<<<(64 * 256 + 255) / 256, 256>>>(to_z_w, wtz, 64, 256);
    conv_mma<1, 1, false><<<dim3(128, 1), 256>>>(
        wtz, sp2, to_z_b, nullptr, out + ZE_OFF, nullptr, 1, 0,
        256, 32, 32, 64, 32, 32, 1, 0, 256, 0, 32, 32);

    // VQ: ids + e_k fp32 + e_k split -> sp1
    vq_kernel<<<2048, 128>>>(out + ZE_OFF, codebk, out + EK_OFF, out + IDS_OFF, sp1);

    // from_z: 64->256, relu (mma); split-only -> sp2
    wsplit16<<<(256 * 64 + 255) / 256, 256>>>(fz_w, wfz, 256, 64);
    conv_mma<1, 1, false><<<dim3(128, 4), 256>>>(
        wfz, sp1, fz_b, nullptr, nullptr, sp2, 0, 0,
        64, 32, 32, 256, 32, 32, 1, 0, 64, 1, 32, 32);

    // t1: convT as 4 subpixel 2x2 convs (mma), relu; f32 d2
    wt_kernel<<<(4 * HIDC * HIDC * 4 + 255) / 256, 256>>>(t1_w, wt1);
    wsplit16<<<(1024 * 1024 + 255) / 256, 256>>>(wt1, wt1e, 1024, 1024);
    conv_mma<2, 2, true><<<dim3(128, 4, 4), 256>>>(
        wt1e, sp2, t1_b, nullptr, d2, nullptr, 1, 0,
        256, 32, 32, 256, 32, 32, 1, 0, 1024, 1, 64, 64);

    // t2: direct transposed conv 256->3 + sigmoid
    t2_kernel<<<dim3(128, BATCH), 128>>>(d2, t2_w, t2_b, out);
}